// round 4
// baseline (speedup 1.0000x reference)
#include <cuda_runtime.h>
#include <cuda_bf16.h>
#include <cstdint>
#include <cstddef>

#define B_WIN 4096
#define SEQ   49
#define CDIM  512
#define NH    16
#define HD    32
#define NW    64
#define MROWS (B_WIN * SEQ)      // 200704
#define KDIM  512

// ---------------- device scratch (no cudaMalloc allowed) -------------------
__device__ float g_qkv[(size_t)MROWS * 1536];             // [B*N, 3C] fp32
__device__ __nv_bfloat16 g_x_hi[(size_t)MROWS * KDIM];    // x split
__device__ __nv_bfloat16 g_x_lo[(size_t)MROWS * KDIM];
__device__ __nv_bfloat16 g_att_hi[(size_t)MROWS * KDIM];  // attn out split
__device__ __nv_bfloat16 g_att_lo[(size_t)MROWS * KDIM];
__device__ __nv_bfloat16 g_qw_hi[1536 * KDIM];            // qkv_w^T split [N,K]
__device__ __nv_bfloat16 g_qw_lo[1536 * KDIM];
__device__ __nv_bfloat16 g_pw_hi[512 * KDIM];             // proj_w^T split [N,K]
__device__ __nv_bfloat16 g_pw_lo[512 * KDIM];

// ---------------- helpers (arch-portable PTX: sm_80+ features only) --------
__device__ __forceinline__ uint32_t smem_u32(const void* p) {
    uint32_t a;
    asm("{ .reg .u64 t; cvta.to.shared.u64 t, %1; cvt.u32.u64 %0, t; }"
        : "=r"(a) : "l"(p));
    return a;
}
#define CPA16(dst, src) \
    asm volatile("cp.async.cg.shared.global [%0], [%1], 16;" \
                 :: "r"(dst), "l"(src) : "memory")
#define CPCOMMIT() asm volatile("cp.async.commit_group;" ::: "memory")
#define CPWAIT(n)  asm volatile("cp.async.wait_group %0;" :: "n"(n) : "memory")
#define LDSM4(r, addr)                                                        \
    asm volatile("ldmatrix.sync.aligned.m8n8.x4.shared.b16 {%0,%1,%2,%3}, [%4];" \
        : "=r"((r)[0]), "=r"((r)[1]), "=r"((r)[2]), "=r"((r)[3]) : "r"(addr))
#define MMA_BF16(d, a, b0, b1)                                                \
    asm volatile("mma.sync.aligned.m16n8k16.row.col.f32.bf16.bf16.f32 "       \
        "{%0,%1,%2,%3},{%4,%5,%6,%7},{%8,%9},{%0,%1,%2,%3};"                  \
        : "+f"((d)[0]), "+f"((d)[1]), "+f"((d)[2]), "+f"((d)[3])              \
        : "r"((a)[0]), "r"((a)[1]), "r"((a)[2]), "r"((a)[3]),                 \
          "r"(b0), "r"(b1))

__device__ __forceinline__ uint32_t pack_bf2(__nv_bfloat16 a, __nv_bfloat16 b) {
    uint16_t ua = *reinterpret_cast<uint16_t*>(&a);
    uint16_t ub = *reinterpret_cast<uint16_t*>(&b);
    return (uint32_t)ua | ((uint32_t)ub << 16);
}
__device__ __forceinline__ void split_pair(float a, float b, uint32_t& hi, uint32_t& lo) {
    __nv_bfloat16 ha = __float2bfloat16_rn(a), hb = __float2bfloat16_rn(b);
    hi = pack_bf2(ha, hb);
    float ra = a - __bfloat162float(ha), rb = b - __bfloat162float(hb);
    lo = pack_bf2(__float2bfloat16_rn(ra), __float2bfloat16_rn(rb));
}

// ---------------------------------------------------------------------------
// fp32 -> bf16 hi/lo split (element-wise, for activations)
// ---------------------------------------------------------------------------
__global__ void fsplit(const float4* __restrict__ in, uint2* __restrict__ hi,
                       uint2* __restrict__ lo, int n4)
{
    const int i = blockIdx.x * blockDim.x + threadIdx.x;
    if (i >= n4) return;
    float4 v = in[i];
    uint2 H, L;
    split_pair(v.x, v.y, H.x, L.x);
    split_pair(v.z, v.w, H.y, L.y);
    hi[i] = H;
    lo[i] = L;
}

// ---------------------------------------------------------------------------
// Weight prep: W[K,N] fp32 -> Bhi/Blo[N,K] bf16 (transposed + split)
// ---------------------------------------------------------------------------
__global__ void wsplit(const float* __restrict__ W, __nv_bfloat16* __restrict__ Bhi,
                       __nv_bfloat16* __restrict__ Blo, int K, int N)
{
    __shared__ float t[32][33];
    const int bx = blockIdx.x, by = blockIdx.y;
    const int x = threadIdx.x, y = threadIdx.y;   // 32 x 8
#pragma unroll
    for (int i = 0; i < 4; i++)
        t[y + i * 8][x] = W[(size_t)(by * 32 + y + i * 8) * N + bx * 32 + x];
    __syncthreads();
#pragma unroll
    for (int i = 0; i < 4; i++) {
        float v = t[x][y + i * 8];
        __nv_bfloat16 h = __float2bfloat16_rn(v);
        size_t o = (size_t)(bx * 32 + y + i * 8) * K + by * 32 + x;
        Bhi[o] = h;
        Blo[o] = __float2bfloat16_rn(v - __bfloat162float(h));
    }
}

// ---------------------------------------------------------------------------
// bf16 mma.sync GEMM, 3-term split, 3-stage cp.async pipeline.
// CTA 128x128, BK=32. SMEM layout per stage:
//   A buf: 128 rows x 128B  (row = [hi 64B | lo 64B], 16B-chunk swizzle c^(r&7))
//   B buf: same, at +16KB.
// One __syncthreads per K-chunk; copy for chunk k+2 overlaps compute of k.
// ---------------------------------------------------------------------------
#define STAGE_A   16384
#define STAGE_SZ  32768
#define NSTAGE    3
#define GSMEM     (NSTAGE * STAGE_SZ)     // 98304 -> 2 CTAs/SM

__global__ __launch_bounds__(256, 2)
void gemm_bf16(const __nv_bfloat16* __restrict__ Ahi_g,
               const __nv_bfloat16* __restrict__ Alo_g,
               const __nv_bfloat16* __restrict__ Bhi_g,
               const __nv_bfloat16* __restrict__ Blo_g,
               const float* __restrict__ bias, float* __restrict__ C, int Ntot)
{
    extern __shared__ __align__(128) char sm[];
    const uint32_t sb = smem_u32(sm);
    const int tid = threadIdx.x;
    const int lane = tid & 31, wid = tid >> 5;
    const int m0 = blockIdx.y * 128, n0 = blockIdx.x * 128;
    const int wm = (wid >> 2) * 64, wn = (wid & 3) * 32;

    // copy roles: each thread owns one row (tid>>1) and the hi or lo 64B half
    const int crow = tid >> 1;
    const int chalf = tid & 1;                 // 0 = hi, 1 = lo
    const uint32_t cswz = (uint32_t)(crow & 7);

    const char* gA = (const char*)((chalf ? Alo_g : Ahi_g) + (size_t)(m0 + crow) * KDIM);
    const char* gB = (const char*)((chalf ? Blo_g : Bhi_g) + (size_t)(n0 + crow) * KDIM);

    float acc[4][4][4];
#pragma unroll
    for (int a = 0; a < 4; a++)
#pragma unroll
        for (int b = 0; b < 4; b++)
#pragma unroll
            for (int c = 0; c < 4; c++) acc[a][b][c] = 0.f;

    auto issue = [&](int s, int kc) {
        const uint32_t abase = sb + s * STAGE_SZ + crow * 128;
        const int gofs = kc * 64;              // 32 bf16 = 64B per chunk
#pragma unroll
        for (int j = 0; j < 4; j++) {
            const uint32_t cswzj = ((uint32_t)(chalf * 4 + j) ^ cswz) * 16;
            CPA16(abase + cswzj,           gA + gofs + j * 16);
            CPA16(abase + STAGE_A + cswzj, gB + gofs + j * 16);
        }
        CPCOMMIT();
    };

    issue(0, 0);
    issue(1, 1);

    const int r = lane & 15;
    const int csel = lane >> 4;                // 16B column half for ldmatrix

    for (int kc = 0; kc < 16; kc++) {
        const int s = kc % NSTAGE;
        if (kc < 15) { CPWAIT(1); } else { CPWAIT(0); }
        __syncthreads();
        if (kc + 2 < 16) issue((kc + 2) % NSTAGE, kc + 2);

        const uint32_t base = sb + s * STAGE_SZ;
#pragma unroll
        for (int kk = 0; kk < 2; kk++) {
            const int c_hi = kk * 2 + csel;    // chunks 0..3 = hi
            const int c_lo = c_hi + 4;         // chunks 4..7 = lo
            uint32_t ah[4][4], al[4][4], bh[2][4], bl[2][4];
#pragma unroll
            for (int mt = 0; mt < 4; mt++) {
                const int ar = wm + mt * 16 + r;
                const uint32_t ra = base + (uint32_t)ar * 128;
                const uint32_t sw = (uint32_t)(ar & 7);
                LDSM4(ah[mt], ra + (((uint32_t)c_hi ^ sw) * 16));
                LDSM4(al[mt], ra + (((uint32_t)c_lo ^ sw) * 16));
            }
#pragma unroll
            for (int p = 0; p < 2; p++) {
                const int br = wn + p * 16 + r;
                const uint32_t rb = base + STAGE_A + (uint32_t)br * 128;
                const uint32_t sw = (uint32_t)(br & 7);
                LDSM4(bh[p], rb + (((uint32_t)c_hi ^ sw) * 16));
                LDSM4(bl[p], rb + (((uint32_t)c_lo ^ sw) * 16));
            }
#pragma unroll
            for (int mt = 0; mt < 4; mt++)
#pragma unroll
                for (int nt = 0; nt < 4; nt++) {
                    const int p = nt >> 1, o = nt & 1;
                    MMA_BF16(acc[mt][nt], ah[mt], bh[p][o], bh[p][o + 2]);
                    MMA_BF16(acc[mt][nt], ah[mt], bl[p][o], bl[p][o + 2]);
                    MMA_BF16(acc[mt][nt], al[mt], bh[p][o], bh[p][o + 2]);
                }
        }
    }

    // epilogue + bias
#pragma unroll
    for (int mt = 0; mt < 4; mt++) {
        const int gr = m0 + wm + mt * 16 + (lane >> 2);
#pragma unroll
        for (int nt = 0; nt < 4; nt++) {
            const int gc = n0 + wn + nt * 8 + (lane & 3) * 2;
            const float b0 = bias[gc], b1 = bias[gc + 1];
            float2 v0 = { acc[mt][nt][0] + b0, acc[mt][nt][1] + b1 };
            float2 v1 = { acc[mt][nt][2] + b0, acc[mt][nt][3] + b1 };
            *(float2*)&C[(size_t)gr * Ntot + gc] = v0;
            *(float2*)&C[(size_t)(gr + 8) * Ntot + gc] = v1;
        }
    }
}

// ---------------------------------------------------------------------------
// Fused window attention; output written pre-split to bf16 hi/lo.
// ---------------------------------------------------------------------------
__global__ __launch_bounds__(256) void attn_kernel(
    const float* __restrict__ qkv, const float* __restrict__ mask,
    const float* __restrict__ table, const int* __restrict__ idx,
    __nv_bfloat16* __restrict__ out_hi, __nv_bfloat16* __restrict__ out_lo)
{
    const int bh = blockIdx.x;
    const int b = bh >> 4, hh = bh & 15;
    const int tid = threadIdx.x;

    __shared__ float qs[SEQ * 33];
    __shared__ float ks[SEQ * 33];
    __shared__ float vs[SEQ * 33];
    __shared__ float sc[SEQ * SEQ];

    const float scale = 0.17677669529663687f;
    const size_t rowbase = (size_t)b * SEQ * 1536;
    const int cq = hh * HD, ck = 512 + hh * HD, cv = 1024 + hh * HD;

    for (int i = tid; i < SEQ * HD; i += 256) {
        const int n = i >> 5, d = i & 31;
        const float* r = qkv + rowbase + (size_t)n * 1536;
        qs[n * 33 + d] = r[cq + d] * scale;
        ks[n * 33 + d] = r[ck + d];
        vs[n * 33 + d] = r[cv + d];
    }
    __syncthreads();

    const float* mrow = mask + (size_t)(b & (NW - 1)) * SEQ * SEQ;
    for (int p = tid; p < SEQ * SEQ; p += 256) {
        const int n = p / SEQ, m = p - n * SEQ;
        float s = 0.f;
#pragma unroll
        for (int d = 0; d < HD; d++) s += qs[n * 33 + d] * ks[m * 33 + d];
        s += table[idx[p] * NH + hh] + mrow[p];
        sc[p] = s;
    }
    __syncthreads();

    const int warp = tid >> 5, lane = tid & 31;
    for (int rr = warp; rr < SEQ; rr += 8) {
        float v0 = sc[rr * SEQ + lane];
        float v1 = (lane < SEQ - 32) ? sc[rr * SEQ + 32 + lane] : -1e30f;
        float mx = fmaxf(v0, v1);
#pragma unroll
        for (int o = 16; o > 0; o >>= 1)
            mx = fmaxf(mx, __shfl_xor_sync(0xffffffffu, mx, o));
        float e0 = __expf(v0 - mx);
        float e1 = (lane < SEQ - 32) ? __expf(v1 - mx) : 0.f;
        float sm = e0 + e1;
#pragma unroll
        for (int o = 16; o > 0; o >>= 1)
            sm += __shfl_xor_sync(0xffffffffu, sm, o);
        const float inv = __frcp_rn(sm);
        sc[rr * SEQ + lane] = e0 * inv;
        if (lane < SEQ - 32) sc[rr * SEQ + 32 + lane] = e1 * inv;
    }
    __syncthreads();

    for (int i = tid; i < SEQ * HD; i += 256) {
        const int n = i >> 5, d = i & 31;
        float acc = 0.f;
#pragma unroll
        for (int m = 0; m < SEQ; m++) acc += sc[n * SEQ + m] * vs[m * 33 + d];
        const size_t o = (size_t)(b * SEQ + n) * CDIM + hh * HD + d;
        __nv_bfloat16 h = __float2bfloat16_rn(acc);
        out_hi[o] = h;
        out_lo[o] = __float2bfloat16_rn(acc - __bfloat162float(h));
    }
}

// ---------------------------------------------------------------------------
extern "C" void kernel_launch(void* const* d_in, const int* in_sizes, int n_in,
                              void* d_out, int out_size)
{
    const float* x      = (const float*)d_in[0];
    const float* mask   = (const float*)d_in[1];
    const float* qkv_w  = (const float*)d_in[2];
    const float* qkv_b  = (const float*)d_in[3];
    const float* proj_w = (const float*)d_in[4];
    const float* proj_b = (const float*)d_in[5];
    const float* table  = (const float*)d_in[6];
    const int*   idx    = (const int*)d_in[7];
    float* out = (float*)d_out;

    float* qkv_s;
    __nv_bfloat16 *xh, *xl, *ah, *al, *qwh, *qwl, *pwh, *pwl;
    cudaGetSymbolAddress((void**)&qkv_s, g_qkv);
    cudaGetSymbolAddress((void**)&xh, g_x_hi);
    cudaGetSymbolAddress((void**)&xl, g_x_lo);
    cudaGetSymbolAddress((void**)&ah, g_att_hi);
    cudaGetSymbolAddress((void**)&al, g_att_lo);
    cudaGetSymbolAddress((void**)&qwh, g_qw_hi);
    cudaGetSymbolAddress((void**)&qwl, g_qw_lo);
    cudaGetSymbolAddress((void**)&pwh, g_pw_hi);
    cudaGetSymbolAddress((void**)&pwl, g_pw_lo);

    cudaFuncSetAttribute(gemm_bf16, cudaFuncAttributeMaxDynamicSharedMemorySize, GSMEM);

    // 0) split x into bf16 hi/lo, weights transpose+split
    const int n4 = MROWS * KDIM / 4;
    fsplit<<<(n4 + 255) / 256, 256>>>((const float4*)x, (uint2*)xh, (uint2*)xl, n4);
    wsplit<<<dim3(1536 / 32, 512 / 32), dim3(32, 8)>>>(qkv_w, qwh, qwl, 512, 1536);
    wsplit<<<dim3(512 / 32, 512 / 32), dim3(32, 8)>>>(proj_w, pwh, pwl, 512, 512);

    // 1) QKV projection (tensor cores via mma.sync)
    gemm_bf16<<<dim3(1536 / 128, MROWS / 128), 256, GSMEM>>>(
        xh, xl, qwh, qwl, qkv_b, qkv_s, 1536);

    // 2) fused window attention (writes split bf16)
    attn_kernel<<<B_WIN * NH, 256>>>(qkv_s, mask, table, idx, ah, al);

    // 3) output projection
    gemm_bf16<<<dim3(512 / 128, MROWS / 128), 256, GSMEM>>>(
        ah, al, pwh, pwl, proj_b, out, 512);
}

// round 5
// speedup vs baseline: 1.3990x; 1.3990x over previous
#include <cuda_runtime.h>
#include <cuda_fp16.h>
#include <cstdint>
#include <cstddef>

#define B_WIN 4096
#define SEQ   49
#define CDIM  512
#define NH    16
#define HD    32
#define NW    64
#define MROWS (B_WIN * SEQ)      // 200704
#define KDIM  512

// ---------------- device scratch (no cudaMalloc allowed) -------------------
__device__ float g_qkv[(size_t)MROWS * 1536];        // [B*N, 3C] fp32
__device__ __half g_x_h[(size_t)MROWS * KDIM];       // x fp16
__device__ __half g_att_h[(size_t)MROWS * KDIM];     // attn out fp16
__device__ __half g_qw_hi[1536 * KDIM];              // qkv_w^T split [N,K]
__device__ __half g_qw_lo[1536 * KDIM];
__device__ __half g_pw_hi[512 * KDIM];               // proj_w^T split [N,K]
__device__ __half g_pw_lo[512 * KDIM];

// ---------------- helpers (arch-portable PTX: sm_80+ features only) --------
__device__ __forceinline__ uint32_t smem_u32(const void* p) {
    uint32_t a;
    asm("{ .reg .u64 t; cvta.to.shared.u64 t, %1; cvt.u32.u64 %0, t; }"
        : "=r"(a) : "l"(p));
    return a;
}
#define CPA16(dst, src) \
    asm volatile("cp.async.cg.shared.global [%0], [%1], 16;" \
                 :: "r"(dst), "l"(src) : "memory")
#define CPCOMMIT() asm volatile("cp.async.commit_group;" ::: "memory")
#define CPWAIT(n)  asm volatile("cp.async.wait_group %0;" :: "n"(n) : "memory")
#define LDSM4(r, addr)                                                        \
    asm volatile("ldmatrix.sync.aligned.m8n8.x4.shared.b16 {%0,%1,%2,%3}, [%4];" \
        : "=r"((r)[0]), "=r"((r)[1]), "=r"((r)[2]), "=r"((r)[3]) : "r"(addr))
#define MMA_F16(d, a, b0, b1)                                                 \
    asm volatile("mma.sync.aligned.m16n8k16.row.col.f32.f16.f16.f32 "         \
        "{%0,%1,%2,%3},{%4,%5,%6,%7},{%8,%9},{%0,%1,%2,%3};"                  \
        : "+f"((d)[0]), "+f"((d)[1]), "+f"((d)[2]), "+f"((d)[3])              \
        : "r"((a)[0]), "r"((a)[1]), "r"((a)[2]), "r"((a)[3]),                 \
          "r"(b0), "r"(b1))

// ---------------------------------------------------------------------------
// fp32 -> fp16 convert (activations)
// ---------------------------------------------------------------------------
__global__ void fconv(const float4* __restrict__ in, uint2* __restrict__ out, int n4)
{
    const int i = blockIdx.x * blockDim.x + threadIdx.x;
    if (i >= n4) return;
    float4 v = in[i];
    __half2 a = __floats2half2_rn(v.x, v.y);
    __half2 b = __floats2half2_rn(v.z, v.w);
    uint2 o = { *(uint32_t*)&a, *(uint32_t*)&b };
    out[i] = o;
}

// ---------------------------------------------------------------------------
// Weight prep: W[K,N] fp32 -> Bhi/Blo[N,K] fp16 (transposed + split)
// ---------------------------------------------------------------------------
__global__ void wsplit(const float* __restrict__ W, __half* __restrict__ Bhi,
                       __half* __restrict__ Blo, int K, int N)
{
    __shared__ float t[32][33];
    const int bx = blockIdx.x, by = blockIdx.y;
    const int x = threadIdx.x, y = threadIdx.y;   // 32 x 8
#pragma unroll
    for (int i = 0; i < 4; i++)
        t[y + i * 8][x] = W[(size_t)(by * 32 + y + i * 8) * N + bx * 32 + x];
    __syncthreads();
#pragma unroll
    for (int i = 0; i < 4; i++) {
        float v = t[x][y + i * 8];
        __half h = __float2half_rn(v);
        size_t o = (size_t)(bx * 32 + y + i * 8) * K + by * 32 + x;
        Bhi[o] = h;
        Blo[o] = __float2half_rn(v - __half2float(h));
    }
}

// ---------------------------------------------------------------------------
// fp16 mma.sync GEMM, 2-term weight split:
//   C[M,Ntot] = A[M,512] @ (Bhi+Blo)[N,512]^T + bias
// CTA 128x128, BK=32, cp.async double buffer (R3-proven structure),
// 8 warps x (64x32). SMEM rows stride 80B -> conflict-free ldmatrix.
// ---------------------------------------------------------------------------
#define RS        80
#define AT_BYTES  (128 * RS)        // 10240 per tensor tile
#define STAGE     (3 * AT_BYTES)    // 30720 per stage (A, Bhi, Blo)
#define GSMEM     (2 * STAGE)       // 61440

__global__ __launch_bounds__(256, 2)
void gemm_f16(const __half* __restrict__ A_g,
              const __half* __restrict__ Bhi_g,
              const __half* __restrict__ Blo_g,
              const float* __restrict__ bias, float* __restrict__ C, int Ntot)
{
    extern __shared__ __align__(128) char sm[];
    const uint32_t sb = smem_u32(sm);
    const int tid = threadIdx.x;
    const int lane = tid & 31, wid = tid >> 5;
    const int m0 = blockIdx.y * 128, n0 = blockIdx.x * 128;
    const int wm = (wid >> 2) * 64, wn = (wid & 3) * 32;

    // copy roles: thread -> (row, 32B half of the 64B k-chunk)
    const int crow = tid >> 1;
    const int cc   = (tid & 1) * 32;

    const char* gsrc0 = (const char*)(A_g   + (size_t)m0 * KDIM);
    const char* gsrc1 = (const char*)(Bhi_g + (size_t)n0 * KDIM);
    const char* gsrc2 = (const char*)(Blo_g + (size_t)n0 * KDIM);

    float acc[4][4][4];
#pragma unroll
    for (int a = 0; a < 4; a++)
#pragma unroll
        for (int b = 0; b < 4; b++)
#pragma unroll
            for (int c = 0; c < 4; c++) acc[a][b][c] = 0.f;

    auto issue = [&](int s, int kc) {
        const int gofs = crow * 1024 + kc * 64 + cc;   // 512 fp16 = 1024B rows
        const uint32_t dst = sb + s * STAGE + crow * RS + cc;
        CPA16(dst + 0 * AT_BYTES,      gsrc0 + gofs);
        CPA16(dst + 0 * AT_BYTES + 16, gsrc0 + gofs + 16);
        CPA16(dst + 1 * AT_BYTES,      gsrc1 + gofs);
        CPA16(dst + 1 * AT_BYTES + 16, gsrc1 + gofs + 16);
        CPA16(dst + 2 * AT_BYTES,      gsrc2 + gofs);
        CPA16(dst + 2 * AT_BYTES + 16, gsrc2 + gofs + 16);
        CPCOMMIT();
    };

    issue(0, 0);
    issue(1, 1);

    const int r = lane & 15;
    const uint32_t khalf = (lane >> 4) * 16;

    for (int kc = 0; kc < 16; kc++) {
        const int s = kc & 1;
        if (kc < 15) { CPWAIT(1); } else { CPWAIT(0); }
        __syncthreads();

        const uint32_t base = sb + s * STAGE;
#pragma unroll
        for (int kk = 0; kk < 2; kk++) {
            const uint32_t ko = kk * 32 + khalf;
            uint32_t ah[4][4], bh[2][4], bl[2][4];
#pragma unroll
            for (int mt = 0; mt < 4; mt++) {
                const uint32_t ra = base + (uint32_t)(wm + mt * 16 + r) * RS + ko;
                LDSM4(ah[mt], ra);
            }
#pragma unroll
            for (int p = 0; p < 2; p++) {
                const uint32_t rb = base + AT_BYTES +
                                    (uint32_t)(wn + p * 16 + r) * RS + ko;
                LDSM4(bh[p], rb);
                LDSM4(bl[p], rb + AT_BYTES);
            }
#pragma unroll
            for (int mt = 0; mt < 4; mt++)
#pragma unroll
                for (int nt = 0; nt < 4; nt++) {
                    const int p = nt >> 1, o = nt & 1;
                    MMA_F16(acc[mt][nt], ah[mt], bh[p][o], bh[p][o + 2]);
                    MMA_F16(acc[mt][nt], ah[mt], bl[p][o], bl[p][o + 2]);
                }
        }
        __syncthreads();
        if (kc + 2 < 16) issue(s, kc + 2);
    }

    // epilogue + bias
#pragma unroll
    for (int mt = 0; mt < 4; mt++) {
        const int gr = m0 + wm + mt * 16 + (lane >> 2);
#pragma unroll
        for (int nt = 0; nt < 4; nt++) {
            const int gc = n0 + wn + nt * 8 + (lane & 3) * 2;
            const float b0 = bias[gc], b1 = bias[gc + 1];
            float2 v0 = { acc[mt][nt][0] + b0, acc[mt][nt][1] + b1 };
            float2 v1 = { acc[mt][nt][2] + b0, acc[mt][nt][3] + b1 };
            *(float2*)&C[(size_t)gr * Ntot + gc] = v0;
            *(float2*)&C[(size_t)(gr + 8) * Ntot + gc] = v1;
        }
    }
}

// ---------------------------------------------------------------------------
// Fused window attention; output written as fp16 for the proj GEMM.
// ---------------------------------------------------------------------------
__global__ __launch_bounds__(256) void attn_kernel(
    const float* __restrict__ qkv, const float* __restrict__ mask,
    const float* __restrict__ table, const int* __restrict__ idx,
    __half* __restrict__ out_h)
{
    const int bh = blockIdx.x;
    const int b = bh >> 4, hh = bh & 15;
    const int tid = threadIdx.x;

    __shared__ float qs[SEQ * 33];
    __shared__ float ks[SEQ * 33];
    __shared__ float vs[SEQ * 33];
    __shared__ float sc[SEQ * SEQ];

    const float scale = 0.17677669529663687f;
    const size_t rowbase = (size_t)b * SEQ * 1536;
    const int cq = hh * HD, ck = 512 + hh * HD, cv = 1024 + hh * HD;

    for (int i = tid; i < SEQ * HD; i += 256) {
        const int n = i >> 5, d = i & 31;
        const float* r = qkv + rowbase + (size_t)n * 1536;
        qs[n * 33 + d] = r[cq + d] * scale;
        ks[n * 33 + d] = r[ck + d];
        vs[n * 33 + d] = r[cv + d];
    }
    __syncthreads();

    const float* mrow = mask + (size_t)(b & (NW - 1)) * SEQ * SEQ;
    for (int p = tid; p < SEQ * SEQ; p += 256) {
        const int n = p / SEQ, m = p - n * SEQ;
        float s = 0.f;
#pragma unroll
        for (int d = 0; d < HD; d++) s += qs[n * 33 + d] * ks[m * 33 + d];
        s += table[idx[p] * NH + hh] + mrow[p];
        sc[p] = s;
    }
    __syncthreads();

    const int warp = tid >> 5, lane = tid & 31;
    for (int rr = warp; rr < SEQ; rr += 8) {
        float v0 = sc[rr * SEQ + lane];
        float v1 = (lane < SEQ - 32) ? sc[rr * SEQ + 32 + lane] : -1e30f;
        float mx = fmaxf(v0, v1);
#pragma unroll
        for (int o = 16; o > 0; o >>= 1)
            mx = fmaxf(mx, __shfl_xor_sync(0xffffffffu, mx, o));
        float e0 = __expf(v0 - mx);
        float e1 = (lane < SEQ - 32) ? __expf(v1 - mx) : 0.f;
        float sm = e0 + e1;
#pragma unroll
        for (int o = 16; o > 0; o >>= 1)
            sm += __shfl_xor_sync(0xffffffffu, sm, o);
        const float inv = __frcp_rn(sm);
        sc[rr * SEQ + lane] = e0 * inv;
        if (lane < SEQ - 32) sc[rr * SEQ + 32 + lane] = e1 * inv;
    }
    __syncthreads();

    for (int i = tid; i < SEQ * HD; i += 256) {
        const int n = i >> 5, d = i & 31;
        float acc = 0.f;
#pragma unroll
        for (int m = 0; m < SEQ; m++) acc += sc[n * SEQ + m] * vs[m * 33 + d];
        out_h[(size_t)(b * SEQ + n) * CDIM + hh * HD + d] = __float2half_rn(acc);
    }
}

// ---------------------------------------------------------------------------
extern "C" void kernel_launch(void* const* d_in, const int* in_sizes, int n_in,
                              void* d_out, int out_size)
{
    const float* x      = (const float*)d_in[0];
    const float* mask   = (const float*)d_in[1];
    const float* qkv_w  = (const float*)d_in[2];
    const float* qkv_b  = (const float*)d_in[3];
    const float* proj_w = (const float*)d_in[4];
    const float* proj_b = (const float*)d_in[5];
    const float* table  = (const float*)d_in[6];
    const int*   idx    = (const int*)d_in[7];
    float* out = (float*)d_out;

    float* qkv_s;
    __half *xh, *ath, *qwh, *qwl, *pwh, *pwl;
    cudaGetSymbolAddress((void**)&qkv_s, g_qkv);
    cudaGetSymbolAddress((void**)&xh, g_x_h);
    cudaGetSymbolAddress((void**)&ath, g_att_h);
    cudaGetSymbolAddress((void**)&qwh, g_qw_hi);
    cudaGetSymbolAddress((void**)&qwl, g_qw_lo);
    cudaGetSymbolAddress((void**)&pwh, g_pw_hi);
    cudaGetSymbolAddress((void**)&pwl, g_pw_lo);

    cudaFuncSetAttribute(gemm_f16, cudaFuncAttributeMaxDynamicSharedMemorySize, GSMEM);

    // 0) convert x to fp16, weights transpose+split
    const int n4 = MROWS * KDIM / 4;
    fconv<<<(n4 + 255) / 256, 256>>>((const float4*)x, (uint2*)xh, n4);
    wsplit<<<dim3(1536 / 32, 512 / 32), dim3(32, 8)>>>(qkv_w, qwh, qwl, 512, 1536);
    wsplit<<<dim3(512 / 32, 512 / 32), dim3(32, 8)>>>(proj_w, pwh, pwl, 512, 512);

    // 1) QKV projection (tensor cores via mma.sync, 2-term fp16)
    gemm_f16<<<dim3(1536 / 128, MROWS / 128), 256, GSMEM>>>(
        xh, qwh, qwl, qkv_b, qkv_s, 1536);

    // 2) fused window attention (writes fp16)
    attn_kernel<<<B_WIN * NH, 256>>>(qkv_s, mask, table, idx, ath);

    // 3) output projection
    gemm_f16<<<dim3(512 / 128, MROWS / 128), 256, GSMEM>>>(
        ath, pwh, pwl, proj_b, out, 512);
}

// round 7
// speedup vs baseline: 1.4129x; 1.0099x over previous
#include <cuda_runtime.h>
#include <cuda_fp16.h>
#include <cstdint>
#include <cstddef>

#define B_WIN 4096
#define SEQ   49
#define CDIM  512
#define NH    16
#define HD    32
#define NW    64
#define MROWS (B_WIN * SEQ)      // 200704
#define KDIM  512

// ---------------- device scratch (no cudaMalloc allowed) -------------------
__device__ float g_qkv[(size_t)MROWS * 1536];        // [B*N, 3C] fp32
__device__ __half g_x_h[(size_t)MROWS * KDIM];       // x fp16
__device__ __half g_att_h[(size_t)MROWS * KDIM];     // attn out fp16
__device__ __half g_qw_hi[1536 * KDIM];              // qkv_w^T split [N,K]
__device__ __half g_qw_lo[1536 * KDIM];
__device__ __half g_pw_hi[512 * KDIM];               // proj_w^T split [N,K]
__device__ __half g_pw_lo[512 * KDIM];

// ---------------- helpers (arch-portable PTX: sm_80+ features only) --------
__device__ __forceinline__ uint32_t smem_u32(const void* p) {
    uint32_t a;
    asm("{ .reg .u64 t; cvta.to.shared.u64 t, %1; cvt.u32.u64 %0, t; }"
        : "=r"(a) : "l"(p));
    return a;
}
#define CPA16(dst, src) \
    asm volatile("cp.async.cg.shared.global [%0], [%1], 16;" \
                 :: "r"(dst), "l"(src) : "memory")
#define CPCOMMIT() asm volatile("cp.async.commit_group;" ::: "memory")
#define CPWAIT(n)  asm volatile("cp.async.wait_group %0;" :: "n"(n) : "memory")
#define LDSM4(r, addr)                                                        \
    asm volatile("ldmatrix.sync.aligned.m8n8.x4.shared.b16 {%0,%1,%2,%3}, [%4];" \
        : "=r"((r)[0]), "=r"((r)[1]), "=r"((r)[2]), "=r"((r)[3]) : "r"(addr))
#define MMA_F16(d, a, b0, b1)                                                 \
    asm volatile("mma.sync.aligned.m16n8k16.row.col.f32.f16.f16.f32 "         \
        "{%0,%1,%2,%3},{%4,%5,%6,%7},{%8,%9},{%0,%1,%2,%3};"                  \
        : "+f"((d)[0]), "+f"((d)[1]), "+f"((d)[2]), "+f"((d)[3])              \
        : "r"((a)[0]), "r"((a)[1]), "r"((a)[2]), "r"((a)[3]),                 \
          "r"(b0), "r"(b1))

// ---------------------------------------------------------------------------
// fp32 -> fp16 convert (activations)
// ---------------------------------------------------------------------------
__global__ void fconv(const float4* __restrict__ in, uint2* __restrict__ out, int n4)
{
    const int i = blockIdx.x * blockDim.x + threadIdx.x;
    if (i >= n4) return;
    float4 v = in[i];
    __half2 a = __floats2half2_rn(v.x, v.y);
    __half2 b = __floats2half2_rn(v.z, v.w);
    uint2 o = { *(uint32_t*)&a, *(uint32_t*)&b };
    out[i] = o;
}

// ---------------------------------------------------------------------------
// Weight prep: W[K,N] fp32 -> Bhi/Blo[N,K] fp16 (transposed + split)
// ---------------------------------------------------------------------------
__global__ void wsplit(const float* __restrict__ W, __half* __restrict__ Bhi,
                       __half* __restrict__ Blo, int K, int N)
{
    __shared__ float t[32][33];
    const int bx = blockIdx.x, by = blockIdx.y;
    const int x = threadIdx.x, y = threadIdx.y;   // 32 x 8
#pragma unroll
    for (int i = 0; i < 4; i++)
        t[y + i * 8][x] = W[(size_t)(by * 32 + y + i * 8) * N + bx * 32 + x];
    __syncthreads();
#pragma unroll
    for (int i = 0; i < 4; i++) {
        float v = t[x][y + i * 8];
        __half h = __float2half_rn(v);
        size_t o = (size_t)(bx * 32 + y + i * 8) * K + by * 32 + x;
        Bhi[o] = h;
        Blo[o] = __float2half_rn(v - __half2float(h));
    }
}

// ---------------------------------------------------------------------------
// fp16 mma.sync GEMM, 2-term weight split, 3-stage cp.async pipeline,
// ONE __syncthreads per K-chunk.
//   C[M,Ntot] = A[M,512] @ (Bhi+Blo)[N,512]^T + bias
// CTA 128x128, BK=32, 8 warps x (64x32). 80B-stride rows (conflict-free).
// Safety: barrier at chunk kc proves stage (kc-1)%3 is no longer read;
// prefetch for kc+2 writes exactly that stage.
// ---------------------------------------------------------------------------
#define RS        80
#define AT_BYTES  (128 * RS)        // 10240 per tensor tile
#define STAGE     (3 * AT_BYTES)    // 30720 per stage (A, Bhi, Blo)
#define NSTAGE    3
#define GSMEM     (NSTAGE * STAGE)  // 92160 -> 2 CTAs/SM

__global__ __launch_bounds__(256, 2)
void gemm_f16(const __half* __restrict__ A_g,
              const __half* __restrict__ Bhi_g,
              const __half* __restrict__ Blo_g,
              const float* __restrict__ bias, float* __restrict__ C, int Ntot)
{
    extern __shared__ __align__(128) char sm[];
    const uint32_t sb = smem_u32(sm);
    const int tid = threadIdx.x;
    const int lane = tid & 31, wid = tid >> 5;
    const int m0 = blockIdx.y * 128, n0 = blockIdx.x * 128;
    const int wm = (wid >> 2) * 64, wn = (wid & 3) * 32;

    // copy roles: thread -> (row, 32B half of the 64B k-chunk)
    const int crow = tid >> 1;
    const int cc   = (tid & 1) * 32;

    const char* gsrc0 = (const char*)(A_g   + (size_t)m0 * KDIM);
    const char* gsrc1 = (const char*)(Bhi_g + (size_t)n0 * KDIM);
    const char* gsrc2 = (const char*)(Blo_g + (size_t)n0 * KDIM);

    float acc[4][4][4];
#pragma unroll
    for (int a = 0; a < 4; a++)
#pragma unroll
        for (int b = 0; b < 4; b++)
#pragma unroll
            for (int c = 0; c < 4; c++) acc[a][b][c] = 0.f;

    auto issue = [&](int s, int kc) {
        const int gofs = crow * 1024 + kc * 64 + cc;   // 512 fp16 = 1024B rows
        const uint32_t dst = sb + s * STAGE + crow * RS + cc;
        CPA16(dst + 0 * AT_BYTES,      gsrc0 + gofs);
        CPA16(dst + 0 * AT_BYTES + 16, gsrc0 + gofs + 16);
        CPA16(dst + 1 * AT_BYTES,      gsrc1 + gofs);
        CPA16(dst + 1 * AT_BYTES + 16, gsrc1 + gofs + 16);
        CPA16(dst + 2 * AT_BYTES,      gsrc2 + gofs);
        CPA16(dst + 2 * AT_BYTES + 16, gsrc2 + gofs + 16);
        CPCOMMIT();
    };

    issue(0, 0);
    issue(1, 1);

    const int r = lane & 15;
    const uint32_t khalf = (lane >> 4) * 16;

    for (int kc = 0; kc < 16; kc++) {
        const int s = kc % NSTAGE;
        if (kc < 15) { CPWAIT(1); } else { CPWAIT(0); }
        __syncthreads();                       // the ONLY barrier per chunk
        if (kc + 2 < 16) issue((kc + 2) % NSTAGE, kc + 2);

        const uint32_t base = sb + s * STAGE;
#pragma unroll
        for (int kk = 0; kk < 2; kk++) {
            const uint32_t ko = kk * 32 + khalf;
            uint32_t ah[4][4], bh[2][4], bl[2][4];
#pragma unroll
            for (int mt = 0; mt < 4; mt++) {
                const uint32_t ra = base + (uint32_t)(wm + mt * 16 + r) * RS + ko;
                LDSM4(ah[mt], ra);
            }
#pragma unroll
            for (int p = 0; p < 2; p++) {
                const uint32_t rb = base + AT_BYTES +
                                    (uint32_t)(wn + p * 16 + r) * RS + ko;
                LDSM4(bh[p], rb);
                LDSM4(bl[p], rb + AT_BYTES);
            }
#pragma unroll
            for (int mt = 0; mt < 4; mt++)
#pragma unroll
                for (int nt = 0; nt < 4; nt++) {
                    const int p = nt >> 1, o = nt & 1;
                    MMA_F16(acc[mt][nt], ah[mt], bh[p][o], bh[p][o + 2]);
                    MMA_F16(acc[mt][nt], ah[mt], bl[p][o], bl[p][o + 2]);
                }
        }
    }

    // epilogue + bias
#pragma unroll
    for (int mt = 0; mt < 4; mt++) {
        const int gr = m0 + wm + mt * 16 + (lane >> 2);
#pragma unroll
        for (int nt = 0; nt < 4; nt++) {
            const int gc = n0 + wn + nt * 8 + (lane & 3) * 2;
            const float b0 = bias[gc], b1 = bias[gc + 1];
            float2 v0 = { acc[mt][nt][0] + b0, acc[mt][nt][1] + b1 };
            float2 v1 = { acc[mt][nt][2] + b0, acc[mt][nt][3] + b1 };
            *(float2*)&C[(size_t)gr * Ntot + gc] = v0;
            *(float2*)&C[(size_t)(gr + 8) * Ntot + gc] = v1;
        }
    }
}

// ---------------------------------------------------------------------------
// Fused window attention; output written as fp16 for the proj GEMM.
// ---------------------------------------------------------------------------
__global__ __launch_bounds__(256) void attn_kernel(
    const float* __restrict__ qkv, const float* __restrict__ mask,
    const float* __restrict__ table, const int* __restrict__ idx,
    __half* __restrict__ out_h)
{
    const int bh = blockIdx.x;
    const int b = bh >> 4, hh = bh & 15;
    const int tid = threadIdx.x;

    __shared__ float qs[SEQ * 33];
    __shared__ float ks[SEQ * 33];
    __shared__ float vs[SEQ * 33];
    __shared__ float sc[SEQ * SEQ];

    const float scale = 0.17677669529663687f;
    const size_t rowbase = (size_t)b * SEQ * 1536;
    const int cq = hh * HD, ck = 512 + hh * HD, cv = 1024 + hh * HD;

    for (int i = tid; i < SEQ * HD; i += 256) {
        const int n = i >> 5, d = i & 31;
        const float* r = qkv + rowbase + (size_t)n * 1536;
        qs[n * 33 + d] = r[cq + d] * scale;
        ks[n * 33 + d] = r[ck + d];
        vs[n * 33 + d] = r[cv + d];
    }
    __syncthreads();

    const float* mrow = mask + (size_t)(b & (NW - 1)) * SEQ * SEQ;
    for (int p = tid; p < SEQ * SEQ; p += 256) {
        const int n = p / SEQ, m = p - n * SEQ;
        float s = 0.f;
#pragma unroll
        for (int d = 0; d < HD; d++) s += qs[n * 33 + d] * ks[m * 33 + d];
        s += table[idx[p] * NH + hh] + mrow[p];
        sc[p] = s;
    }
    __syncthreads();

    const int warp = tid >> 5, lane = tid & 31;
    for (int rr = warp; rr < SEQ; rr += 8) {
        float v0 = sc[rr * SEQ + lane];
        float v1 = (lane < SEQ - 32) ? sc[rr * SEQ + 32 + lane] : -1e30f;
        float mx = fmaxf(v0, v1);
#pragma unroll
        for (int o = 16; o > 0; o >>= 1)
            mx = fmaxf(mx, __shfl_xor_sync(0xffffffffu, mx, o));
        float e0 = __expf(v0 - mx);
        float e1 = (lane < SEQ - 32) ? __expf(v1 - mx) : 0.f;
        float sm = e0 + e1;
#pragma unroll
        for (int o = 16; o > 0; o >>= 1)
            sm += __shfl_xor_sync(0xffffffffu, sm, o);
        const float inv = __frcp_rn(sm);
        sc[rr * SEQ + lane] = e0 * inv;
        if (lane < SEQ - 32) sc[rr * SEQ + 32 + lane] = e1 * inv;
    }
    __syncthreads();

    for (int i = tid; i < SEQ * HD; i += 256) {
        const int n = i >> 5, d = i & 31;
        float acc = 0.f;
#pragma unroll
        for (int m = 0; m < SEQ; m++) acc += sc[n * SEQ + m] * vs[m * 33 + d];
        out_h[(size_t)(b * SEQ + n) * CDIM + hh * HD + d] = __float2half_rn(acc);
    }
}

// ---------------------------------------------------------------------------
extern "C" void kernel_launch(void* const* d_in, const int* in_sizes, int n_in,
                              void* d_out, int out_size)
{
    const float* x      = (const float*)d_in[0];
    const float* mask   = (const float*)d_in[1];
    const float* qkv_w  = (const float*)d_in[2];
    const float* qkv_b  = (const float*)d_in[3];
    const float* proj_w = (const float*)d_in[4];
    const float* proj_b = (const float*)d_in[5];
    const float* table  = (const float*)d_in[6];
    const int*   idx    = (const int*)d_in[7];
    float* out = (float*)d_out;

    float* qkv_s;
    __half *xh, *ath, *qwh, *qwl, *pwh, *pwl;
    cudaGetSymbolAddress((void**)&qkv_s, g_qkv);
    cudaGetSymbolAddress((void**)&xh, g_x_h);
    cudaGetSymbolAddress((void**)&ath, g_att_h);
    cudaGetSymbolAddress((void**)&qwh, g_qw_hi);
    cudaGetSymbolAddress((void**)&qwl, g_qw_lo);
    cudaGetSymbolAddress((void**)&pwh, g_pw_hi);
    cudaGetSymbolAddress((void**)&pwl, g_pw_lo);

    cudaFuncSetAttribute(gemm_f16, cudaFuncAttributeMaxDynamicSharedMemorySize, GSMEM);

    // 0) convert x to fp16, weights transpose+split
    const int n4 = MROWS * KDIM / 4;
    fconv<<<(n4 + 255) / 256, 256>>>((const float4*)x, (uint2*)xh, n4);
    wsplit<<<dim3(1536 / 32, 512 / 32), dim3(32, 8)>>>(qkv_w, qwh, qwl, 512, 1536);
    wsplit<<<dim3(512 / 32, 512 / 32), dim3(32, 8)>>>(proj_w, pwh, pwl, 512, 512);

    // 1) QKV projection (tensor cores via mma.sync, 2-term fp16)
    gemm_f16<<<dim3(1536 / 128, MROWS / 128), 256, GSMEM>>>(
        xh, qwh, qwl, qkv_b, qkv_s, 1536);

    // 2) fused window attention (writes fp16)
    attn_kernel<<<B_WIN * NH, 256>>>(qkv_s, mask, table, idx, ath);

    // 3) output projection
    gemm_f16<<<dim3(512 / 128, MROWS / 128), 256, GSMEM>>>(
        ath, pwh, pwl, proj_b, out, 512);
}

// round 8
// speedup vs baseline: 2.0632x; 1.4602x over previous
#include <cuda_runtime.h>
#include <cuda_fp16.h>
#include <cstdint>
#include <cstddef>

#define B_WIN 4096
#define SEQ   49
#define CDIM  512
#define NH    16
#define HD    32
#define NW    64
#define MROWS (B_WIN * SEQ)      // 200704
#define KDIM  512

// ---------------- device scratch (no cudaMalloc allowed) -------------------
__device__ float g_qkv[(size_t)MROWS * 1536];        // [B*N, 3C] fp32
__device__ __half g_x_h[(size_t)MROWS * KDIM];       // x fp16
__device__ __half g_att_h[(size_t)MROWS * KDIM];     // attn out fp16
__device__ __half g_qw_hi[1536 * KDIM];              // qkv_w^T split [N,K]
__device__ __half g_qw_lo[1536 * KDIM];
__device__ __half g_pw_hi[512 * KDIM];               // proj_w^T split [N,K]
__device__ __half g_pw_lo[512 * KDIM];
__device__ float g_cmb[(size_t)NW * NH * 64 * 64];   // bias+mask, padded

// ---------------- helpers (arch-portable PTX: sm_80+ features only) --------
__device__ __forceinline__ uint32_t smem_u32(const void* p) {
    uint32_t a;
    asm("{ .reg .u64 t; cvta.to.shared.u64 t, %1; cvt.u32.u64 %0, t; }"
        : "=r"(a) : "l"(p));
    return a;
}
#define CPA16(dst, src) \
    asm volatile("cp.async.cg.shared.global [%0], [%1], 16;" \
                 :: "r"(dst), "l"(src) : "memory")
#define CPCOMMIT() asm volatile("cp.async.commit_group;" ::: "memory")
#define CPWAIT(n)  asm volatile("cp.async.wait_group %0;" :: "n"(n) : "memory")
#define LDSM4(r, addr)                                                        \
    asm volatile("ldmatrix.sync.aligned.m8n8.x4.shared.b16 {%0,%1,%2,%3}, [%4];" \
        : "=r"((r)[0]), "=r"((r)[1]), "=r"((r)[2]), "=r"((r)[3]) : "r"(addr))
#define LDSM4T(r, addr)                                                       \
    asm volatile("ldmatrix.sync.aligned.m8n8.x4.trans.shared.b16 {%0,%1,%2,%3}, [%4];" \
        : "=r"((r)[0]), "=r"((r)[1]), "=r"((r)[2]), "=r"((r)[3]) : "r"(addr))
#define MMA_F16(d, a, b0, b1)                                                 \
    asm volatile("mma.sync.aligned.m16n8k16.row.col.f32.f16.f16.f32 "         \
        "{%0,%1,%2,%3},{%4,%5,%6,%7},{%8,%9},{%0,%1,%2,%3};"                  \
        : "+f"((d)[0]), "+f"((d)[1]), "+f"((d)[2]), "+f"((d)[3])              \
        : "r"((a)[0]), "r"((a)[1]), "r"((a)[2]), "r"((a)[3]),                 \
          "r"(b0), "r"(b1))

__device__ __forceinline__ void hsplit2(float a, float b, uint32_t& hi, uint32_t& lo) {
    __half2 h = __floats2half2_rn(a, b);
    float2 hf = __half22float2(h);
    __half2 l = __floats2half2_rn(a - hf.x, b - hf.y);
    hi = *(uint32_t*)&h;
    lo = *(uint32_t*)&l;
}

// ---------------------------------------------------------------------------
// fp32 -> fp16 convert (activations)
// ---------------------------------------------------------------------------
__global__ void fconv(const float4* __restrict__ in, uint2* __restrict__ out, int n4)
{
    const int i = blockIdx.x * blockDim.x + threadIdx.x;
    if (i >= n4) return;
    float4 v = in[i];
    __half2 a = __floats2half2_rn(v.x, v.y);
    __half2 b = __floats2half2_rn(v.z, v.w);
    uint2 o = { *(uint32_t*)&a, *(uint32_t*)&b };
    out[i] = o;
}

// ---------------------------------------------------------------------------
// Weight prep: W[K,N] fp32 -> Bhi/Blo[N,K] fp16 (transposed + split)
// ---------------------------------------------------------------------------
__global__ void wsplit(const float* __restrict__ W, __half* __restrict__ Bhi,
                       __half* __restrict__ Blo, int K, int N)
{
    __shared__ float t[32][33];
    const int bx = blockIdx.x, by = blockIdx.y;
    const int x = threadIdx.x, y = threadIdx.y;   // 32 x 8
#pragma unroll
    for (int i = 0; i < 4; i++)
        t[y + i * 8][x] = W[(size_t)(by * 32 + y + i * 8) * N + bx * 32 + x];
    __syncthreads();
#pragma unroll
    for (int i = 0; i < 4; i++) {
        float v = t[x][y + i * 8];
        __half h = __float2half_rn(v);
        size_t o = (size_t)(bx * 32 + y + i * 8) * K + by * 32 + x;
        Bhi[o] = h;
        Blo[o] = __float2half_rn(v - __half2float(h));
    }
}

// ---------------------------------------------------------------------------
// cmb[w][h][n][m] = bias(h,n,m) + mask(w,n,m), padded 64x64 (pad cols = -1e9)
// ---------------------------------------------------------------------------
__global__ void cmb_prep(const float* __restrict__ mask, const float* __restrict__ table,
                         const int* __restrict__ idx, float* __restrict__ cmb)
{
    const int w = blockIdx.x, h = blockIdx.y;
    float* dst = cmb + (((size_t)w * NH + h) << 12);
    for (int i = threadIdx.x; i < 4096; i += 256) {
        const int n = i >> 6, m = i & 63;
        float v;
        if (m >= SEQ)      v = -1e9f;
        else if (n >= SEQ) v = 0.f;
        else v = table[idx[n * SEQ + m] * NH + h] + mask[(size_t)w * SEQ * SEQ + n * SEQ + m];
        dst[i] = v;
    }
}

// ---------------------------------------------------------------------------
// fp16 mma.sync GEMM (unchanged from R7 — passing, 47% tensor)
// ---------------------------------------------------------------------------
#define RS        80
#define AT_BYTES  (128 * RS)
#define STAGE     (3 * AT_BYTES)
#define NSTAGE    3
#define GSMEM     (NSTAGE * STAGE)

__global__ __launch_bounds__(256, 2)
void gemm_f16(const __half* __restrict__ A_g,
              const __half* __restrict__ Bhi_g,
              const __half* __restrict__ Blo_g,
              const float* __restrict__ bias, float* __restrict__ C, int Ntot)
{
    extern __shared__ __align__(128) char sm[];
    const uint32_t sb = smem_u32(sm);
    const int tid = threadIdx.x;
    const int lane = tid & 31, wid = tid >> 5;
    const int m0 = blockIdx.y * 128, n0 = blockIdx.x * 128;
    const int wm = (wid >> 2) * 64, wn = (wid & 3) * 32;

    const int crow = tid >> 1;
    const int cc   = (tid & 1) * 32;

    const char* gsrc0 = (const char*)(A_g   + (size_t)m0 * KDIM);
    const char* gsrc1 = (const char*)(Bhi_g + (size_t)n0 * KDIM);
    const char* gsrc2 = (const char*)(Blo_g + (size_t)n0 * KDIM);

    float acc[4][4][4];
#pragma unroll
    for (int a = 0; a < 4; a++)
#pragma unroll
        for (int b = 0; b < 4; b++)
#pragma unroll
            for (int c = 0; c < 4; c++) acc[a][b][c] = 0.f;

    auto issue = [&](int s, int kc) {
        const int gofs = crow * 1024 + kc * 64 + cc;
        const uint32_t dst = sb + s * STAGE + crow * RS + cc;
        CPA16(dst + 0 * AT_BYTES,      gsrc0 + gofs);
        CPA16(dst + 0 * AT_BYTES + 16, gsrc0 + gofs + 16);
        CPA16(dst + 1 * AT_BYTES,      gsrc1 + gofs);
        CPA16(dst + 1 * AT_BYTES + 16, gsrc1 + gofs + 16);
        CPA16(dst + 2 * AT_BYTES,      gsrc2 + gofs);
        CPA16(dst + 2 * AT_BYTES + 16, gsrc2 + gofs + 16);
        CPCOMMIT();
    };

    issue(0, 0);
    issue(1, 1);

    const int r = lane & 15;
    const uint32_t khalf = (lane >> 4) * 16;

    for (int kc = 0; kc < 16; kc++) {
        const int s = kc % NSTAGE;
        if (kc < 15) { CPWAIT(1); } else { CPWAIT(0); }
        __syncthreads();
        if (kc + 2 < 16) issue((kc + 2) % NSTAGE, kc + 2);

        const uint32_t base = sb + s * STAGE;
#pragma unroll
        for (int kk = 0; kk < 2; kk++) {
            const uint32_t ko = kk * 32 + khalf;
            uint32_t ah[4][4], bh[2][4], bl[2][4];
#pragma unroll
            for (int mt = 0; mt < 4; mt++) {
                const uint32_t ra = base + (uint32_t)(wm + mt * 16 + r) * RS + ko;
                LDSM4(ah[mt], ra);
            }
#pragma unroll
            for (int p = 0; p < 2; p++) {
                const uint32_t rb = base + AT_BYTES +
                                    (uint32_t)(wn + p * 16 + r) * RS + ko;
                LDSM4(bh[p], rb);
                LDSM4(bl[p], rb + AT_BYTES);
            }
#pragma unroll
            for (int mt = 0; mt < 4; mt++)
#pragma unroll
                for (int nt = 0; nt < 4; nt++) {
                    const int p = nt >> 1, o = nt & 1;
                    MMA_F16(acc[mt][nt], ah[mt], bh[p][o], bh[p][o + 2]);
                    MMA_F16(acc[mt][nt], ah[mt], bl[p][o], bl[p][o + 2]);
                }
        }
    }

#pragma unroll
    for (int mt = 0; mt < 4; mt++) {
        const int gr = m0 + wm + mt * 16 + (lane >> 2);
#pragma unroll
        for (int nt = 0; nt < 4; nt++) {
            const int gc = n0 + wn + nt * 8 + (lane & 3) * 2;
            const float b0 = bias[gc], b1 = bias[gc + 1];
            float2 v0 = { acc[mt][nt][0] + b0, acc[mt][nt][1] + b1 };
            float2 v1 = { acc[mt][nt][2] + b0, acc[mt][nt][3] + b1 };
            *(float2*)&C[(size_t)gr * Ntot + gc] = v0;
            *(float2*)&C[(size_t)(gr + 8) * Ntot + gc] = v1;
        }
    }
}

// ---------------------------------------------------------------------------
// Tensor-core window attention. Block = (window, head), 4 warps.
// 64x64 padded scores; Q/K/V fp16 hi/lo in smem (80B rows, conflict-free).
// acc init from cmb (bias+mask); fragment softmax; PV via ldmatrix.trans.
// ---------------------------------------------------------------------------
#define TQ_H 0
#define TQ_L 5120
#define TK_H 10240
#define TK_L 15360
#define TV_H 20480
#define TV_L 25600
#define ASMEM 30720

__global__ __launch_bounds__(128)
void attn_mma(const float* __restrict__ qkv, const float* __restrict__ cmb,
              __half* __restrict__ out_h)
{
    const int bh = blockIdx.x;
    const int b = bh >> 4, h = bh & 15;
    const int tid = threadIdx.x;
    const int lane = tid & 31, wq = tid >> 5;

    __shared__ __align__(16) char smem[ASMEM];
    const uint32_t sb = smem_u32(smem);

    // zero (pad rows 49..63 must be 0)
    for (int i = tid; i < ASMEM / 16; i += 128)
        ((uint4*)smem)[i] = make_uint4(0, 0, 0, 0);
    __syncthreads();

    // stage q(*scale), k, v -> fp16 hi/lo tiles
    const float scale = 0.17677669529663687f;
    const size_t rowbase = (size_t)b * SEQ * 1536;
    for (int i = tid; i < 3 * SEQ * 8; i += 128) {
        const int t = i / (SEQ * 8);
        const int rem = i - t * (SEQ * 8);
        const int row = rem >> 3, c4 = rem & 7;
        float4 v = *(const float4*)(qkv + rowbase + (size_t)row * 1536 +
                                    t * 512 + h * HD + c4 * 4);
        if (t == 0) { v.x *= scale; v.y *= scale; v.z *= scale; v.w *= scale; }
        uint2 hi, lo;
        hsplit2(v.x, v.y, hi.x, lo.x);
        hsplit2(v.z, v.w, hi.y, lo.y);
        char* dst = smem + t * 10240 + row * RS + c4 * 8;
        *(uint2*)dst = hi;
        *(uint2*)(dst + 5120) = lo;
    }
    __syncthreads();

    // ---- scores: acc init from cmb, then 3-term QK^T ----
    const int r0 = wq * 16 + (lane >> 2);
    const int cb = (lane & 3) * 2;
    float acc[8][4];
    const float* cw = cmb + (((size_t)(b & (NW - 1)) * NH + h) << 12);
#pragma unroll
    for (int nt = 0; nt < 8; nt++) {
        float2 v0 = *(const float2*)(cw + r0 * 64 + nt * 8 + cb);
        float2 v1 = *(const float2*)(cw + (r0 + 8) * 64 + nt * 8 + cb);
        acc[nt][0] = v0.x; acc[nt][1] = v0.y;
        acc[nt][2] = v1.x; acc[nt][3] = v1.y;
    }

    uint32_t qh[2][4], ql[2][4];
#pragma unroll
    for (int kt = 0; kt < 2; kt++) {
        const uint32_t ra = sb + TQ_H + (uint32_t)(wq * 16 + (lane & 15)) * RS +
                            kt * 32 + (lane >> 4) * 16;
        LDSM4(qh[kt], ra);
        LDSM4(ql[kt], ra + 5120);
    }
#pragma unroll
    for (int kt = 0; kt < 2; kt++)
#pragma unroll
        for (int t2 = 0; t2 < 4; t2++) {
            uint32_t kh4[4], kl4[4];
            const uint32_t rk = sb + TK_H +
                (uint32_t)(t2 * 16 + (lane & 7) + ((lane >> 4) & 1) * 8) * RS +
                kt * 32 + ((lane >> 3) & 1) * 16;
            LDSM4(kh4, rk);
            LDSM4(kl4, rk + 5120);
            MMA_F16(acc[2 * t2],     qh[kt], kh4[0], kh4[1]);
            MMA_F16(acc[2 * t2 + 1], qh[kt], kh4[2], kh4[3]);
            MMA_F16(acc[2 * t2],     qh[kt], kl4[0], kl4[1]);
            MMA_F16(acc[2 * t2 + 1], qh[kt], kl4[2], kl4[3]);
            MMA_F16(acc[2 * t2],     ql[kt], kh4[0], kh4[1]);
            MMA_F16(acc[2 * t2 + 1], ql[kt], kh4[2], kh4[3]);
        }

    // ---- fragment softmax (unnormalized; divide at the end) ----
    float m0 = -1e30f, m1 = -1e30f;
#pragma unroll
    for (int nt = 0; nt < 8; nt++) {
        m0 = fmaxf(m0, fmaxf(acc[nt][0], acc[nt][1]));
        m1 = fmaxf(m1, fmaxf(acc[nt][2], acc[nt][3]));
    }
    m0 = fmaxf(m0, __shfl_xor_sync(0xffffffffu, m0, 1));
    m0 = fmaxf(m0, __shfl_xor_sync(0xffffffffu, m0, 2));
    m1 = fmaxf(m1, __shfl_xor_sync(0xffffffffu, m1, 1));
    m1 = fmaxf(m1, __shfl_xor_sync(0xffffffffu, m1, 2));
    float s0 = 0.f, s1 = 0.f;
#pragma unroll
    for (int nt = 0; nt < 8; nt++) {
        acc[nt][0] = __expf(acc[nt][0] - m0); s0 += acc[nt][0];
        acc[nt][1] = __expf(acc[nt][1] - m0); s0 += acc[nt][1];
        acc[nt][2] = __expf(acc[nt][2] - m1); s1 += acc[nt][2];
        acc[nt][3] = __expf(acc[nt][3] - m1); s1 += acc[nt][3];
    }
    s0 += __shfl_xor_sync(0xffffffffu, s0, 1);
    s0 += __shfl_xor_sync(0xffffffffu, s0, 2);
    s1 += __shfl_xor_sync(0xffffffffu, s1, 1);
    s1 += __shfl_xor_sync(0xffffffffu, s1, 2);

    // ---- P -> fp16 hi/lo A-fragments ----
    uint32_t ph[4][4], pl[4][4];
#pragma unroll
    for (int kk = 0; kk < 4; kk++) {
        hsplit2(acc[2 * kk][0],     acc[2 * kk][1],     ph[kk][0], pl[kk][0]);
        hsplit2(acc[2 * kk][2],     acc[2 * kk][3],     ph[kk][1], pl[kk][1]);
        hsplit2(acc[2 * kk + 1][0], acc[2 * kk + 1][1], ph[kk][2], pl[kk][2]);
        hsplit2(acc[2 * kk + 1][2], acc[2 * kk + 1][3], ph[kk][3], pl[kk][3]);
    }

    // ---- O = P @ V (3-term) ----
    float oacc[4][4];
#pragma unroll
    for (int a = 0; a < 4; a++)
#pragma unroll
        for (int c = 0; c < 4; c++) oacc[a][c] = 0.f;
#pragma unroll
    for (int kk = 0; kk < 4; kk++)
#pragma unroll
        for (int d2 = 0; d2 < 2; d2++) {
            uint32_t vh4[4], vl4[4];
            const uint32_t rv = sb + TV_H +
                (uint32_t)(kk * 16 + (lane & 7) + ((lane >> 3) & 1) * 8) * RS +
                d2 * 32 + ((lane >> 4) & 1) * 16;
            LDSM4T(vh4, rv);
            LDSM4T(vl4, rv + 5120);
            MMA_F16(oacc[2 * d2],     ph[kk], vh4[0], vh4[1]);
            MMA_F16(oacc[2 * d2 + 1], ph[kk], vh4[2], vh4[3]);
            MMA_F16(oacc[2 * d2],     ph[kk], vl4[0], vl4[1]);
            MMA_F16(oacc[2 * d2 + 1], ph[kk], vl4[2], vl4[3]);
            MMA_F16(oacc[2 * d2],     pl[kk], vh4[0], vh4[1]);
            MMA_F16(oacc[2 * d2 + 1], pl[kk], vh4[2], vh4[3]);
        }

    // ---- normalize + write ----
    const float inv0 = 1.f / s0, inv1 = 1.f / s1;
    if (r0 < SEQ) {
        __half* orow = out_h + (size_t)(b * SEQ + r0) * CDIM + h * HD + cb;
#pragma unroll
        for (int dt = 0; dt < 4; dt++) {
            __half2 o = __floats2half2_rn(oacc[dt][0] * inv0, oacc[dt][1] * inv0);
            *(__half2*)(orow + dt * 8) = o;
        }
    }
    if (r0 + 8 < SEQ) {
        __half* orow = out_h + (size_t)(b * SEQ + r0 + 8) * CDIM + h * HD + cb;
#pragma unroll
        for (int dt = 0; dt < 4; dt++) {
            __half2 o = __floats2half2_rn(oacc[dt][2] * inv1, oacc[dt][3] * inv1);
            *(__half2*)(orow + dt * 8) = o;
        }
    }
}

// ---------------------------------------------------------------------------
extern "C" void kernel_launch(void* const* d_in, const int* in_sizes, int n_in,
                              void* d_out, int out_size)
{
    const float* x      = (const float*)d_in[0];
    const float* mask   = (const float*)d_in[1];
    const float* qkv_w  = (const float*)d_in[2];
    const float* qkv_b  = (const float*)d_in[3];
    const float* proj_w = (const float*)d_in[4];
    const float* proj_b = (const float*)d_in[5];
    const float* table  = (const float*)d_in[6];
    const int*   idx    = (const int*)d_in[7];
    float* out = (float*)d_out;

    float *qkv_s, *cmb_s;
    __half *xh, *ath, *qwh, *qwl, *pwh, *pwl;
    cudaGetSymbolAddress((void**)&qkv_s, g_qkv);
    cudaGetSymbolAddress((void**)&cmb_s, g_cmb);
    cudaGetSymbolAddress((void**)&xh, g_x_h);
    cudaGetSymbolAddress((void**)&ath, g_att_h);
    cudaGetSymbolAddress((void**)&qwh, g_qw_hi);
    cudaGetSymbolAddress((void**)&qwl, g_qw_lo);
    cudaGetSymbolAddress((void**)&pwh, g_pw_hi);
    cudaGetSymbolAddress((void**)&pwl, g_pw_lo);

    cudaFuncSetAttribute(gemm_f16, cudaFuncAttributeMaxDynamicSharedMemorySize, GSMEM);

    // 0) prep: x->fp16, weight transpose+split, bias+mask table
    const int n4 = MROWS * KDIM / 4;
    fconv<<<(n4 + 255) / 256, 256>>>((const float4*)x, (uint2*)xh, n4);
    wsplit<<<dim3(1536 / 32, 512 / 32), dim3(32, 8)>>>(qkv_w, qwh, qwl, 512, 1536);
    wsplit<<<dim3(512 / 32, 512 / 32), dim3(32, 8)>>>(proj_w, pwh, pwl, 512, 512);
    cmb_prep<<<dim3(NW, NH), 256>>>(mask, table, idx, cmb_s);

    // 1) QKV projection
    gemm_f16<<<dim3(1536 / 128, MROWS / 128), 256, GSMEM>>>(
        xh, qwh, qwl, qkv_b, qkv_s, 1536);

    // 2) tensor-core window attention
    attn_mma<<<B_WIN * NH, 128>>>(qkv_s, cmb_s, ath);

    // 3) output projection
    gemm_f16<<<dim3(512 / 128, MROWS / 128), 256, GSMEM>>>(
        ath, pwh, pwl, proj_b, out, 512);
}

// round 9
// speedup vs baseline: 2.0832x; 1.0097x over previous
#include <cuda_runtime.h>
#include <cuda_fp16.h>
#include <cstdint>
#include <cstddef>

#define B_WIN 4096
#define SEQ   49
#define CDIM  512
#define NH    16
#define HD    32
#define NW    64
#define MROWS (B_WIN * SEQ)      // 200704
#define KDIM  512

// ---------------- device scratch (no cudaMalloc allowed) -------------------
__device__ float g_qkv[(size_t)MROWS * 1536];        // [B*N, 3C] fp32
__device__ __half g_x_h[(size_t)MROWS * KDIM];       // x fp16
__device__ __half g_att_h[(size_t)MROWS * KDIM];     // attn out fp16
__device__ __half g_qw_hi[1536 * KDIM];              // qkv_w^T split [N,K]
__device__ __half g_qw_lo[1536 * KDIM];
__device__ __half g_pw_hi[512 * KDIM];               // proj_w^T split [N,K]
__device__ __half g_pw_lo[512 * KDIM];
__device__ float g_cmb[(size_t)NW * NH * 64 * 64];   // bias+mask, padded

// ---------------- helpers (arch-portable PTX: sm_80+ features only) --------
__device__ __forceinline__ uint32_t smem_u32(const void* p) {
    uint32_t a;
    asm("{ .reg .u64 t; cvta.to.shared.u64 t, %1; cvt.u32.u64 %0, t; }"
        : "=r"(a) : "l"(p));
    return a;
}
#define CPA16(dst, src) \
    asm volatile("cp.async.cg.shared.global [%0], [%1], 16;" \
                 :: "r"(dst), "l"(src) : "memory")
#define CPCOMMIT() asm volatile("cp.async.commit_group;" ::: "memory")
#define CPWAIT(n)  asm volatile("cp.async.wait_group %0;" :: "n"(n) : "memory")
#define LDSM4(r, addr)                                                        \
    asm volatile("ldmatrix.sync.aligned.m8n8.x4.shared.b16 {%0,%1,%2,%3}, [%4];" \
        : "=r"((r)[0]), "=r"((r)[1]), "=r"((r)[2]), "=r"((r)[3]) : "r"(addr))
#define LDSM4T(r, addr)                                                       \
    asm volatile("ldmatrix.sync.aligned.m8n8.x4.trans.shared.b16 {%0,%1,%2,%3}, [%4];" \
        : "=r"((r)[0]), "=r"((r)[1]), "=r"((r)[2]), "=r"((r)[3]) : "r"(addr))
#define MMA_F16(d, a, b0, b1)                                                 \
    asm volatile("mma.sync.aligned.m16n8k16.row.col.f32.f16.f16.f32 "         \
        "{%0,%1,%2,%3},{%4,%5,%6,%7},{%8,%9},{%0,%1,%2,%3};"                  \
        : "+f"((d)[0]), "+f"((d)[1]), "+f"((d)[2]), "+f"((d)[3])              \
        : "r"((a)[0]), "r"((a)[1]), "r"((a)[2]), "r"((a)[3]),                 \
          "r"(b0), "r"(b1))

__device__ __forceinline__ void hsplit2(float a, float b, uint32_t& hi, uint32_t& lo) {
    __half2 h = __floats2half2_rn(a, b);
    float2 hf = __half22float2(h);
    __half2 l = __floats2half2_rn(a - hf.x, b - hf.y);
    hi = *(uint32_t*)&h;
    lo = *(uint32_t*)&l;
}

// ---------------------------------------------------------------------------
// fp32 -> fp16 convert (activations)
// ---------------------------------------------------------------------------
__global__ void fconv(const float4* __restrict__ in, uint2* __restrict__ out, int n4)
{
    const int i = blockIdx.x * blockDim.x + threadIdx.x;
    if (i >= n4) return;
    float4 v = in[i];
    __half2 a = __floats2half2_rn(v.x, v.y);
    __half2 b = __floats2half2_rn(v.z, v.w);
    uint2 o = { *(uint32_t*)&a, *(uint32_t*)&b };
    out[i] = o;
}

// ---------------------------------------------------------------------------
// Weight prep: W[K,N] fp32 -> Bhi/Blo[N,K] fp16 (transposed + split)
// ---------------------------------------------------------------------------
__global__ void wsplit(const float* __restrict__ W, __half* __restrict__ Bhi,
                       __half* __restrict__ Blo, int K, int N)
{
    __shared__ float t[32][33];
    const int bx = blockIdx.x, by = blockIdx.y;
    const int x = threadIdx.x, y = threadIdx.y;   // 32 x 8
#pragma unroll
    for (int i = 0; i < 4; i++)
        t[y + i * 8][x] = W[(size_t)(by * 32 + y + i * 8) * N + bx * 32 + x];
    __syncthreads();
#pragma unroll
    for (int i = 0; i < 4; i++) {
        float v = t[x][y + i * 8];
        __half h = __float2half_rn(v);
        size_t o = (size_t)(bx * 32 + y + i * 8) * K + by * 32 + x;
        Bhi[o] = h;
        Blo[o] = __float2half_rn(v - __half2float(h));
    }
}

// ---------------------------------------------------------------------------
// cmb[w][h][n][m] = bias(h,n,m) + mask(w,n,m), padded 64x64 (pad cols = -1e9)
// ---------------------------------------------------------------------------
__global__ void cmb_prep(const float* __restrict__ mask, const float* __restrict__ table,
                         const int* __restrict__ idx, float* __restrict__ cmb)
{
    const int w = blockIdx.x, h = blockIdx.y;
    float* dst = cmb + (((size_t)w * NH + h) << 12);
    for (int i = threadIdx.x; i < 4096; i += 256) {
        const int n = i >> 6, m = i & 63;
        float v;
        if (m >= SEQ)      v = -1e9f;
        else if (n >= SEQ) v = 0.f;
        else v = table[idx[n * SEQ + m] * NH + h] + mask[(size_t)w * SEQ * SEQ + n * SEQ + m];
        dst[i] = v;
    }
}

// ---------------------------------------------------------------------------
// fp16 mma.sync GEMM, 2-term weight split. MMA emission reordered so that
// consecutive MMAs never share an accumulator (hi sweep, then lo sweep).
// ---------------------------------------------------------------------------
#define RS        80
#define AT_BYTES  (128 * RS)
#define STAGE     (3 * AT_BYTES)
#define NSTAGE    3
#define GSMEM     (NSTAGE * STAGE)

__global__ __launch_bounds__(256, 2)
void gemm_f16(const __half* __restrict__ A_g,
              const __half* __restrict__ Bhi_g,
              const __half* __restrict__ Blo_g,
              const float* __restrict__ bias, float* __restrict__ C, int Ntot)
{
    extern __shared__ __align__(128) char sm[];
    const uint32_t sb = smem_u32(sm);
    const int tid = threadIdx.x;
    const int lane = tid & 31, wid = tid >> 5;
    const int m0 = blockIdx.y * 128, n0 = blockIdx.x * 128;
    const int wm = (wid >> 2) * 64, wn = (wid & 3) * 32;

    const int crow = tid >> 1;
    const int cc   = (tid & 1) * 32;

    const char* gsrc0 = (const char*)(A_g   + (size_t)m0 * KDIM);
    const char* gsrc1 = (const char*)(Bhi_g + (size_t)n0 * KDIM);
    const char* gsrc2 = (const char*)(Blo_g + (size_t)n0 * KDIM);

    float acc[4][4][4];
#pragma unroll
    for (int a = 0; a < 4; a++)
#pragma unroll
        for (int b = 0; b < 4; b++)
#pragma unroll
            for (int c = 0; c < 4; c++) acc[a][b][c] = 0.f;

    auto issue = [&](int s, int kc) {
        const int gofs = crow * 1024 + kc * 64 + cc;
        const uint32_t dst = sb + s * STAGE + crow * RS + cc;
        CPA16(dst + 0 * AT_BYTES,      gsrc0 + gofs);
        CPA16(dst + 0 * AT_BYTES + 16, gsrc0 + gofs + 16);
        CPA16(dst + 1 * AT_BYTES,      gsrc1 + gofs);
        CPA16(dst + 1 * AT_BYTES + 16, gsrc1 + gofs + 16);
        CPA16(dst + 2 * AT_BYTES,      gsrc2 + gofs);
        CPA16(dst + 2 * AT_BYTES + 16, gsrc2 + gofs + 16);
        CPCOMMIT();
    };

    issue(0, 0);
    issue(1, 1);

    const int r = lane & 15;
    const uint32_t khalf = (lane >> 4) * 16;

    for (int kc = 0; kc < 16; kc++) {
        const int s = kc % NSTAGE;
        if (kc < 15) { CPWAIT(1); } else { CPWAIT(0); }
        __syncthreads();
        if (kc + 2 < 16) issue((kc + 2) % NSTAGE, kc + 2);

        const uint32_t base = sb + s * STAGE;
#pragma unroll
        for (int kk = 0; kk < 2; kk++) {
            const uint32_t ko = kk * 32 + khalf;
            uint32_t ah[4][4], bh[2][4], bl[2][4];
#pragma unroll
            for (int mt = 0; mt < 4; mt++) {
                const uint32_t ra = base + (uint32_t)(wm + mt * 16 + r) * RS + ko;
                LDSM4(ah[mt], ra);
            }
#pragma unroll
            for (int p = 0; p < 2; p++) {
                const uint32_t rb = base + AT_BYTES +
                                    (uint32_t)(wn + p * 16 + r) * RS + ko;
                LDSM4(bh[p], rb);
                LDSM4(bl[p], rb + AT_BYTES);
            }
            // hi sweep: 16 MMAs, all-distinct accumulators (RAW distance 16)
#pragma unroll
            for (int mt = 0; mt < 4; mt++)
#pragma unroll
                for (int nt = 0; nt < 4; nt++) {
                    const int p = nt >> 1, o = nt & 1;
                    MMA_F16(acc[mt][nt], ah[mt], bh[p][o], bh[p][o + 2]);
                }
            // lo sweep
#pragma unroll
            for (int mt = 0; mt < 4; mt++)
#pragma unroll
                for (int nt = 0; nt < 4; nt++) {
                    const int p = nt >> 1, o = nt & 1;
                    MMA_F16(acc[mt][nt], ah[mt], bl[p][o], bl[p][o + 2]);
                }
        }
    }

#pragma unroll
    for (int mt = 0; mt < 4; mt++) {
        const int gr = m0 + wm + mt * 16 + (lane >> 2);
#pragma unroll
        for (int nt = 0; nt < 4; nt++) {
            const int gc = n0 + wn + nt * 8 + (lane & 3) * 2;
            const float b0 = bias[gc], b1 = bias[gc + 1];
            float2 v0 = { acc[mt][nt][0] + b0, acc[mt][nt][1] + b1 };
            float2 v1 = { acc[mt][nt][2] + b0, acc[mt][nt][3] + b1 };
            *(float2*)&C[(size_t)gr * Ntot + gc] = v0;
            *(float2*)&C[(size_t)(gr + 8) * Ntot + gc] = v1;
        }
    }
}

// ---------------------------------------------------------------------------
// Tensor-core window attention; MMAs grouped term-major over fragment pairs
// to widen accumulator RAW distance.
// ---------------------------------------------------------------------------
#define TQ_H 0
#define TQ_L 5120
#define TK_H 10240
#define TK_L 15360
#define TV_H 20480
#define TV_L 25600
#define ASMEM 30720

__global__ __launch_bounds__(128)
void attn_mma(const float* __restrict__ qkv, const float* __restrict__ cmb,
              __half* __restrict__ out_h)
{
    const int bh = blockIdx.x;
    const int b = bh >> 4, h = bh & 15;
    const int tid = threadIdx.x;
    const int lane = tid & 31, wq = tid >> 5;

    __shared__ __align__(16) char smem[ASMEM];
    const uint32_t sb = smem_u32(smem);

    for (int i = tid; i < ASMEM / 16; i += 128)
        ((uint4*)smem)[i] = make_uint4(0, 0, 0, 0);
    __syncthreads();

    const float scale = 0.17677669529663687f;
    const size_t rowbase = (size_t)b * SEQ * 1536;
    for (int i = tid; i < 3 * SEQ * 8; i += 128) {
        const int t = i / (SEQ * 8);
        const int rem = i - t * (SEQ * 8);
        const int row = rem >> 3, c4 = rem & 7;
        float4 v = *(const float4*)(qkv + rowbase + (size_t)row * 1536 +
                                    t * 512 + h * HD + c4 * 4);
        if (t == 0) { v.x *= scale; v.y *= scale; v.z *= scale; v.w *= scale; }
        uint2 hi, lo;
        hsplit2(v.x, v.y, hi.x, lo.x);
        hsplit2(v.z, v.w, hi.y, lo.y);
        char* dst = smem + t * 10240 + row * RS + c4 * 8;
        *(uint2*)dst = hi;
        *(uint2*)(dst + 5120) = lo;
    }
    __syncthreads();

    // ---- scores: acc init from cmb, then 3-term QK^T ----
    const int r0 = wq * 16 + (lane >> 2);
    const int cb = (lane & 3) * 2;
    float acc[8][4];
    const float* cw = cmb + (((size_t)(b & (NW - 1)) * NH + h) << 12);
#pragma unroll
    for (int nt = 0; nt < 8; nt++) {
        float2 v0 = *(const float2*)(cw + r0 * 64 + nt * 8 + cb);
        float2 v1 = *(const float2*)(cw + (r0 + 8) * 64 + nt * 8 + cb);
        acc[nt][0] = v0.x; acc[nt][1] = v0.y;
        acc[nt][2] = v1.x; acc[nt][3] = v1.y;
    }

    uint32_t qh[2][4], ql[2][4];
#pragma unroll
    for (int kt = 0; kt < 2; kt++) {
        const uint32_t ra = sb + TQ_H + (uint32_t)(wq * 16 + (lane & 15)) * RS +
                            kt * 32 + (lane >> 4) * 16;
        LDSM4(qh[kt], ra);
        LDSM4(ql[kt], ra + 5120);
    }
#pragma unroll
    for (int kt = 0; kt < 2; kt++)
#pragma unroll
        for (int t2p = 0; t2p < 4; t2p += 2) {
            uint32_t kh4[2][4], kl4[2][4];
#pragma unroll
            for (int j = 0; j < 2; j++) {
                const uint32_t rk = sb + TK_H +
                    (uint32_t)((t2p + j) * 16 + (lane & 7) + ((lane >> 4) & 1) * 8) * RS +
                    kt * 32 + ((lane >> 3) & 1) * 16;
                LDSM4(kh4[j], rk);
                LDSM4(kl4[j], rk + 5120);
            }
            // term-major: RAW distance 4
#pragma unroll
            for (int j = 0; j < 2; j++) {
                MMA_F16(acc[2 * (t2p + j)],     qh[kt], kh4[j][0], kh4[j][1]);
                MMA_F16(acc[2 * (t2p + j) + 1], qh[kt], kh4[j][2], kh4[j][3]);
            }
#pragma unroll
            for (int j = 0; j < 2; j++) {
                MMA_F16(acc[2 * (t2p + j)],     qh[kt], kl4[j][0], kl4[j][1]);
                MMA_F16(acc[2 * (t2p + j) + 1], qh[kt], kl4[j][2], kl4[j][3]);
            }
#pragma unroll
            for (int j = 0; j < 2; j++) {
                MMA_F16(acc[2 * (t2p + j)],     ql[kt], kh4[j][0], kh4[j][1]);
                MMA_F16(acc[2 * (t2p + j) + 1], ql[kt], kh4[j][2], kh4[j][3]);
            }
        }

    // ---- fragment softmax (unnormalized; divide at the end) ----
    float m0 = -1e30f, m1 = -1e30f;
#pragma unroll
    for (int nt = 0; nt < 8; nt++) {
        m0 = fmaxf(m0, fmaxf(acc[nt][0], acc[nt][1]));
        m1 = fmaxf(m1, fmaxf(acc[nt][2], acc[nt][3]));
    }
    m0 = fmaxf(m0, __shfl_xor_sync(0xffffffffu, m0, 1));
    m0 = fmaxf(m0, __shfl_xor_sync(0xffffffffu, m0, 2));
    m1 = fmaxf(m1, __shfl_xor_sync(0xffffffffu, m1, 1));
    m1 = fmaxf(m1, __shfl_xor_sync(0xffffffffu, m1, 2));
    float s0 = 0.f, s1 = 0.f;
#pragma unroll
    for (int nt = 0; nt < 8; nt++) {
        acc[nt][0] = __expf(acc[nt][0] - m0); s0 += acc[nt][0];
        acc[nt][1] = __expf(acc[nt][1] - m0); s0 += acc[nt][1];
        acc[nt][2] = __expf(acc[nt][2] - m1); s1 += acc[nt][2];
        acc[nt][3] = __expf(acc[nt][3] - m1); s1 += acc[nt][3];
    }
    s0 += __shfl_xor_sync(0xffffffffu, s0, 1);
    s0 += __shfl_xor_sync(0xffffffffu, s0, 2);
    s1 += __shfl_xor_sync(0xffffffffu, s1, 1);
    s1 += __shfl_xor_sync(0xffffffffu, s1, 2);

    // ---- P -> fp16 hi/lo A-fragments ----
    uint32_t ph[4][4], pl[4][4];
#pragma unroll
    for (int kk = 0; kk < 4; kk++) {
        hsplit2(acc[2 * kk][0],     acc[2 * kk][1],     ph[kk][0], pl[kk][0]);
        hsplit2(acc[2 * kk][2],     acc[2 * kk][3],     ph[kk][1], pl[kk][1]);
        hsplit2(acc[2 * kk + 1][0], acc[2 * kk + 1][1], ph[kk][2], pl[kk][2]);
        hsplit2(acc[2 * kk + 1][2], acc[2 * kk + 1][3], ph[kk][3], pl[kk][3]);
    }

    // ---- O = P @ V (3-term), kk processed in pairs, term-major ----
    float oacc[4][4];
#pragma unroll
    for (int a = 0; a < 4; a++)
#pragma unroll
        for (int c = 0; c < 4; c++) oacc[a][c] = 0.f;
#pragma unroll
    for (int kkp = 0; kkp < 4; kkp += 2) {
        uint32_t vh4[2][2][4], vl4[2][2][4];
#pragma unroll
        for (int j = 0; j < 2; j++)
#pragma unroll
            for (int d2 = 0; d2 < 2; d2++) {
                const uint32_t rv = sb + TV_H +
                    (uint32_t)((kkp + j) * 16 + (lane & 7) + ((lane >> 3) & 1) * 8) * RS +
                    d2 * 32 + ((lane >> 4) & 1) * 16;
                LDSM4T(vh4[j][d2], rv);
                LDSM4T(vl4[j][d2], rv + 5120);
            }
#pragma unroll
        for (int j = 0; j < 2; j++)
#pragma unroll
            for (int d2 = 0; d2 < 2; d2++) {
                MMA_F16(oacc[2 * d2],     ph[kkp + j], vh4[j][d2][0], vh4[j][d2][1]);
                MMA_F16(oacc[2 * d2 + 1], ph[kkp + j], vh4[j][d2][2], vh4[j][d2][3]);
            }
#pragma unroll
        for (int j = 0; j < 2; j++)
#pragma unroll
            for (int d2 = 0; d2 < 2; d2++) {
                MMA_F16(oacc[2 * d2],     ph[kkp + j], vl4[j][d2][0], vl4[j][d2][1]);
                MMA_F16(oacc[2 * d2 + 1], ph[kkp + j], vl4[j][d2][2], vl4[j][d2][3]);
            }
#pragma unroll
        for (int j = 0; j < 2; j++)
#pragma unroll
            for (int d2 = 0; d2 < 2; d2++) {
                MMA_F16(oacc[2 * d2],     pl[kkp + j], vh4[j][d2][0], vh4[j][d2][1]);
                MMA_F16(oacc[2 * d2 + 1], pl[kkp + j], vh4[j][d2][2], vh4[j][d2][3]);
            }
    }

    // ---- normalize + write ----
    const float inv0 = 1.f / s0, inv1 = 1.f / s1;
    if (r0 < SEQ) {
        __half* orow = out_h + (size_t)(b * SEQ + r0) * CDIM + h * HD + cb;
#pragma unroll
        for (int dt = 0; dt < 4; dt++) {
            __half2 o = __floats2half2_rn(oacc[dt][0] * inv0, oacc[dt][1] * inv0);
            *(__half2*)(orow + dt * 8) = o;
        }
    }
    if (r0 + 8 < SEQ) {
        __half* orow = out_h + (size_t)(b * SEQ + r0 + 8) * CDIM + h * HD + cb;
#pragma unroll
        for (int dt = 0; dt < 4; dt++) {
            __half2 o = __floats2half2_rn(oacc[dt][2] * inv1, oacc[dt][3] * inv1);
            *(__half2*)(orow + dt * 8) = o;
        }
    }
}

// ---------------------------------------------------------------------------
extern "C" void kernel_launch(void* const* d_in, const int* in_sizes, int n_in,
                              void* d_out, int out_size)
{
    const float* x      = (const float*)d_in[0];
    const float* mask   = (const float*)d_in[1];
    const float* qkv_w  = (const float*)d_in[2];
    const float* qkv_b  = (const float*)d_in[3];
    const float* proj_w = (const float*)d_in[4];
    const float* proj_b = (const float*)d_in[5];
    const float* table  = (const float*)d_in[6];
    const int*   idx    = (const int*)d_in[7];
    float* out = (float*)d_out;

    float *qkv_s, *cmb_s;
    __half *xh, *ath, *qwh, *qwl, *pwh, *pwl;
    cudaGetSymbolAddress((void**)&qkv_s, g_qkv);
    cudaGetSymbolAddress((void**)&cmb_s, g_cmb);
    cudaGetSymbolAddress((void**)&xh, g_x_h);
    cudaGetSymbolAddress((void**)&ath, g_att_h);
    cudaGetSymbolAddress((void**)&qwh, g_qw_hi);
    cudaGetSymbolAddress((void**)&qwl, g_qw_lo);
    cudaGetSymbolAddress((void**)&pwh, g_pw_hi);
    cudaGetSymbolAddress((void**)&pwl, g_pw_lo);

    cudaFuncSetAttribute(gemm_f16, cudaFuncAttributeMaxDynamicSharedMemorySize, GSMEM);

    const int n4 = MROWS * KDIM / 4;
    fconv<<<(n4 + 255) / 256, 256>>>((const float4*)x, (uint2*)xh, n4);
    wsplit<<<dim3(1536 / 32, 512 / 32), dim3(32, 8)>>>(qkv_w, qwh, qwl, 512, 1536);
    wsplit<<<dim3(512 / 32, 512 / 32), dim3(32, 8)>>>(proj_w, pwh, pwl, 512, 512);
    cmb_prep<<<dim3(NW, NH), 256>>>(mask, table, idx, cmb_s);

    gemm_f16<<<dim3(1536 / 128, MROWS / 128), 256, GSMEM>>>(
        xh, qwh, qwl, qkv_b, qkv_s, 1536);

    attn_mma<<<B_WIN * NH, 128>>>(qkv_s, cmb_s, ath);

    gemm_f16<<<dim3(512 / 128, MROWS / 128), 256, GSMEM>>>(
        ath, pwh, pwl, proj_b, out, 512);
}

// round 10
// speedup vs baseline: 3.2265x; 1.5488x over previous
#include <cuda_runtime.h>
#include <cuda_fp16.h>
#include <cstdint>
#include <cstddef>

#define B_WIN 4096
#define SEQ   49
#define CDIM  512
#define NH    16
#define HD    32
#define NW    64
#define MROWS (B_WIN * SEQ)      // 200704
#define KDIM  512

// ---------------- device scratch (no cudaMalloc allowed) -------------------
__device__ float g_qkv[(size_t)MROWS * 1536];        // [B*N, 3C] fp32
__device__ __half g_x_h[(size_t)MROWS * KDIM];       // x fp16
__device__ __half g_att_h[(size_t)MROWS * KDIM];     // attn out fp16
__device__ __half g_qw_h[1536 * KDIM];               // qkv_w^T fp16 [N,K]
__device__ __half g_pw_h[512 * KDIM];                // proj_w^T fp16 [N,K]
__device__ float g_cmb[(size_t)NW * NH * 64 * 64];   // bias+mask, padded

// ---------------- helpers (arch-portable PTX: sm_80+ features only) --------
__device__ __forceinline__ uint32_t smem_u32(const void* p) {
    uint32_t a;
    asm("{ .reg .u64 t; cvta.to.shared.u64 t, %1; cvt.u32.u64 %0, t; }"
        : "=r"(a) : "l"(p));
    return a;
}
#define CPA16(dst, src) \
    asm volatile("cp.async.cg.shared.global [%0], [%1], 16;" \
                 :: "r"(dst), "l"(src) : "memory")
#define CPCOMMIT() asm volatile("cp.async.commit_group;" ::: "memory")
#define CPWAIT(n)  asm volatile("cp.async.wait_group %0;" :: "n"(n) : "memory")
#define LDSM4(r, addr)                                                        \
    asm volatile("ldmatrix.sync.aligned.m8n8.x4.shared.b16 {%0,%1,%2,%3}, [%4];" \
        : "=r"((r)[0]), "=r"((r)[1]), "=r"((r)[2]), "=r"((r)[3]) : "r"(addr))
#define LDSM4T(r, addr)                                                       \
    asm volatile("ldmatrix.sync.aligned.m8n8.x4.trans.shared.b16 {%0,%1,%2,%3}, [%4];" \
        : "=r"((r)[0]), "=r"((r)[1]), "=r"((r)[2]), "=r"((r)[3]) : "r"(addr))
#define MMA_F16(d, a, b0, b1)                                                 \
    asm volatile("mma.sync.aligned.m16n8k16.row.col.f32.f16.f16.f32 "         \
        "{%0,%1,%2,%3},{%4,%5,%6,%7},{%8,%9},{%0,%1,%2,%3};"                  \
        : "+f"((d)[0]), "+f"((d)[1]), "+f"((d)[2]), "+f"((d)[3])              \
        : "r"((a)[0]), "r"((a)[1]), "r"((a)[2]), "r"((a)[3]),                 \
          "r"(b0), "r"(b1))

__device__ __forceinline__ void hsplit2(float a, float b, uint32_t& hi, uint32_t& lo) {
    __half2 h = __floats2half2_rn(a, b);
    float2 hf = __half22float2(h);
    __half2 l = __floats2half2_rn(a - hf.x, b - hf.y);
    hi = *(uint32_t*)&h;
    lo = *(uint32_t*)&l;
}

// ---------------------------------------------------------------------------
// fp32 -> fp16 convert (activations)
// ---------------------------------------------------------------------------
__global__ void fconv(const float4* __restrict__ in, uint2* __restrict__ out, int n4)
{
    const int i = blockIdx.x * blockDim.x + threadIdx.x;
    if (i >= n4) return;
    float4 v = in[i];
    __half2 a = __floats2half2_rn(v.x, v.y);
    __half2 b = __floats2half2_rn(v.z, v.w);
    uint2 o = { *(uint32_t*)&a, *(uint32_t*)&b };
    out[i] = o;
}

// ---------------------------------------------------------------------------
// Weight prep: W[K,N] fp32 -> B[N,K] fp16 (transposed, single term)
// ---------------------------------------------------------------------------
__global__ void wconv(const float* __restrict__ W, __half* __restrict__ Bh,
                      int K, int N)
{
    __shared__ float t[32][33];
    const int bx = blockIdx.x, by = blockIdx.y;
    const int x = threadIdx.x, y = threadIdx.y;   // 32 x 8
#pragma unroll
    for (int i = 0; i < 4; i++)
        t[y + i * 8][x] = W[(size_t)(by * 32 + y + i * 8) * N + bx * 32 + x];
    __syncthreads();
#pragma unroll
    for (int i = 0; i < 4; i++)
        Bh[(size_t)(bx * 32 + y + i * 8) * K + by * 32 + x] =
            __float2half_rn(t[x][y + i * 8]);
}

// ---------------------------------------------------------------------------
// cmb[w][h][n][m] = bias(h,n,m) + mask(w,n,m), padded 64x64 (pad cols = -1e9)
// ---------------------------------------------------------------------------
__global__ void cmb_prep(const float* __restrict__ mask, const float* __restrict__ table,
                         const int* __restrict__ idx, float* __restrict__ cmb)
{
    const int w = blockIdx.x, h = blockIdx.y;
    float* dst = cmb + (((size_t)w * NH + h) << 12);
    for (int i = threadIdx.x; i < 4096; i += 256) {
        const int n = i >> 6, m = i & 63;
        float v;
        if (m >= SEQ)      v = -1e9f;
        else if (n >= SEQ) v = 0.f;
        else v = table[idx[n * SEQ + m] * NH + h] + mask[(size_t)w * SEQ * SEQ + n * SEQ + m];
        dst[i] = v;
    }
}

// ---------------------------------------------------------------------------
// fp16 mma.sync GEMM, single-term weights:
//   C[M,Ntot] = A[M,512] @ B[N,512]^T + bias
// CTA 128x128, BK=32, 3-stage cp.async, 8 warps x (64x32). 80B rows.
// ---------------------------------------------------------------------------
#define RS        80
#define AT_BYTES  (128 * RS)
#define STAGE     (2 * AT_BYTES)       // A + B
#define NSTAGE    3
#define GSMEM     (NSTAGE * STAGE)     // 61440

__global__ __launch_bounds__(256, 2)
void gemm_f16(const __half* __restrict__ A_g,
              const __half* __restrict__ B_g,
              const float* __restrict__ bias, float* __restrict__ C, int Ntot)
{
    extern __shared__ __align__(128) char sm[];
    const uint32_t sb = smem_u32(sm);
    const int tid = threadIdx.x;
    const int lane = tid & 31, wid = tid >> 5;
    const int m0 = blockIdx.y * 128, n0 = blockIdx.x * 128;
    const int wm = (wid >> 2) * 64, wn = (wid & 3) * 32;

    const int crow = tid >> 1;
    const int cc   = (tid & 1) * 32;

    const char* gsrc0 = (const char*)(A_g + (size_t)m0 * KDIM);
    const char* gsrc1 = (const char*)(B_g + (size_t)n0 * KDIM);

    float acc[4][4][4];
#pragma unroll
    for (int a = 0; a < 4; a++)
#pragma unroll
        for (int b = 0; b < 4; b++)
#pragma unroll
            for (int c = 0; c < 4; c++) acc[a][b][c] = 0.f;

    auto issue = [&](int s, int kc) {
        const int gofs = crow * 1024 + kc * 64 + cc;
        const uint32_t dst = sb + s * STAGE + crow * RS + cc;
        CPA16(dst,                     gsrc0 + gofs);
        CPA16(dst + 16,                gsrc0 + gofs + 16);
        CPA16(dst + AT_BYTES,          gsrc1 + gofs);
        CPA16(dst + AT_BYTES + 16,     gsrc1 + gofs + 16);
        CPCOMMIT();
    };

    issue(0, 0);
    issue(1, 1);

    const int r = lane & 15;
    const uint32_t khalf = (lane >> 4) * 16;

    for (int kc = 0; kc < 16; kc++) {
        const int s = kc % NSTAGE;
        if (kc < 15) { CPWAIT(1); } else { CPWAIT(0); }
        __syncthreads();
        if (kc + 2 < 16) issue((kc + 2) % NSTAGE, kc + 2);

        const uint32_t base = sb + s * STAGE;
#pragma unroll
        for (int kk = 0; kk < 2; kk++) {
            const uint32_t ko = kk * 32 + khalf;
            uint32_t ah[4][4], bh[2][4];
#pragma unroll
            for (int mt = 0; mt < 4; mt++) {
                const uint32_t ra = base + (uint32_t)(wm + mt * 16 + r) * RS + ko;
                LDSM4(ah[mt], ra);
            }
#pragma unroll
            for (int p = 0; p < 2; p++) {
                const uint32_t rb = base + AT_BYTES +
                                    (uint32_t)(wn + p * 16 + r) * RS + ko;
                LDSM4(bh[p], rb);
            }
#pragma unroll
            for (int mt = 0; mt < 4; mt++)
#pragma unroll
                for (int nt = 0; nt < 4; nt++) {
                    const int p = nt >> 1, o = nt & 1;
                    MMA_F16(acc[mt][nt], ah[mt], bh[p][o], bh[p][o + 2]);
                }
        }
    }

#pragma unroll
    for (int mt = 0; mt < 4; mt++) {
        const int gr = m0 + wm + mt * 16 + (lane >> 2);
#pragma unroll
        for (int nt = 0; nt < 4; nt++) {
            const int gc = n0 + wn + nt * 8 + (lane & 3) * 2;
            const float b0 = bias[gc], b1 = bias[gc + 1];
            float2 v0 = { acc[mt][nt][0] + b0, acc[mt][nt][1] + b1 };
            float2 v1 = { acc[mt][nt][2] + b0, acc[mt][nt][3] + b1 };
            *(float2*)&C[(size_t)gr * Ntot + gc] = v0;
            *(float2*)&C[(size_t)(gr + 8) * Ntot + gc] = v1;
        }
    }
}

// ---------------------------------------------------------------------------
// Tensor-core window attention (unchanged from R9 — 3-term splits)
// ---------------------------------------------------------------------------
#define TQ_H 0
#define TQ_L 5120
#define TK_H 10240
#define TK_L 15360
#define TV_H 20480
#define TV_L 25600
#define ASMEM 30720

__global__ __launch_bounds__(128)
void attn_mma(const float* __restrict__ qkv, const float* __restrict__ cmb,
              __half* __restrict__ out_h)
{
    const int bh = blockIdx.x;
    const int b = bh >> 4, h = bh & 15;
    const int tid = threadIdx.x;
    const int lane = tid & 31, wq = tid >> 5;

    __shared__ __align__(16) char smem[ASMEM];
    const uint32_t sb = smem_u32(smem);

    for (int i = tid; i < ASMEM / 16; i += 128)
        ((uint4*)smem)[i] = make_uint4(0, 0, 0, 0);
    __syncthreads();

    const float scale = 0.17677669529663687f;
    const size_t rowbase = (size_t)b * SEQ * 1536;
    for (int i = tid; i < 3 * SEQ * 8; i += 128) {
        const int t = i / (SEQ * 8);
        const int rem = i - t * (SEQ * 8);
        const int row = rem >> 3, c4 = rem & 7;
        float4 v = *(const float4*)(qkv + rowbase + (size_t)row * 1536 +
                                    t * 512 + h * HD + c4 * 4);
        if (t == 0) { v.x *= scale; v.y *= scale; v.z *= scale; v.w *= scale; }
        uint2 hi, lo;
        hsplit2(v.x, v.y, hi.x, lo.x);
        hsplit2(v.z, v.w, hi.y, lo.y);
        char* dst = smem + t * 10240 + row * RS + c4 * 8;
        *(uint2*)dst = hi;
        *(uint2*)(dst + 5120) = lo;
    }
    __syncthreads();

    const int r0 = wq * 16 + (lane >> 2);
    const int cb = (lane & 3) * 2;
    float acc[8][4];
    const float* cw = cmb + (((size_t)(b & (NW - 1)) * NH + h) << 12);
#pragma unroll
    for (int nt = 0; nt < 8; nt++) {
        float2 v0 = *(const float2*)(cw + r0 * 64 + nt * 8 + cb);
        float2 v1 = *(const float2*)(cw + (r0 + 8) * 64 + nt * 8 + cb);
        acc[nt][0] = v0.x; acc[nt][1] = v0.y;
        acc[nt][2] = v1.x; acc[nt][3] = v1.y;
    }

    uint32_t qh[2][4], ql[2][4];
#pragma unroll
    for (int kt = 0; kt < 2; kt++) {
        const uint32_t ra = sb + TQ_H + (uint32_t)(wq * 16 + (lane & 15)) * RS +
                            kt * 32 + (lane >> 4) * 16;
        LDSM4(qh[kt], ra);
        LDSM4(ql[kt], ra + 5120);
    }
#pragma unroll
    for (int kt = 0; kt < 2; kt++)
#pragma unroll
        for (int t2p = 0; t2p < 4; t2p += 2) {
            uint32_t kh4[2][4], kl4[2][4];
#pragma unroll
            for (int j = 0; j < 2; j++) {
                const uint32_t rk = sb + TK_H +
                    (uint32_t)((t2p + j) * 16 + (lane & 7) + ((lane >> 4) & 1) * 8) * RS +
                    kt * 32 + ((lane >> 3) & 1) * 16;
                LDSM4(kh4[j], rk);
                LDSM4(kl4[j], rk + 5120);
            }
#pragma unroll
            for (int j = 0; j < 2; j++) {
                MMA_F16(acc[2 * (t2p + j)],     qh[kt], kh4[j][0], kh4[j][1]);
                MMA_F16(acc[2 * (t2p + j) + 1], qh[kt], kh4[j][2], kh4[j][3]);
            }
#pragma unroll
            for (int j = 0; j < 2; j++) {
                MMA_F16(acc[2 * (t2p + j)],     qh[kt], kl4[j][0], kl4[j][1]);
                MMA_F16(acc[2 * (t2p + j) + 1], qh[kt], kl4[j][2], kl4[j][3]);
            }
#pragma unroll
            for (int j = 0; j < 2; j++) {
                MMA_F16(acc[2 * (t2p + j)],     ql[kt], kh4[j][0], kh4[j][1]);
                MMA_F16(acc[2 * (t2p + j) + 1], ql[kt], kh4[j][2], kh4[j][3]);
            }
        }

    float m0 = -1e30f, m1 = -1e30f;
#pragma unroll
    for (int nt = 0; nt < 8; nt++) {
        m0 = fmaxf(m0, fmaxf(acc[nt][0], acc[nt][1]));
        m1 = fmaxf(m1, fmaxf(acc[nt][2], acc[nt][3]));
    }
    m0 = fmaxf(m0, __shfl_xor_sync(0xffffffffu, m0, 1));
    m0 = fmaxf(m0, __shfl_xor_sync(0xffffffffu, m0, 2));
    m1 = fmaxf(m1, __shfl_xor_sync(0xffffffffu, m1, 1));
    m1 = fmaxf(m1, __shfl_xor_sync(0xffffffffu, m1, 2));
    float s0 = 0.f, s1 = 0.f;
#pragma unroll
    for (int nt = 0; nt < 8; nt++) {
        acc[nt][0] = __expf(acc[nt][0] - m0); s0 += acc[nt][0];
        acc[nt][1] = __expf(acc[nt][1] - m0); s0 += acc[nt][1];
        acc[nt][2] = __expf(acc[nt][2] - m1); s1 += acc[nt][2];
        acc[nt][3] = __expf(acc[nt][3] - m1); s1 += acc[nt][3];
    }
    s0 += __shfl_xor_sync(0xffffffffu, s0, 1);
    s0 += __shfl_xor_sync(0xffffffffu, s0, 2);
    s1 += __shfl_xor_sync(0xffffffffu, s1, 1);
    s1 += __shfl_xor_sync(0xffffffffu, s1, 2);

    uint32_t ph[4][4], pl[4][4];
#pragma unroll
    for (int kk = 0; kk < 4; kk++) {
        hsplit2(acc[2 * kk][0],     acc[2 * kk][1],     ph[kk][0], pl[kk][0]);
        hsplit2(acc[2 * kk][2],     acc[2 * kk][3],     ph[kk][1], pl[kk][1]);
        hsplit2(acc[2 * kk + 1][0], acc[2 * kk + 1][1], ph[kk][2], pl[kk][2]);
        hsplit2(acc[2 * kk + 1][2], acc[2 * kk + 1][3], ph[kk][3], pl[kk][3]);
    }

    float oacc[4][4];
#pragma unroll
    for (int a = 0; a < 4; a++)
#pragma unroll
        for (int c = 0; c < 4; c++) oacc[a][c] = 0.f;
#pragma unroll
    for (int kkp = 0; kkp < 4; kkp += 2) {
        uint32_t vh4[2][2][4], vl4[2][2][4];
#pragma unroll
        for (int j = 0; j < 2; j++)
#pragma unroll
            for (int d2 = 0; d2 < 2; d2++) {
                const uint32_t rv = sb + TV_H +
                    (uint32_t)((kkp + j) * 16 + (lane & 7) + ((lane >> 3) & 1) * 8) * RS +
                    d2 * 32 + ((lane >> 4) & 1) * 16;
                LDSM4T(vh4[j][d2], rv);
                LDSM4T(vl4[j][d2], rv + 5120);
            }
#pragma unroll
        for (int j = 0; j < 2; j++)
#pragma unroll
            for (int d2 = 0; d2 < 2; d2++) {
                MMA_F16(oacc[2 * d2],     ph[kkp + j], vh4[j][d2][0], vh4[j][d2][1]);
                MMA_F16(oacc[2 * d2 + 1], ph[kkp + j], vh4[j][d2][2], vh4[j][d2][3]);
            }
#pragma unroll
        for (int j = 0; j < 2; j++)
#pragma unroll
            for (int d2 = 0; d2 < 2; d2++) {
                MMA_F16(oacc[2 * d2],     ph[kkp + j], vl4[j][d2][0], vl4[j][d2][1]);
                MMA_F16(oacc[2 * d2 + 1], ph[kkp + j], vl4[j][d2][2], vl4[j][d2][3]);
            }
#pragma unroll
        for (int j = 0; j < 2; j++)
#pragma unroll
            for (int d2 = 0; d2 < 2; d2++) {
                MMA_F16(oacc[2 * d2],     pl[kkp + j], vh4[j][d2][0], vh4[j][d2][1]);
                MMA_F16(oacc[2 * d2 + 1], pl[kkp + j], vh4[j][d2][2], vh4[j][d2][3]);
            }
    }

    const float inv0 = 1.f / s0, inv1 = 1.f / s1;
    if (r0 < SEQ) {
        __half* orow = out_h + (size_t)(b * SEQ + r0) * CDIM + h * HD + cb;
#pragma unroll
        for (int dt = 0; dt < 4; dt++) {
            __half2 o = __floats2half2_rn(oacc[dt][0] * inv0, oacc[dt][1] * inv0);
            *(__half2*)(orow + dt * 8) = o;
        }
    }
    if (r0 + 8 < SEQ) {
        __half* orow = out_h + (size_t)(b * SEQ + r0 + 8) * CDIM + h * HD + cb;
#pragma unroll
        for (int dt = 0; dt < 4; dt++) {
            __half2 o = __floats2half2_rn(oacc[dt][2] * inv1, oacc[dt][3] * inv1);
            *(__half2*)(orow + dt * 8) = o;
        }
    }
}

// ---------------------------------------------------------------------------
extern "C" void kernel_launch(void* const* d_in, const int* in_sizes, int n_in,
                              void* d_out, int out_size)
{
    const float* x      = (const float*)d_in[0];
    const float* mask   = (const float*)d_in[1];
    const float* qkv_w  = (const float*)d_in[2];
    const float* qkv_b  = (const float*)d_in[3];
    const float* proj_w = (const float*)d_in[4];
    const float* proj_b = (const float*)d_in[5];
    const float* table  = (const float*)d_in[6];
    const int*   idx    = (const int*)d_in[7];
    float* out = (float*)d_out;

    float *qkv_s, *cmb_s;
    __half *xh, *ath, *qwh, *pwh;
    cudaGetSymbolAddress((void**)&qkv_s, g_qkv);
    cudaGetSymbolAddress((void**)&cmb_s, g_cmb);
    cudaGetSymbolAddress((void**)&xh, g_x_h);
    cudaGetSymbolAddress((void**)&ath, g_att_h);
    cudaGetSymbolAddress((void**)&qwh, g_qw_h);
    cudaGetSymbolAddress((void**)&pwh, g_pw_h);

    cudaFuncSetAttribute(gemm_f16, cudaFuncAttributeMaxDynamicSharedMemorySize, GSMEM);

    const int n4 = MROWS * KDIM / 4;
    fconv<<<(n4 + 255) / 256, 256>>>((const float4*)x, (uint2*)xh, n4);
    wconv<<<dim3(1536 / 32, 512 / 32), dim3(32, 8)>>>(qkv_w, qwh, 512, 1536);
    wconv<<<dim3(512 / 32, 512 / 32), dim3(32, 8)>>>(proj_w, pwh, 512, 512);
    cmb_prep<<<dim3(NW, NH), 256>>>(mask, table, idx, cmb_s);

    gemm_f16<<<dim3(1536 / 128, MROWS / 128), 256, GSMEM>>>(
        xh, qwh, qkv_b, qkv_s, 1536);

    attn_mma<<<B_WIN * NH, 128>>>(qkv_s, cmb_s, ath);

    gemm_f16<<<dim3(512 / 128, MROWS / 128), 256, GSMEM>>>(
        ath, pwh, proj_b, out, 512);
}

// round 11
// speedup vs baseline: 3.2291x; 1.0008x over previous
#include <cuda_runtime.h>
#include <cuda_fp16.h>
#include <cstdint>
#include <cstddef>

#define B_WIN 4096
#define SEQ   49
#define CDIM  512
#define NH    16
#define HD    32
#define NW    64
#define MROWS (B_WIN * SEQ)      // 200704
#define KDIM  512

// ---------------- device scratch (no cudaMalloc allowed) -------------------
__device__ float g_qkv[(size_t)MROWS * 1536];        // [B*N, 3C] fp32
__device__ __half g_x_h[(size_t)MROWS * KDIM];       // x fp16
__device__ __half g_att_h[(size_t)MROWS * KDIM];     // attn out fp16
__device__ __half g_qw_h[1536 * KDIM];               // qkv_w^T fp16 [N,K]
__device__ __half g_pw_h[512 * KDIM];                // proj_w^T fp16 [N,K]
__device__ float g_cmb[(size_t)NW * NH * 64 * 64];   // bias+mask, padded

// ---------------- helpers (arch-portable PTX: sm_80+ features only) --------
__device__ __forceinline__ uint32_t smem_u32(const void* p) {
    uint32_t a;
    asm("{ .reg .u64 t; cvta.to.shared.u64 t, %1; cvt.u32.u64 %0, t; }"
        : "=r"(a) : "l"(p));
    return a;
}
#define CPA16(dst, src) \
    asm volatile("cp.async.cg.shared.global [%0], [%1], 16;" \
                 :: "r"(dst), "l"(src) : "memory")
#define CPCOMMIT() asm volatile("cp.async.commit_group;" ::: "memory")
#define CPWAIT(n)  asm volatile("cp.async.wait_group %0;" :: "n"(n) : "memory")
#define LDSM4(r, addr)                                                        \
    asm volatile("ldmatrix.sync.aligned.m8n8.x4.shared.b16 {%0,%1,%2,%3}, [%4];" \
        : "=r"((r)[0]), "=r"((r)[1]), "=r"((r)[2]), "=r"((r)[3]) : "r"(addr))
#define LDSM4T(r, addr)                                                       \
    asm volatile("ldmatrix.sync.aligned.m8n8.x4.trans.shared.b16 {%0,%1,%2,%3}, [%4];" \
        : "=r"((r)[0]), "=r"((r)[1]), "=r"((r)[2]), "=r"((r)[3]) : "r"(addr))
#define MMA_F16(d, a, b0, b1)                                                 \
    asm volatile("mma.sync.aligned.m16n8k16.row.col.f32.f16.f16.f32 "         \
        "{%0,%1,%2,%3},{%4,%5,%6,%7},{%8,%9},{%0,%1,%2,%3};"                  \
        : "+f"((d)[0]), "+f"((d)[1]), "+f"((d)[2]), "+f"((d)[3])              \
        : "r"((a)[0]), "r"((a)[1]), "r"((a)[2]), "r"((a)[3]),                 \
          "r"(b0), "r"(b1))

__device__ __forceinline__ void hsplit2(float a, float b, uint32_t& hi, uint32_t& lo) {
    __half2 h = __floats2half2_rn(a, b);
    float2 hf = __half22float2(h);
    __half2 l = __floats2half2_rn(a - hf.x, b - hf.y);
    hi = *(uint32_t*)&h;
    lo = *(uint32_t*)&l;
}

// ---------------------------------------------------------------------------
// fp32 -> fp16 convert (activations)
// ---------------------------------------------------------------------------
__global__ void fconv(const float4* __restrict__ in, uint2* __restrict__ out, int n4)
{
    const int i = blockIdx.x * blockDim.x + threadIdx.x;
    if (i >= n4) return;
    float4 v = in[i];
    __half2 a = __floats2half2_rn(v.x, v.y);
    __half2 b = __floats2half2_rn(v.z, v.w);
    uint2 o = { *(uint32_t*)&a, *(uint32_t*)&b };
    out[i] = o;
}

// ---------------------------------------------------------------------------
// Weight prep: W[K,N] fp32 -> B[N,K] fp16 (transposed, single term)
// ---------------------------------------------------------------------------
__global__ void wconv(const float* __restrict__ W, __half* __restrict__ Bh,
                      int K, int N)
{
    __shared__ float t[32][33];
    const int bx = blockIdx.x, by = blockIdx.y;
    const int x = threadIdx.x, y = threadIdx.y;   // 32 x 8
#pragma unroll
    for (int i = 0; i < 4; i++)
        t[y + i * 8][x] = W[(size_t)(by * 32 + y + i * 8) * N + bx * 32 + x];
    __syncthreads();
#pragma unroll
    for (int i = 0; i < 4; i++)
        Bh[(size_t)(bx * 32 + y + i * 8) * K + by * 32 + x] =
            __float2half_rn(t[x][y + i * 8]);
}

// ---------------------------------------------------------------------------
// cmb[w][h][n][m] = bias(h,n,m) + mask(w,n,m), padded 64x64 (pad cols = -1e9)
// ---------------------------------------------------------------------------
__global__ void cmb_prep(const float* __restrict__ mask, const float* __restrict__ table,
                         const int* __restrict__ idx, float* __restrict__ cmb)
{
    const int w = blockIdx.x, h = blockIdx.y;
    float* dst = cmb + (((size_t)w * NH + h) << 12);
    for (int i = threadIdx.x; i < 4096; i += 256) {
        const int n = i >> 6, m = i & 63;
        float v;
        if (m >= SEQ)      v = -1e9f;
        else if (n >= SEQ) v = 0.f;
        else v = table[idx[n * SEQ + m] * NH + h] + mask[(size_t)w * SEQ * SEQ + n * SEQ + m];
        dst[i] = v;
    }
}

// ---------------------------------------------------------------------------
// fp16 mma.sync GEMM, single-term weights:
//   C[M,Ntot] = A[M,512] @ B[N,512]^T + bias
// CTA 128x128, BK=32, 3-stage cp.async, 8 warps x (64x32). 80B rows.
// ---------------------------------------------------------------------------
#define RS        80
#define AT_BYTES  (128 * RS)
#define STAGE     (2 * AT_BYTES)       // A + B
#define NSTAGE    3
#define GSMEM     (NSTAGE * STAGE)     // 61440

__global__ __launch_bounds__(256, 2)
void gemm_f16(const __half* __restrict__ A_g,
              const __half* __restrict__ B_g,
              const float* __restrict__ bias, float* __restrict__ C, int Ntot)
{
    extern __shared__ __align__(128) char sm[];
    const uint32_t sb = smem_u32(sm);
    const int tid = threadIdx.x;
    const int lane = tid & 31, wid = tid >> 5;
    const int m0 = blockIdx.y * 128, n0 = blockIdx.x * 128;
    const int wm = (wid >> 2) * 64, wn = (wid & 3) * 32;

    const int crow = tid >> 1;
    const int cc   = (tid & 1) * 32;

    const char* gsrc0 = (const char*)(A_g + (size_t)m0 * KDIM);
    const char* gsrc1 = (const char*)(B_g + (size_t)n0 * KDIM);

    float acc[4][4][4];
#pragma unroll
    for (int a = 0; a < 4; a++)
#pragma unroll
        for (int b = 0; b < 4; b++)
#pragma unroll
            for (int c = 0; c < 4; c++) acc[a][b][c] = 0.f;

    auto issue = [&](int s, int kc) {
        const int gofs = crow * 1024 + kc * 64 + cc;
        const uint32_t dst = sb + s * STAGE + crow * RS + cc;
        CPA16(dst,                     gsrc0 + gofs);
        CPA16(dst + 16,                gsrc0 + gofs + 16);
        CPA16(dst + AT_BYTES,          gsrc1 + gofs);
        CPA16(dst + AT_BYTES + 16,     gsrc1 + gofs + 16);
        CPCOMMIT();
    };

    issue(0, 0);
    issue(1, 1);

    const int r = lane & 15;
    const uint32_t khalf = (lane >> 4) * 16;

    for (int kc = 0; kc < 16; kc++) {
        const int s = kc % NSTAGE;
        if (kc < 15) { CPWAIT(1); } else { CPWAIT(0); }
        __syncthreads();
        if (kc + 2 < 16) issue((kc + 2) % NSTAGE, kc + 2);

        const uint32_t base = sb + s * STAGE;
#pragma unroll
        for (int kk = 0; kk < 2; kk++) {
            const uint32_t ko = kk * 32 + khalf;
            uint32_t ah[4][4], bh[2][4];
#pragma unroll
            for (int mt = 0; mt < 4; mt++) {
                const uint32_t ra = base + (uint32_t)(wm + mt * 16 + r) * RS + ko;
                LDSM4(ah[mt], ra);
            }
#pragma unroll
            for (int p = 0; p < 2; p++) {
                const uint32_t rb = base + AT_BYTES +
                                    (uint32_t)(wn + p * 16 + r) * RS + ko;
                LDSM4(bh[p], rb);
            }
#pragma unroll
            for (int mt = 0; mt < 4; mt++)
#pragma unroll
                for (int nt = 0; nt < 4; nt++) {
                    const int p = nt >> 1, o = nt & 1;
                    MMA_F16(acc[mt][nt], ah[mt], bh[p][o], bh[p][o + 2]);
                }
        }
    }

#pragma unroll
    for (int mt = 0; mt < 4; mt++) {
        const int gr = m0 + wm + mt * 16 + (lane >> 2);
#pragma unroll
        for (int nt = 0; nt < 4; nt++) {
            const int gc = n0 + wn + nt * 8 + (lane & 3) * 2;
            const float b0 = bias[gc], b1 = bias[gc + 1];
            float2 v0 = { acc[mt][nt][0] + b0, acc[mt][nt][1] + b1 };
            float2 v1 = { acc[mt][nt][2] + b0, acc[mt][nt][3] + b1 };
            *(float2*)&C[(size_t)gr * Ntot + gc] = v0;
            *(float2*)&C[(size_t)(gr + 8) * Ntot + gc] = v1;
        }
    }
}

// ---------------------------------------------------------------------------
// Tensor-core window attention (unchanged from R9 — 3-term splits)
// ---------------------------------------------------------------------------
#define TQ_H 0
#define TQ_L 5120
#define TK_H 10240
#define TK_L 15360
#define TV_H 20480
#define TV_L 25600
#define ASMEM 30720

__global__ __launch_bounds__(128)
void attn_mma(const float* __restrict__ qkv, const float* __restrict__ cmb,
              __half* __restrict__ out_h)
{
    const int bh = blockIdx.x;
    const int b = bh >> 4, h = bh & 15;
    const int tid = threadIdx.x;
    const int lane = tid & 31, wq = tid >> 5;

    __shared__ __align__(16) char smem[ASMEM];
    const uint32_t sb = smem_u32(smem);

    for (int i = tid; i < ASMEM / 16; i += 128)
        ((uint4*)smem)[i] = make_uint4(0, 0, 0, 0);
    __syncthreads();

    const float scale = 0.17677669529663687f;
    const size_t rowbase = (size_t)b * SEQ * 1536;
    for (int i = tid; i < 3 * SEQ * 8; i += 128) {
        const int t = i / (SEQ * 8);
        const int rem = i - t * (SEQ * 8);
        const int row = rem >> 3, c4 = rem & 7;
        float4 v = *(const float4*)(qkv + rowbase + (size_t)row * 1536 +
                                    t * 512 + h * HD + c4 * 4);
        if (t == 0) { v.x *= scale; v.y *= scale; v.z *= scale; v.w *= scale; }
        uint2 hi, lo;
        hsplit2(v.x, v.y, hi.x, lo.x);
        hsplit2(v.z, v.w, hi.y, lo.y);
        char* dst = smem + t * 10240 + row * RS + c4 * 8;
        *(uint2*)dst = hi;
        *(uint2*)(dst + 5120) = lo;
    }
    __syncthreads();

    const int r0 = wq * 16 + (lane >> 2);
    const int cb = (lane & 3) * 2;
    float acc[8][4];
    const float* cw = cmb + (((size_t)(b & (NW - 1)) * NH + h) << 12);
#pragma unroll
    for (int nt = 0; nt < 8; nt++) {
        float2 v0 = *(const float2*)(cw + r0 * 64 + nt * 8 + cb);
        float2 v1 = *(const float2*)(cw + (r0 + 8) * 64 + nt * 8 + cb);
        acc[nt][0] = v0.x; acc[nt][1] = v0.y;
        acc[nt][2] = v1.x; acc[nt][3] = v1.y;
    }

    uint32_t qh[2][4], ql[2][4];
#pragma unroll
    for (int kt = 0; kt < 2; kt++) {
        const uint32_t ra = sb + TQ_H + (uint32_t)(wq * 16 + (lane & 15)) * RS +
                            kt * 32 + (lane >> 4) * 16;
        LDSM4(qh[kt], ra);
        LDSM4(ql[kt], ra + 5120);
    }
#pragma unroll
    for (int kt = 0; kt < 2; kt++)
#pragma unroll
        for (int t2p = 0; t2p < 4; t2p += 2) {
            uint32_t kh4[2][4], kl4[2][4];
#pragma unroll
            for (int j = 0; j < 2; j++) {
                const uint32_t rk = sb + TK_H +
                    (uint32_t)((t2p + j) * 16 + (lane & 7) + ((lane >> 4) & 1) * 8) * RS +
                    kt * 32 + ((lane >> 3) & 1) * 16;
                LDSM4(kh4[j], rk);
                LDSM4(kl4[j], rk + 5120);
            }
#pragma unroll
            for (int j = 0; j < 2; j++) {
                MMA_F16(acc[2 * (t2p + j)],     qh[kt], kh4[j][0], kh4[j][1]);
                MMA_F16(acc[2 * (t2p + j) + 1], qh[kt], kh4[j][2], kh4[j][3]);
            }
#pragma unroll
            for (int j = 0; j < 2; j++) {
                MMA_F16(acc[2 * (t2p + j)],     qh[kt], kl4[j][0], kl4[j][1]);
                MMA_F16(acc[2 * (t2p + j) + 1], qh[kt], kl4[j][2], kl4[j][3]);
            }
#pragma unroll
            for (int j = 0; j < 2; j++) {
                MMA_F16(acc[2 * (t2p + j)],     ql[kt], kh4[j][0], kh4[j][1]);
                MMA_F16(acc[2 * (t2p + j) + 1], ql[kt], kh4[j][2], kh4[j][3]);
            }
        }

    float m0 = -1e30f, m1 = -1e30f;
#pragma unroll
    for (int nt = 0; nt < 8; nt++) {
        m0 = fmaxf(m0, fmaxf(acc[nt][0], acc[nt][1]));
        m1 = fmaxf(m1, fmaxf(acc[nt][2], acc[nt][3]));
    }
    m0 = fmaxf(m0, __shfl_xor_sync(0xffffffffu, m0, 1));
    m0 = fmaxf(m0, __shfl_xor_sync(0xffffffffu, m0, 2));
    m1 = fmaxf(m1, __shfl_xor_sync(0xffffffffu, m1, 1));
    m1 = fmaxf(m1, __shfl_xor_sync(0xffffffffu, m1, 2));
    float s0 = 0.f, s1 = 0.f;
#pragma unroll
    for (int nt = 0; nt < 8; nt++) {
        acc[nt][0] = __expf(acc[nt][0] - m0); s0 += acc[nt][0];
        acc[nt][1] = __expf(acc[nt][1] - m0); s0 += acc[nt][1];
        acc[nt][2] = __expf(acc[nt][2] - m1); s1 += acc[nt][2];
        acc[nt][3] = __expf(acc[nt][3] - m1); s1 += acc[nt][3];
    }
    s0 += __shfl_xor_sync(0xffffffffu, s0, 1);
    s0 += __shfl_xor_sync(0xffffffffu, s0, 2);
    s1 += __shfl_xor_sync(0xffffffffu, s1, 1);
    s1 += __shfl_xor_sync(0xffffffffu, s1, 2);

    uint32_t ph[4][4], pl[4][4];
#pragma unroll
    for (int kk = 0; kk < 4; kk++) {
        hsplit2(acc[2 * kk][0],     acc[2 * kk][1],     ph[kk][0], pl[kk][0]);
        hsplit2(acc[2 * kk][2],     acc[2 * kk][3],     ph[kk][1], pl[kk][1]);
        hsplit2(acc[2 * kk + 1][0], acc[2 * kk + 1][1], ph[kk][2], pl[kk][2]);
        hsplit2(acc[2 * kk + 1][2], acc[2 * kk + 1][3], ph[kk][3], pl[kk][3]);
    }

    float oacc[4][4];
#pragma unroll
    for (int a = 0; a < 4; a++)
#pragma unroll
        for (int c = 0; c < 4; c++) oacc[a][c] = 0.f;
#pragma unroll
    for (int kkp = 0; kkp < 4; kkp += 2) {
        uint32_t vh4[2][2][4], vl4[2][2][4];
#pragma unroll
        for (int j = 0; j < 2; j++)
#pragma unroll
            for (int d2 = 0; d2 < 2; d2++) {
                const uint32_t rv = sb + TV_H +
                    (uint32_t)((kkp + j) * 16 + (lane & 7) + ((lane >> 3) & 1) * 8) * RS +
                    d2 * 32 + ((lane >> 4) & 1) * 16;
                LDSM4T(vh4[j][d2], rv);
                LDSM4T(vl4[j][d2], rv + 5120);
            }
#pragma unroll
        for (int j = 0; j < 2; j++)
#pragma unroll
            for (int d2 = 0; d2 < 2; d2++) {
                MMA_F16(oacc[2 * d2],     ph[kkp + j], vh4[j][d2][0], vh4[j][d2][1]);
                MMA_F16(oacc[2 * d2 + 1], ph[kkp + j], vh4[j][d2][2], vh4[j][d2][3]);
            }
#pragma unroll
        for (int j = 0; j < 2; j++)
#pragma unroll
            for (int d2 = 0; d2 < 2; d2++) {
                MMA_F16(oacc[2 * d2],     ph[kkp + j], vl4[j][d2][0], vl4[j][d2][1]);
                MMA_F16(oacc[2 * d2 + 1], ph[kkp + j], vl4[j][d2][2], vl4[j][d2][3]);
            }
#pragma unroll
        for (int j = 0; j < 2; j++)
#pragma unroll
            for (int d2 = 0; d2 < 2; d2++) {
                MMA_F16(oacc[2 * d2],     pl[kkp + j], vh4[j][d2][0], vh4[j][d2][1]);
                MMA_F16(oacc[2 * d2 + 1], pl[kkp + j], vh4[j][d2][2], vh4[j][d2][3]);
            }
    }

    const float inv0 = 1.f / s0, inv1 = 1.f / s1;
    if (r0 < SEQ) {
        __half* orow = out_h + (size_t)(b * SEQ + r0) * CDIM + h * HD + cb;
#pragma unroll
        for (int dt = 0; dt < 4; dt++) {
            __half2 o = __floats2half2_rn(oacc[dt][0] * inv0, oacc[dt][1] * inv0);
            *(__half2*)(orow + dt * 8) = o;
        }
    }
    if (r0 + 8 < SEQ) {
        __half* orow = out_h + (size_t)(b * SEQ + r0 + 8) * CDIM + h * HD + cb;
#pragma unroll
        for (int dt = 0; dt < 4; dt++) {
            __half2 o = __floats2half2_rn(oacc[dt][2] * inv1, oacc[dt][3] * inv1);
            *(__half2*)(orow + dt * 8) = o;
        }
    }
}

// ---------------------------------------------------------------------------
extern "C" void kernel_launch(void* const* d_in, const int* in_sizes, int n_in,
                              void* d_out, int out_size)
{
    const float* x      = (const float*)d_in[0];
    const float* mask   = (const float*)d_in[1];
    const float* qkv_w  = (const float*)d_in[2];
    const float* qkv_b  = (const float*)d_in[3];
    const float* proj_w = (const float*)d_in[4];
    const float* proj_b = (const float*)d_in[5];
    const float* table  = (const float*)d_in[6];
    const int*   idx    = (const int*)d_in[7];
    float* out = (float*)d_out;

    float *qkv_s, *cmb_s;
    __half *xh, *ath, *qwh, *pwh;
    cudaGetSymbolAddress((void**)&qkv_s, g_qkv);
    cudaGetSymbolAddress((void**)&cmb_s, g_cmb);
    cudaGetSymbolAddress((void**)&xh, g_x_h);
    cudaGetSymbolAddress((void**)&ath, g_att_h);
    cudaGetSymbolAddress((void**)&qwh, g_qw_h);
    cudaGetSymbolAddress((void**)&pwh, g_pw_h);

    cudaFuncSetAttribute(gemm_f16, cudaFuncAttributeMaxDynamicSharedMemorySize, GSMEM);

    const int n4 = MROWS * KDIM / 4;
    fconv<<<(n4 + 255) / 256, 256>>>((const float4*)x, (uint2*)xh, n4);
    wconv<<<dim3(1536 / 32, 512 / 32), dim3(32, 8)>>>(qkv_w, qwh, 512, 1536);
    wconv<<<dim3(512 / 32, 512 / 32), dim3(32, 8)>>>(proj_w, pwh, 512, 512);
    cmb_prep<<<dim3(NW, NH), 256>>>(mask, table, idx, cmb_s);

    gemm_f16<<<dim3(1536 / 128, MROWS / 128), 256, GSMEM>>>(
        xh, qwh, qkv_b, qkv_s, 1536);

    attn_mma<<<B_WIN * NH, 128>>>(qkv_s, cmb_s, ath);

    gemm_f16<<<dim3(512 / 128, MROWS / 128), 256, GSMEM>>>(
        ath, pwh, proj_b, out, 512);
}

// round 12
// speedup vs baseline: 3.3575x; 1.0398x over previous
#include <cuda_runtime.h>
#include <cuda_fp16.h>
#include <cstdint>
#include <cstddef>

#define B_WIN 4096
#define SEQ   49
#define CDIM  512
#define NH    16
#define HD    32
#define NW    64
#define MROWS (B_WIN * SEQ)      // 200704
#define KDIM  512

// ---------------- device scratch (no cudaMalloc allowed) -------------------
__device__ float g_qkv[(size_t)MROWS * 1536];        // [B*N, 3C] fp32
__device__ __half g_x_h[(size_t)MROWS * KDIM];       // x fp16
__device__ __half g_att_h[(size_t)MROWS * KDIM];     // attn out fp16
__device__ __half g_qw_h[1536 * KDIM];               // qkv_w^T fp16 [N,K]
__device__ __half g_pw_h[512 * KDIM];                // proj_w^T fp16 [N,K]
__device__ float g_cmb[(size_t)NW * NH * 64 * 64];   // bias+mask, padded

// ---------------- helpers (arch-portable PTX: sm_80+ features only) --------
__device__ __forceinline__ uint32_t smem_u32(const void* p) {
    uint32_t a;
    asm("{ .reg .u64 t; cvta.to.shared.u64 t, %1; cvt.u32.u64 %0, t; }"
        : "=r"(a) : "l"(p));
    return a;
}
#define CPA16(dst, src) \
    asm volatile("cp.async.cg.shared.global [%0], [%1], 16;" \
                 :: "r"(dst), "l"(src) : "memory")
#define CPCOMMIT() asm volatile("cp.async.commit_group;" ::: "memory")
#define CPWAIT(n)  asm volatile("cp.async.wait_group %0;" :: "n"(n) : "memory")
#define LDSM4(r, addr)                                                        \
    asm volatile("ldmatrix.sync.aligned.m8n8.x4.shared.b16 {%0,%1,%2,%3}, [%4];" \
        : "=r"((r)[0]), "=r"((r)[1]), "=r"((r)[2]), "=r"((r)[3]) : "r"(addr))
#define LDSM4T(r, addr)                                                       \
    asm volatile("ldmatrix.sync.aligned.m8n8.x4.trans.shared.b16 {%0,%1,%2,%3}, [%4];" \
        : "=r"((r)[0]), "=r"((r)[1]), "=r"((r)[2]), "=r"((r)[3]) : "r"(addr))
#define MMA_F16(d, a, b0, b1)                                                 \
    asm volatile("mma.sync.aligned.m16n8k16.row.col.f32.f16.f16.f32 "         \
        "{%0,%1,%2,%3},{%4,%5,%6,%7},{%8,%9},{%0,%1,%2,%3};"                  \
        : "+f"((d)[0]), "+f"((d)[1]), "+f"((d)[2]), "+f"((d)[3])              \
        : "r"((a)[0]), "r"((a)[1]), "r"((a)[2]), "r"((a)[3]),                 \
          "r"(b0), "r"(b1))

__device__ __forceinline__ void hsplit2(float a, float b, uint32_t& hi, uint32_t& lo) {
    __half2 h = __floats2half2_rn(a, b);
    float2 hf = __half22float2(h);
    __half2 l = __floats2half2_rn(a - hf.x, b - hf.y);
    hi = *(uint32_t*)&h;
    lo = *(uint32_t*)&l;
}
__device__ __forceinline__ uint32_t hpack2(float a, float b) {
    __half2 h = __floats2half2_rn(a, b);
    return *(uint32_t*)&h;
}

// ---------------------------------------------------------------------------
// fp32 -> fp16 convert (activations)
// ---------------------------------------------------------------------------
__global__ void fconv(const float4* __restrict__ in, uint2* __restrict__ out, int n4)
{
    const int i = blockIdx.x * blockDim.x + threadIdx.x;
    if (i >= n4) return;
    float4 v = in[i];
    uint2 o = { hpack2(v.x, v.y), hpack2(v.z, v.w) };
    out[i] = o;
}

// ---------------------------------------------------------------------------
// Weight prep: W[K,N] fp32 -> B[N,K] fp16 (transposed, single term)
// ---------------------------------------------------------------------------
__global__ void wconv(const float* __restrict__ W, __half* __restrict__ Bh,
                      int K, int N)
{
    __shared__ float t[32][33];
    const int bx = blockIdx.x, by = blockIdx.y;
    const int x = threadIdx.x, y = threadIdx.y;   // 32 x 8
#pragma unroll
    for (int i = 0; i < 4; i++)
        t[y + i * 8][x] = W[(size_t)(by * 32 + y + i * 8) * N + bx * 32 + x];
    __syncthreads();
#pragma unroll
    for (int i = 0; i < 4; i++)
        Bh[(size_t)(bx * 32 + y + i * 8) * K + by * 32 + x] =
            __float2half_rn(t[x][y + i * 8]);
}

// ---------------------------------------------------------------------------
// cmb[w][h][n][m] = bias(h,n,m) + mask(w,n,m), padded 64x64 (pad cols = -1e9)
// ---------------------------------------------------------------------------
__global__ void cmb_prep(const float* __restrict__ mask, const float* __restrict__ table,
                         const int* __restrict__ idx, float* __restrict__ cmb)
{
    const int w = blockIdx.x, h = blockIdx.y;
    float* dst = cmb + (((size_t)w * NH + h) << 12);
    for (int i = threadIdx.x; i < 4096; i += 256) {
        const int n = i >> 6, m = i & 63;
        float v;
        if (m >= SEQ)      v = -1e9f;
        else if (n >= SEQ) v = 0.f;
        else v = table[idx[n * SEQ + m] * NH + h] + mask[(size_t)w * SEQ * SEQ + n * SEQ + m];
        dst[i] = v;
    }
}

// ---------------------------------------------------------------------------
// fp16 mma.sync GEMM, single-term weights (unchanged from R11 — at HMMA floor)
// ---------------------------------------------------------------------------
#define RS        80
#define AT_BYTES  (128 * RS)
#define STAGE     (2 * AT_BYTES)       // A + B
#define NSTAGE    3
#define GSMEM     (NSTAGE * STAGE)     // 61440

__global__ __launch_bounds__(256, 2)
void gemm_f16(const __half* __restrict__ A_g,
              const __half* __restrict__ B_g,
              const float* __restrict__ bias, float* __restrict__ C, int Ntot)
{
    extern __shared__ __align__(128) char sm[];
    const uint32_t sb = smem_u32(sm);
    const int tid = threadIdx.x;
    const int lane = tid & 31, wid = tid >> 5;
    const int m0 = blockIdx.y * 128, n0 = blockIdx.x * 128;
    const int wm = (wid >> 2) * 64, wn = (wid & 3) * 32;

    const int crow = tid >> 1;
    const int cc   = (tid & 1) * 32;

    const char* gsrc0 = (const char*)(A_g + (size_t)m0 * KDIM);
    const char* gsrc1 = (const char*)(B_g + (size_t)n0 * KDIM);

    float acc[4][4][4];
#pragma unroll
    for (int a = 0; a < 4; a++)
#pragma unroll
        for (int b = 0; b < 4; b++)
#pragma unroll
            for (int c = 0; c < 4; c++) acc[a][b][c] = 0.f;

    auto issue = [&](int s, int kc) {
        const int gofs = crow * 1024 + kc * 64 + cc;
        const uint32_t dst = sb + s * STAGE + crow * RS + cc;
        CPA16(dst,                 gsrc0 + gofs);
        CPA16(dst + 16,            gsrc0 + gofs + 16);
        CPA16(dst + AT_BYTES,      gsrc1 + gofs);
        CPA16(dst + AT_BYTES + 16, gsrc1 + gofs + 16);
        CPCOMMIT();
    };

    issue(0, 0);
    issue(1, 1);

    const int r = lane & 15;
    const uint32_t khalf = (lane >> 4) * 16;

    for (int kc = 0; kc < 16; kc++) {
        const int s = kc % NSTAGE;
        if (kc < 15) { CPWAIT(1); } else { CPWAIT(0); }
        __syncthreads();
        if (kc + 2 < 16) issue((kc + 2) % NSTAGE, kc + 2);

        const uint32_t base = sb + s * STAGE;
#pragma unroll
        for (int kk = 0; kk < 2; kk++) {
            const uint32_t ko = kk * 32 + khalf;
            uint32_t ah[4][4], bh[2][4];
#pragma unroll
            for (int mt = 0; mt < 4; mt++) {
                const uint32_t ra = base + (uint32_t)(wm + mt * 16 + r) * RS + ko;
                LDSM4(ah[mt], ra);
            }
#pragma unroll
            for (int p = 0; p < 2; p++) {
                const uint32_t rb = base + AT_BYTES +
                                    (uint32_t)(wn + p * 16 + r) * RS + ko;
                LDSM4(bh[p], rb);
            }
#pragma unroll
            for (int mt = 0; mt < 4; mt++)
#pragma unroll
                for (int nt = 0; nt < 4; nt++) {
                    const int p = nt >> 1, o = nt & 1;
                    MMA_F16(acc[mt][nt], ah[mt], bh[p][o], bh[p][o + 2]);
                }
        }
    }

#pragma unroll
    for (int mt = 0; mt < 4; mt++) {
        const int gr = m0 + wm + mt * 16 + (lane >> 2);
#pragma unroll
        for (int nt = 0; nt < 4; nt++) {
            const int gc = n0 + wn + nt * 8 + (lane & 3) * 2;
            const float b0 = bias[gc], b1 = bias[gc + 1];
            float2 v0 = { acc[mt][nt][0] + b0, acc[mt][nt][1] + b1 };
            float2 v1 = { acc[mt][nt][2] + b0, acc[mt][nt][3] + b1 };
            *(float2*)&C[(size_t)gr * Ntot + gc] = v0;
            *(float2*)&C[(size_t)(gr + 8) * Ntot + gc] = v1;
        }
    }
}

// ---------------------------------------------------------------------------
// Tensor-core window attention.
//  - QK: 3-term split, nt=7 (cols 56..63, pure padding) dropped exactly.
//  - softmax: 28 exps/thread (acc[7] skipped; pad cols 49..55 give exp->0).
//  - PV: single-term fp16 (P hi only, V hi only).
// ---------------------------------------------------------------------------
#define TQ_H 0
#define TQ_L 5120
#define TK_H 10240
#define TK_L 15360
#define TV_H 20480
#define ASMEM 25600

__global__ __launch_bounds__(128)
void attn_mma(const float* __restrict__ qkv, const float* __restrict__ cmb,
              __half* __restrict__ out_h)
{
    const int bh = blockIdx.x;
    const int b = bh >> 4, h = bh & 15;
    const int tid = threadIdx.x;
    const int lane = tid & 31, wq = tid >> 5;

    __shared__ __align__(16) char smem[ASMEM];
    const uint32_t sb = smem_u32(smem);

    for (int i = tid; i < ASMEM / 16; i += 128)
        ((uint4*)smem)[i] = make_uint4(0, 0, 0, 0);
    __syncthreads();

    const float scale = 0.17677669529663687f;
    const size_t rowbase = (size_t)b * SEQ * 1536;
    for (int i = tid; i < 3 * SEQ * 8; i += 128) {
        const int t = i / (SEQ * 8);
        const int rem = i - t * (SEQ * 8);
        const int row = rem >> 3, c4 = rem & 7;
        float4 v = *(const float4*)(qkv + rowbase + (size_t)row * 1536 +
                                    t * 512 + h * HD + c4 * 4);
        if (t == 0) { v.x *= scale; v.y *= scale; v.z *= scale; v.w *= scale; }
        char* dst = smem + t * 10240 + row * RS + c4 * 8;
        if (t < 2) {
            uint2 hi, lo;
            hsplit2(v.x, v.y, hi.x, lo.x);
            hsplit2(v.z, v.w, hi.y, lo.y);
            *(uint2*)dst = hi;
            *(uint2*)(dst + 5120) = lo;
        } else {
            uint2 hi = { hpack2(v.x, v.y), hpack2(v.z, v.w) };
            *(uint2*)dst = hi;
        }
    }
    __syncthreads();

    // ---- scores: acc init from cmb, then 3-term QK^T (nt 0..6 only) ----
    const int r0 = wq * 16 + (lane >> 2);
    const int cb = (lane & 3) * 2;
    float acc[7][4];
    const float* cw = cmb + (((size_t)(b & (NW - 1)) * NH + h) << 12);
#pragma unroll
    for (int nt = 0; nt < 7; nt++) {
        float2 v0 = *(const float2*)(cw + r0 * 64 + nt * 8 + cb);
        float2 v1 = *(const float2*)(cw + (r0 + 8) * 64 + nt * 8 + cb);
        acc[nt][0] = v0.x; acc[nt][1] = v0.y;
        acc[nt][2] = v1.x; acc[nt][3] = v1.y;
    }

    uint32_t qh[2][4], ql[2][4];
#pragma unroll
    for (int kt = 0; kt < 2; kt++) {
        const uint32_t ra = sb + TQ_H + (uint32_t)(wq * 16 + (lane & 15)) * RS +
                            kt * 32 + (lane >> 4) * 16;
        LDSM4(qh[kt], ra);
        LDSM4(ql[kt], ra + 5120);
    }
#pragma unroll
    for (int kt = 0; kt < 2; kt++)
#pragma unroll
        for (int t2p = 0; t2p < 4; t2p += 2) {
            uint32_t kh4[2][4], kl4[2][4];
#pragma unroll
            for (int j = 0; j < 2; j++) {
                const uint32_t rk = sb + TK_H +
                    (uint32_t)((t2p + j) * 16 + (lane & 7) + ((lane >> 4) & 1) * 8) * RS +
                    kt * 32 + ((lane >> 3) & 1) * 16;
                LDSM4(kh4[j], rk);
                LDSM4(kl4[j], rk + 5120);
            }
#pragma unroll
            for (int j = 0; j < 2; j++) {
                MMA_F16(acc[2 * (t2p + j)], qh[kt], kh4[j][0], kh4[j][1]);
                if (t2p + j < 3)
                    MMA_F16(acc[2 * (t2p + j) + 1], qh[kt], kh4[j][2], kh4[j][3]);
            }
#pragma unroll
            for (int j = 0; j < 2; j++) {
                MMA_F16(acc[2 * (t2p + j)], qh[kt], kl4[j][0], kl4[j][1]);
                if (t2p + j < 3)
                    MMA_F16(acc[2 * (t2p + j) + 1], qh[kt], kl4[j][2], kl4[j][3]);
            }
#pragma unroll
            for (int j = 0; j < 2; j++) {
                MMA_F16(acc[2 * (t2p + j)], ql[kt], kh4[j][0], kh4[j][1]);
                if (t2p + j < 3)
                    MMA_F16(acc[2 * (t2p + j) + 1], ql[kt], kh4[j][2], kh4[j][3]);
            }
        }

    // ---- fragment softmax over nt 0..6 ----
    float m0 = -1e30f, m1 = -1e30f;
#pragma unroll
    for (int nt = 0; nt < 7; nt++) {
        m0 = fmaxf(m0, fmaxf(acc[nt][0], acc[nt][1]));
        m1 = fmaxf(m1, fmaxf(acc[nt][2], acc[nt][3]));
    }
    m0 = fmaxf(m0, __shfl_xor_sync(0xffffffffu, m0, 1));
    m0 = fmaxf(m0, __shfl_xor_sync(0xffffffffu, m0, 2));
    m1 = fmaxf(m1, __shfl_xor_sync(0xffffffffu, m1, 1));
    m1 = fmaxf(m1, __shfl_xor_sync(0xffffffffu, m1, 2));
    float s0 = 0.f, s1 = 0.f;
#pragma unroll
    for (int nt = 0; nt < 7; nt++) {
        acc[nt][0] = __expf(acc[nt][0] - m0); s0 += acc[nt][0];
        acc[nt][1] = __expf(acc[nt][1] - m0); s0 += acc[nt][1];
        acc[nt][2] = __expf(acc[nt][2] - m1); s1 += acc[nt][2];
        acc[nt][3] = __expf(acc[nt][3] - m1); s1 += acc[nt][3];
    }
    s0 += __shfl_xor_sync(0xffffffffu, s0, 1);
    s0 += __shfl_xor_sync(0xffffffffu, s0, 2);
    s1 += __shfl_xor_sync(0xffffffffu, s1, 1);
    s1 += __shfl_xor_sync(0xffffffffu, s1, 2);

    // ---- P -> fp16 single-term A-fragments (cols 56..63 are zero) ----
    uint32_t ph[4][4];
#pragma unroll
    for (int kk = 0; kk < 3; kk++) {
        ph[kk][0] = hpack2(acc[2 * kk][0],     acc[2 * kk][1]);
        ph[kk][1] = hpack2(acc[2 * kk][2],     acc[2 * kk][3]);
        ph[kk][2] = hpack2(acc[2 * kk + 1][0], acc[2 * kk + 1][1]);
        ph[kk][3] = hpack2(acc[2 * kk + 1][2], acc[2 * kk + 1][3]);
    }
    ph[3][0] = hpack2(acc[6][0], acc[6][1]);
    ph[3][1] = hpack2(acc[6][2], acc[6][3]);
    ph[3][2] = 0u;
    ph[3][3] = 0u;

    // ---- O = P @ V (single-term) ----
    float oacc[4][4];
#pragma unroll
    for (int a = 0; a < 4; a++)
#pragma unroll
        for (int c = 0; c < 4; c++) oacc[a][c] = 0.f;
#pragma unroll
    for (int kkp = 0; kkp < 4; kkp += 2) {
        uint32_t vh4[2][2][4];
#pragma unroll
        for (int j = 0; j < 2; j++)
#pragma unroll
            for (int d2 = 0; d2 < 2; d2++) {
                const uint32_t rv = sb + TV_H +
                    (uint32_t)((kkp + j) * 16 + (lane & 7) + ((lane >> 3) & 1) * 8) * RS +
                    d2 * 32 + ((lane >> 4) & 1) * 16;
                LDSM4T(vh4[j][d2], rv);
            }
#pragma unroll
        for (int j = 0; j < 2; j++)
#pragma unroll
            for (int d2 = 0; d2 < 2; d2++) {
                MMA_F16(oacc[2 * d2],     ph[kkp + j], vh4[j][d2][0], vh4[j][d2][1]);
                MMA_F16(oacc[2 * d2 + 1], ph[kkp + j], vh4[j][d2][2], vh4[j][d2][3]);
            }
    }

    // ---- normalize + write ----
    const float inv0 = 1.f / s0, inv1 = 1.f / s1;
    if (r0 < SEQ) {
        __half* orow = out_h + (size_t)(b * SEQ + r0) * CDIM + h * HD + cb;
#pragma unroll
        for (int dt = 0; dt < 4; dt++) {
            __half2 o = __floats2half2_rn(oacc[dt][0] * inv0, oacc[dt][1] * inv0);
            *(__half2*)(orow + dt * 8) = o;
        }
    }
    if (r0 + 8 < SEQ) {
        __half* orow = out_h + (size_t)(b * SEQ + r0 + 8) * CDIM + h * HD + cb;
#pragma unroll
        for (int dt = 0; dt < 4; dt++) {
            __half2 o = __floats2half2_rn(oacc[dt][2] * inv1, oacc[dt][3] * inv1);
            *(__half2*)(orow + dt * 8) = o;
        }
    }
}

// ---------------------------------------------------------------------------
extern "C" void kernel_launch(void* const* d_in, const int* in_sizes, int n_in,
                              void* d_out, int out_size)
{
    const float* x      = (const float*)d_in[0];
    const float* mask   = (const float*)d_in[1];
    const float* qkv_w  = (const float*)d_in[2];
    const float* qkv_b  = (const float*)d_in[3];
    const float* proj_w = (const float*)d_in[4];
    const float* proj_b = (const float*)d_in[5];
    const float* table  = (const float*)d_in[6];
    const int*   idx    = (const int*)d_in[7];
    float* out = (float*)d_out;

    float *qkv_s, *cmb_s;
    __half *xh, *ath, *qwh, *pwh;
    cudaGetSymbolAddress((void**)&qkv_s, g_qkv);
    cudaGetSymbolAddress((void**)&cmb_s, g_cmb);
    cudaGetSymbolAddress((void**)&xh, g_x_h);
    cudaGetSymbolAddress((void**)&ath, g_att_h);
    cudaGetSymbolAddress((void**)&qwh, g_qw_h);
    cudaGetSymbolAddress((void**)&pwh, g_pw_h);

    cudaFuncSetAttribute(gemm_f16, cudaFuncAttributeMaxDynamicSharedMemorySize, GSMEM);

    const int n4 = MROWS * KDIM / 4;
    fconv<<<(n4 + 255) / 256, 256>>>((const float4*)x, (uint2*)xh, n4);
    wconv<<<dim3(1536 / 32, 512 / 32), dim3(32, 8)>>>(qkv_w, qwh, 512, 1536);
    wconv<<<dim3(512 / 32, 512 / 32), dim3(32, 8)>>>(proj_w, pwh, 512, 512);
    cmb_prep<<<dim3(NW, NH), 256>>>(mask, table, idx, cmb_s);

    gemm_f16<<<dim3(1536 / 128, MROWS / 128), 256, GSMEM>>>(
        xh, qwh, qkv_b, qkv_s, 1536);

    attn_mma<<<B_WIN * NH, 128>>>(qkv_s, cmb_s, ath);

    gemm_f16<<<dim3(512 / 128, MROWS / 128), 256, GSMEM>>>(
        ath, pwh, proj_b, out, 512);
}

// round 13
// speedup vs baseline: 3.7147x; 1.1064x over previous
#include <cuda_runtime.h>
#include <cuda_fp16.h>
#include <cstdint>
#include <cstddef>

#define B_WIN 4096
#define SEQ   49
#define CDIM  512
#define NH    16
#define HD    32
#define NW    64
#define MROWS (B_WIN * SEQ)      // 200704
#define KDIM  512

// ---------------- device scratch (no cudaMalloc allowed) -------------------
__device__ __half g_x_h[(size_t)MROWS * KDIM];       // x fp16
__device__ __half g_att_h[(size_t)MROWS * KDIM];     // attn out fp16
__device__ __half g_qw_h[1536 * KDIM];               // qkv_w^T fp16 [N,K] (q cols prescaled)
__device__ __half g_pw_h[512 * KDIM];                // proj_w^T fp16 [N,K]
__device__ float  g_qb[1536];                        // qkv bias (q prescaled)
__device__ float  g_cmb[(size_t)NW * NH * 64 * 64];  // (bias+mask)*log2e, padded
// pre-split QKV outputs
__device__ __half g_q_hi[(size_t)MROWS * 512];
__device__ __half g_q_lo[(size_t)MROWS * 512];
__device__ __half g_k_hi[(size_t)MROWS * 512];
__device__ __half g_k_lo[(size_t)MROWS * 512];
__device__ __half g_v_h [(size_t)MROWS * 512];

#define SCALE_Q 0.17677669529663687f      // 32^-0.5
#define LOG2E   1.4426950408889634f
#define SLQ     (SCALE_Q * LOG2E)

// ---------------- helpers (arch-portable PTX: sm_80+ features only) --------
__device__ __forceinline__ uint32_t smem_u32(const void* p) {
    uint32_t a;
    asm("{ .reg .u64 t; cvta.to.shared.u64 t, %1; cvt.u32.u64 %0, t; }"
        : "=r"(a) : "l"(p));
    return a;
}
#define CPA16(dst, src) \
    asm volatile("cp.async.cg.shared.global [%0], [%1], 16;" \
                 :: "r"(dst), "l"(src) : "memory")
#define CPCOMMIT() asm volatile("cp.async.commit_group;" ::: "memory")
#define CPWAIT(n)  asm volatile("cp.async.wait_group %0;" :: "n"(n) : "memory")
#define LDSM4(r, addr)                                                        \
    asm volatile("ldmatrix.sync.aligned.m8n8.x4.shared.b16 {%0,%1,%2,%3}, [%4];" \
        : "=r"((r)[0]), "=r"((r)[1]), "=r"((r)[2]), "=r"((r)[3]) : "r"(addr))
#define LDSM4T(r, addr)                                                       \
    asm volatile("ldmatrix.sync.aligned.m8n8.x4.trans.shared.b16 {%0,%1,%2,%3}, [%4];" \
        : "=r"((r)[0]), "=r"((r)[1]), "=r"((r)[2]), "=r"((r)[3]) : "r"(addr))
#define MMA_F16(d, a, b0, b1)                                                 \
    asm volatile("mma.sync.aligned.m16n8k16.row.col.f32.f16.f16.f32 "         \
        "{%0,%1,%2,%3},{%4,%5,%6,%7},{%8,%9},{%0,%1,%2,%3};"                  \
        : "+f"((d)[0]), "+f"((d)[1]), "+f"((d)[2]), "+f"((d)[3])              \
        : "r"((a)[0]), "r"((a)[1]), "r"((a)[2]), "r"((a)[3]),                 \
          "r"(b0), "r"(b1))

__device__ __forceinline__ void hsplit2(float a, float b, uint32_t& hi, uint32_t& lo) {
    __half2 h = __floats2half2_rn(a, b);
    float2 hf = __half22float2(h);
    __half2 l = __floats2half2_rn(a - hf.x, b - hf.y);
    hi = *(uint32_t*)&h;
    lo = *(uint32_t*)&l;
}
__device__ __forceinline__ uint32_t hpack2(float a, float b) {
    __half2 h = __floats2half2_rn(a, b);
    return *(uint32_t*)&h;
}
__device__ __forceinline__ float ex2(float x) {
    float y;
    asm("ex2.approx.f32 %0, %1;" : "=f"(y) : "f"(x));
    return y;
}

// ---------------------------------------------------------------------------
// prep kernels
// ---------------------------------------------------------------------------
__global__ void fconv(const float4* __restrict__ in, uint2* __restrict__ out, int n4)
{
    const int i = blockIdx.x * blockDim.x + threadIdx.x;
    if (i >= n4) return;
    float4 v = in[i];
    uint2 o = { hpack2(v.x, v.y), hpack2(v.z, v.w) };
    out[i] = o;
}

// W[K,N] fp32 -> B[N,K] fp16, rows n < nscale prescaled
__global__ void wconv(const float* __restrict__ W, __half* __restrict__ Bh,
                      int K, int N, float scale, int nscale)
{
    __shared__ float t[32][33];
    const int bx = blockIdx.x, by = blockIdx.y;
    const int x = threadIdx.x, y = threadIdx.y;   // 32 x 8
#pragma unroll
    for (int i = 0; i < 4; i++)
        t[y + i * 8][x] = W[(size_t)(by * 32 + y + i * 8) * N + bx * 32 + x];
    __syncthreads();
#pragma unroll
    for (int i = 0; i < 4; i++) {
        const int n = bx * 32 + y + i * 8;
        float v = t[x][y + i * 8];
        if (n < nscale) v *= scale;
        Bh[(size_t)n * K + by * 32 + x] = __float2half_rn(v);
    }
}

__global__ void bprep(const float* __restrict__ b, float* __restrict__ o)
{
    const int i = blockIdx.x * blockDim.x + threadIdx.x;
    if (i < 1536) o[i] = b[i] * (i < 512 ? SLQ : 1.f);
}

// cmb[w][h][n][m] = (bias+mask)*log2e, pad cols = -1e9, pad rows = 0
__global__ void cmb_prep(const float* __restrict__ mask, const float* __restrict__ table,
                         const int* __restrict__ idx, float* __restrict__ cmb)
{
    const int w = blockIdx.x, h = blockIdx.y;
    float* dst = cmb + (((size_t)w * NH + h) << 12);
    for (int i = threadIdx.x; i < 4096; i += 256) {
        const int n = i >> 6, m = i & 63;
        float v;
        if (m >= SEQ)      v = -1e9f;
        else if (n >= SEQ) v = 0.f;
        else v = (table[idx[n * SEQ + m] * NH + h] +
                  mask[(size_t)w * SEQ * SEQ + n * SEQ + m]) * LOG2E;
        dst[i] = v;
    }
}

// ---------------------------------------------------------------------------
// fp16 mma.sync GEMM (R11 structure, at HMMA path roofline).
// MODE 0: C fp32 + bias (proj).  MODE 1: QKV split epilogue.
// ---------------------------------------------------------------------------
#define RS        80
#define AT_BYTES  (128 * RS)
#define STAGE     (2 * AT_BYTES)
#define NSTAGE    3
#define GSMEM     (NSTAGE * STAGE)     // 61440

template<int MODE>
__global__ __launch_bounds__(256, 2)
void gemm_f16(const __half* __restrict__ A_g,
              const __half* __restrict__ B_g,
              const float* __restrict__ bias, float* __restrict__ C,
              uint32_t* __restrict__ qh_g, uint32_t* __restrict__ ql_g,
              uint32_t* __restrict__ kh_g, uint32_t* __restrict__ kl_g,
              uint32_t* __restrict__ vh_g, int Ntot)
{
    extern __shared__ __align__(128) char sm[];
    const uint32_t sb = smem_u32(sm);
    const int tid = threadIdx.x;
    const int lane = tid & 31, wid = tid >> 5;
    const int m0 = blockIdx.y * 128, n0 = blockIdx.x * 128;
    const int wm = (wid >> 2) * 64, wn = (wid & 3) * 32;

    const int crow = tid >> 1;
    const int cc   = (tid & 1) * 32;

    const char* gsrc0 = (const char*)(A_g + (size_t)m0 * KDIM);
    const char* gsrc1 = (const char*)(B_g + (size_t)n0 * KDIM);

    float acc[4][4][4];
#pragma unroll
    for (int a = 0; a < 4; a++)
#pragma unroll
        for (int b = 0; b < 4; b++)
#pragma unroll
            for (int c = 0; c < 4; c++) acc[a][b][c] = 0.f;

    auto issue = [&](int s, int kc) {
        const int gofs = crow * 1024 + kc * 64 + cc;
        const uint32_t dst = sb + s * STAGE + crow * RS + cc;
        CPA16(dst,                 gsrc0 + gofs);
        CPA16(dst + 16,            gsrc0 + gofs + 16);
        CPA16(dst + AT_BYTES,      gsrc1 + gofs);
        CPA16(dst + AT_BYTES + 16, gsrc1 + gofs + 16);
        CPCOMMIT();
    };

    issue(0, 0);
    issue(1, 1);

    const int r = lane & 15;
    const uint32_t khalf = (lane >> 4) * 16;

    for (int kc = 0; kc < 16; kc++) {
        const int s = kc % NSTAGE;
        if (kc < 15) { CPWAIT(1); } else { CPWAIT(0); }
        __syncthreads();
        if (kc + 2 < 16) issue((kc + 2) % NSTAGE, kc + 2);

        const uint32_t base = sb + s * STAGE;
#pragma unroll
        for (int kk = 0; kk < 2; kk++) {
            const uint32_t ko = kk * 32 + khalf;
            uint32_t ah[4][4], bh[2][4];
#pragma unroll
            for (int mt = 0; mt < 4; mt++) {
                const uint32_t ra = base + (uint32_t)(wm + mt * 16 + r) * RS + ko;
                LDSM4(ah[mt], ra);
            }
#pragma unroll
            for (int p = 0; p < 2; p++) {
                const uint32_t rb = base + AT_BYTES +
                                    (uint32_t)(wn + p * 16 + r) * RS + ko;
                LDSM4(bh[p], rb);
            }
#pragma unroll
            for (int mt = 0; mt < 4; mt++)
#pragma unroll
                for (int nt = 0; nt < 4; nt++) {
                    const int p = nt >> 1, o = nt & 1;
                    MMA_F16(acc[mt][nt], ah[mt], bh[p][o], bh[p][o + 2]);
                }
        }
    }

    // ---- epilogue ----
    if (MODE == 0) {
#pragma unroll
        for (int mt = 0; mt < 4; mt++) {
            const int gr = m0 + wm + mt * 16 + (lane >> 2);
#pragma unroll
            for (int nt = 0; nt < 4; nt++) {
                const int gc = n0 + wn + nt * 8 + (lane & 3) * 2;
                const float b0 = bias[gc], b1 = bias[gc + 1];
                float2 v0 = { acc[mt][nt][0] + b0, acc[mt][nt][1] + b1 };
                float2 v1 = { acc[mt][nt][2] + b0, acc[mt][nt][3] + b1 };
                *(float2*)&C[(size_t)gr * Ntot + gc] = v0;
                *(float2*)&C[(size_t)(gr + 8) * Ntot + gc] = v1;
            }
        }
    } else {
        const int t = n0 >> 9;                 // 0=q, 1=k, 2=v (uniform per CTA)
        uint32_t* hi_g = (t == 0) ? qh_g : kh_g;
        uint32_t* lo_g = (t == 0) ? ql_g : kl_g;
#pragma unroll
        for (int mt = 0; mt < 4; mt++) {
            const int gr = m0 + wm + mt * 16 + (lane >> 2);
#pragma unroll
            for (int nt = 0; nt < 4; nt++) {
                const int gc = n0 + wn + nt * 8 + (lane & 3) * 2;
                const int lc = gc & 511;
                const float b0 = bias[gc], b1 = bias[gc + 1];
                const float a0 = acc[mt][nt][0] + b0, a1 = acc[mt][nt][1] + b1;
                const float a2 = acc[mt][nt][2] + b0, a3 = acc[mt][nt][3] + b1;
                const size_t i0 = ((size_t)gr * 512 + lc) >> 1;
                const size_t i1 = ((size_t)(gr + 8) * 512 + lc) >> 1;
                if (t == 2) {
                    vh_g[i0] = hpack2(a0, a1);
                    vh_g[i1] = hpack2(a2, a3);
                } else {
                    uint32_t H, L;
                    hsplit2(a0, a1, H, L);
                    hi_g[i0] = H; lo_g[i0] = L;
                    hsplit2(a2, a3, H, L);
                    hi_g[i1] = H; lo_g[i1] = L;
                }
            }
        }
    }
}

// ---------------------------------------------------------------------------
// Tensor-core window attention, pre-split inputs, log2-domain softmax.
// smem: QH 0, QL 5120, KH 10240, KL 15360, VH 20480 (64 rows x 80B each)
// ---------------------------------------------------------------------------
#define TQ_H 0
#define TK_H 10240
#define TV_H 20480
#define ASMEM 25600

__global__ __launch_bounds__(128)
void attn_mma(const char* __restrict__ qh_g, const char* __restrict__ ql_g,
              const char* __restrict__ kh_g, const char* __restrict__ kl_g,
              const char* __restrict__ vh_g,
              const float* __restrict__ cmb, __half* __restrict__ out_h)
{
    const int bh = blockIdx.x;
    const int b = bh >> 4, h = bh & 15;
    const int tid = threadIdx.x;
    const int lane = tid & 31, wq = tid >> 5;

    __shared__ __align__(16) char smem[ASMEM];
    const uint32_t sb = smem_u32(smem);

    // zero pad rows 49..63 of all 5 arrays (5 arrays x 15 rows x 5 chunks)
    for (int i = tid; i < 375; i += 128) {
        const int t = i / 75, rem = i - t * 75;
        const int row = 49 + rem / 5, c = (rem - (rem / 5) * 5) * 16;
        *(uint4*)(smem + t * 5120 + row * 80 + c) = make_uint4(0, 0, 0, 0);
    }

    // cp.async staging: rows 0..48, 64B per row, per array
    const size_t rbase = (size_t)b * SEQ * 1024 + h * 64;   // bytes
    const char* gsrc[5] = { qh_g + rbase, ql_g + rbase, kh_g + rbase,
                            kl_g + rbase, vh_g + rbase };
#pragma unroll
    for (int t = 0; t < 5; t++) {
        {
            const int row = tid >> 2, c = (tid & 3) * 16;
            CPA16(sb + t * 5120 + row * 80 + c, gsrc[t] + (size_t)row * 1024 + c);
        }
        const int i = tid + 128;
        if (i < 196) {
            const int row = i >> 2, c = (i & 3) * 16;
            CPA16(sb + t * 5120 + row * 80 + c, gsrc[t] + (size_t)row * 1024 + c);
        }
    }
    CPCOMMIT();

    // ---- acc init from cmb (overlaps the cp.async) ----
    const int r0 = wq * 16 + (lane >> 2);
    const int cb = (lane & 3) * 2;
    float acc[7][4];
    const float* cw = cmb + (((size_t)(b & (NW - 1)) * NH + h) << 12);
#pragma unroll
    for (int nt = 0; nt < 7; nt++) {
        float2 v0 = *(const float2*)(cw + r0 * 64 + nt * 8 + cb);
        float2 v1 = *(const float2*)(cw + (r0 + 8) * 64 + nt * 8 + cb);
        acc[nt][0] = v0.x; acc[nt][1] = v0.y;
        acc[nt][2] = v1.x; acc[nt][3] = v1.y;
    }

    CPWAIT(0);
    __syncthreads();

    // ---- scores: 3-term QK^T (nt 0..6) ----
    uint32_t qh[2][4], ql[2][4];
#pragma unroll
    for (int kt = 0; kt < 2; kt++) {
        const uint32_t ra = sb + TQ_H + (uint32_t)(wq * 16 + (lane & 15)) * RS +
                            kt * 32 + (lane >> 4) * 16;
        LDSM4(qh[kt], ra);
        LDSM4(ql[kt], ra + 5120);
    }
#pragma unroll
    for (int kt = 0; kt < 2; kt++)
#pragma unroll
        for (int t2p = 0; t2p < 4; t2p += 2) {
            uint32_t kh4[2][4], kl4[2][4];
#pragma unroll
            for (int j = 0; j < 2; j++) {
                const uint32_t rk = sb + TK_H +
                    (uint32_t)((t2p + j) * 16 + (lane & 7) + ((lane >> 4) & 1) * 8) * RS +
                    kt * 32 + ((lane >> 3) & 1) * 16;
                LDSM4(kh4[j], rk);
                LDSM4(kl4[j], rk + 5120);
            }
#pragma unroll
            for (int j = 0; j < 2; j++) {
                MMA_F16(acc[2 * (t2p + j)], qh[kt], kh4[j][0], kh4[j][1]);
                if (t2p + j < 3)
                    MMA_F16(acc[2 * (t2p + j) + 1], qh[kt], kh4[j][2], kh4[j][3]);
            }
#pragma unroll
            for (int j = 0; j < 2; j++) {
                MMA_F16(acc[2 * (t2p + j)], qh[kt], kl4[j][0], kl4[j][1]);
                if (t2p + j < 3)
                    MMA_F16(acc[2 * (t2p + j) + 1], qh[kt], kl4[j][2], kl4[j][3]);
            }
#pragma unroll
            for (int j = 0; j < 2; j++) {
                MMA_F16(acc[2 * (t2p + j)], ql[kt], kh4[j][0], kh4[j][1]);
                if (t2p + j < 3)
                    MMA_F16(acc[2 * (t2p + j) + 1], ql[kt], kh4[j][2], kh4[j][3]);
            }
        }

    // ---- fragment softmax (log2 domain, unnormalized) ----
    float m0 = -1e30f, m1 = -1e30f;
#pragma unroll
    for (int nt = 0; nt < 7; nt++) {
        m0 = fmaxf(m0, fmaxf(acc[nt][0], acc[nt][1]));
        m1 = fmaxf(m1, fmaxf(acc[nt][2], acc[nt][3]));
    }
    m0 = fmaxf(m0, __shfl_xor_sync(0xffffffffu, m0, 1));
    m0 = fmaxf(m0, __shfl_xor_sync(0xffffffffu, m0, 2));
    m1 = fmaxf(m1, __shfl_xor_sync(0xffffffffu, m1, 1));
    m1 = fmaxf(m1, __shfl_xor_sync(0xffffffffu, m1, 2));
    float s0 = 0.f, s1 = 0.f;
#pragma unroll
    for (int nt = 0; nt < 7; nt++) {
        acc[nt][0] = ex2(acc[nt][0] - m0); s0 += acc[nt][0];
        acc[nt][1] = ex2(acc[nt][1] - m0); s0 += acc[nt][1];
        acc[nt][2] = ex2(acc[nt][2] - m1); s1 += acc[nt][2];
        acc[nt][3] = ex2(acc[nt][3] - m1); s1 += acc[nt][3];
    }
    s0 += __shfl_xor_sync(0xffffffffu, s0, 1);
    s0 += __shfl_xor_sync(0xffffffffu, s0, 2);
    s1 += __shfl_xor_sync(0xffffffffu, s1, 1);
    s1 += __shfl_xor_sync(0xffffffffu, s1, 2);

    // ---- P -> fp16 single-term fragments ----
    uint32_t ph[4][4];
#pragma unroll
    for (int kk = 0; kk < 3; kk++) {
        ph[kk][0] = hpack2(acc[2 * kk][0],     acc[2 * kk][1]);
        ph[kk][1] = hpack2(acc[2 * kk][2],     acc[2 * kk][3]);
        ph[kk][2] = hpack2(acc[2 * kk + 1][0], acc[2 * kk + 1][1]);
        ph[kk][3] = hpack2(acc[2 * kk + 1][2], acc[2 * kk + 1][3]);
    }
    ph[3][0] = hpack2(acc[6][0], acc[6][1]);
    ph[3][1] = hpack2(acc[6][2], acc[6][3]);
    ph[3][2] = 0u;
    ph[3][3] = 0u;

    // ---- O = P @ V (single-term) ----
    float oacc[4][4];
#pragma unroll
    for (int a = 0; a < 4; a++)
#pragma unroll
        for (int c = 0; c < 4; c++) oacc[a][c] = 0.f;
#pragma unroll
    for (int kkp = 0; kkp < 4; kkp += 2) {
        uint32_t vh4[2][2][4];
#pragma unroll
        for (int j = 0; j < 2; j++)
#pragma unroll
            for (int d2 = 0; d2 < 2; d2++) {
                const uint32_t rv = sb + TV_H +
                    (uint32_t)((kkp + j) * 16 + (lane & 7) + ((lane >> 3) & 1) * 8) * RS +
                    d2 * 32 + ((lane >> 4) & 1) * 16;
                LDSM4T(vh4[j][d2], rv);
            }
#pragma unroll
        for (int j = 0; j < 2; j++)
#pragma unroll
            for (int d2 = 0; d2 < 2; d2++) {
                MMA_F16(oacc[2 * d2],     ph[kkp + j], vh4[j][d2][0], vh4[j][d2][1]);
                MMA_F16(oacc[2 * d2 + 1], ph[kkp + j], vh4[j][d2][2], vh4[j][d2][3]);
            }
    }

    // ---- normalize + write ----
    const float inv0 = 1.f / s0, inv1 = 1.f / s1;
    if (r0 < SEQ) {
        __half* orow = out_h + (size_t)(b * SEQ + r0) * CDIM + h * HD + cb;
#pragma unroll
        for (int dt = 0; dt < 4; dt++) {
            __half2 o = __floats2half2_rn(oacc[dt][0] * inv0, oacc[dt][1] * inv0);
            *(__half2*)(orow + dt * 8) = o;
        }
    }
    if (r0 + 8 < SEQ) {
        __half* orow = out_h + (size_t)(b * SEQ + r0 + 8) * CDIM + h * HD + cb;
#pragma unroll
        for (int dt = 0; dt < 4; dt++) {
            __half2 o = __floats2half2_rn(oacc[dt][2] * inv1, oacc[dt][3] * inv1);
            *(__half2*)(orow + dt * 8) = o;
        }
    }
}

// ---------------------------------------------------------------------------
extern "C" void kernel_launch(void* const* d_in, const int* in_sizes, int n_in,
                              void* d_out, int out_size)
{
    const float* x      = (const float*)d_in[0];
    const float* mask   = (const float*)d_in[1];
    const float* qkv_w  = (const float*)d_in[2];
    const float* qkv_b  = (const float*)d_in[3];
    const float* proj_w = (const float*)d_in[4];
    const float* proj_b = (const float*)d_in[5];
    const float* table  = (const float*)d_in[6];
    const int*   idx    = (const int*)d_in[7];
    float* out = (float*)d_out;

    float *cmb_s, *qb_s;
    __half *xh, *ath, *qwh, *pwh, *qhi, *qlo, *khi, *klo, *vh;
    cudaGetSymbolAddress((void**)&cmb_s, g_cmb);
    cudaGetSymbolAddress((void**)&qb_s, g_qb);
    cudaGetSymbolAddress((void**)&xh, g_x_h);
    cudaGetSymbolAddress((void**)&ath, g_att_h);
    cudaGetSymbolAddress((void**)&qwh, g_qw_h);
    cudaGetSymbolAddress((void**)&pwh, g_pw_h);
    cudaGetSymbolAddress((void**)&qhi, g_q_hi);
    cudaGetSymbolAddress((void**)&qlo, g_q_lo);
    cudaGetSymbolAddress((void**)&khi, g_k_hi);
    cudaGetSymbolAddress((void**)&klo, g_k_lo);
    cudaGetSymbolAddress((void**)&vh, g_v_h);

    cudaFuncSetAttribute(gemm_f16<0>, cudaFuncAttributeMaxDynamicSharedMemorySize, GSMEM);
    cudaFuncSetAttribute(gemm_f16<1>, cudaFuncAttributeMaxDynamicSharedMemorySize, GSMEM);

    const int n4 = MROWS * KDIM / 4;
    fconv<<<(n4 + 255) / 256, 256>>>((const float4*)x, (uint2*)xh, n4);
    wconv<<<dim3(1536 / 32, 512 / 32), dim3(32, 8)>>>(qkv_w, qwh, 512, 1536, SLQ, 512);
    wconv<<<dim3(512 / 32, 512 / 32), dim3(32, 8)>>>(proj_w, pwh, 512, 512, 1.f, 0);
    bprep<<<6, 256>>>(qkv_b, qb_s);
    cmb_prep<<<dim3(NW, NH), 256>>>(mask, table, idx, cmb_s);

    // 1) QKV projection, split epilogue
    gemm_f16<1><<<dim3(1536 / 128, MROWS / 128), 256, GSMEM>>>(
        xh, qwh, qb_s, nullptr,
        (uint32_t*)qhi, (uint32_t*)qlo, (uint32_t*)khi, (uint32_t*)klo,
        (uint32_t*)vh, 1536);

    // 2) tensor-core window attention
    attn_mma<<<B_WIN * NH, 128>>>((const char*)qhi, (const char*)qlo,
                                  (const char*)khi, (const char*)klo,
                                  (const char*)vh, cmb_s, ath);

    // 3) output projection
    gemm_f16<0><<<dim3(512 / 128, MROWS / 128), 256, GSMEM>>>(
        ath, pwh, proj_b, out,
        nullptr, nullptr, nullptr, nullptr, nullptr, 512);
}

// round 16
// speedup vs baseline: 4.0003x; 1.0769x over previous
#include <cuda_runtime.h>
#include <cuda_fp16.h>
#include <cstdint>
#include <cstddef>

#define B_WIN 4096
#define SEQ   49
#define CDIM  512
#define NH    16
#define HD    32
#define NW    64
#define MROWS (B_WIN * SEQ)      // 200704
#define KDIM  512

// ---------------- device scratch (no cudaMalloc allowed) -------------------
__device__ __half g_x_h[(size_t)MROWS * KDIM];       // x fp16
__device__ __half g_att_h[(size_t)MROWS * KDIM];     // attn out fp16
__device__ __half g_qw_h[1536 * KDIM];               // qkv_w^T fp16 [N,K] (q cols prescaled)
__device__ __half g_pw_h[512 * KDIM];                // proj_w^T fp16 [N,K]
__device__ float  g_qb[1536];                        // qkv bias (q prescaled)
__device__ float  g_cmb[(size_t)NW * NH * 64 * 64];  // (bias+mask)*log2e, padded
// QKV outputs, single fp16 each
__device__ __half g_q_h[(size_t)MROWS * 512];
__device__ __half g_k_h[(size_t)MROWS * 512];
__device__ __half g_v_h[(size_t)MROWS * 512];

#define SCALE_Q 0.17677669529663687f      // 32^-0.5
#define LOG2E   1.4426950408889634f
#define SLQ     (SCALE_Q * LOG2E)

// ---------------- helpers (arch-portable PTX: sm_80+ features only) --------
__device__ __forceinline__ uint32_t smem_u32(const void* p) {
    uint32_t a;
    asm("{ .reg .u64 t; cvta.to.shared.u64 t, %1; cvt.u32.u64 %0, t; }"
        : "=r"(a) : "l"(p));
    return a;
}
#define CPA16(dst, src) \
    asm volatile("cp.async.cg.shared.global [%0], [%1], 16;" \
                 :: "r"(dst), "l"(src) : "memory")
#define CPCOMMIT() asm volatile("cp.async.commit_group;" ::: "memory")
#define CPWAIT(n)  asm volatile("cp.async.wait_group %0;" :: "n"(n) : "memory")
#define LDSM4(r, addr)                                                        \
    asm volatile("ldmatrix.sync.aligned.m8n8.x4.shared.b16 {%0,%1,%2,%3}, [%4];" \
        : "=r"((r)[0]), "=r"((r)[1]), "=r"((r)[2]), "=r"((r)[3]) : "r"(addr))
#define LDSM4T(r, addr)                                                       \
    asm volatile("ldmatrix.sync.aligned.m8n8.x4.trans.shared.b16 {%0,%1,%2,%3}, [%4];" \
        : "=r"((r)[0]), "=r"((r)[1]), "=r"((r)[2]), "=r"((r)[3]) : "r"(addr))
#define MMA_F16(d, a, b0, b1)                                                 \
    asm volatile("mma.sync.aligned.m16n8k16.row.col.f32.f16.f16.f32 "         \
        "{%0,%1,%2,%3},{%4,%5,%6,%7},{%8,%9},{%0,%1,%2,%3};"                  \
        : "+f"((d)[0]), "+f"((d)[1]), "+f"((d)[2]), "+f"((d)[3])              \
        : "r"((a)[0]), "r"((a)[1]), "r"((a)[2]), "r"((a)[3]),                 \
          "r"(b0), "r"(b1))

__device__ __forceinline__ uint32_t hpack2(float a, float b) {
    __half2 h = __floats2half2_rn(a, b);
    return *(uint32_t*)&h;
}
__device__ __forceinline__ float ex2(float x) {
    float y;
    asm("ex2.approx.f32 %0, %1;" : "=f"(y) : "f"(x));
    return y;
}

// ---------------------------------------------------------------------------
// prep kernels
// ---------------------------------------------------------------------------
__global__ void fconv(const float4* __restrict__ in, uint2* __restrict__ out, int n4)
{
    const int i = blockIdx.x * blockDim.x + threadIdx.x;
    if (i >= n4) return;
    float4 v = in[i];
    uint2 o = { hpack2(v.x, v.y), hpack2(v.z, v.w) };
    out[i] = o;
}

// W[K,N] fp32 -> B[N,K] fp16, rows n < nscale prescaled
__global__ void wconv(const float* __restrict__ W, __half* __restrict__ Bh,
                      int K, int N, float scale, int nscale)
{
    __shared__ float t[32][33];
    const int bx = blockIdx.x, by = blockIdx.y;
    const int x = threadIdx.x, y = threadIdx.y;   // 32 x 8
#pragma unroll
    for (int i = 0; i < 4; i++)
        t[y + i * 8][x] = W[(size_t)(by * 32 + y + i * 8) * N + bx * 32 + x];
    __syncthreads();
#pragma unroll
    for (int i = 0; i < 4; i++) {
        const int n = bx * 32 + y + i * 8;
        float v = t[x][y + i * 8];
        if (n < nscale) v *= scale;
        Bh[(size_t)n * K + by * 32 + x] = __float2half_rn(v);
    }
}

__global__ void bprep(const float* __restrict__ b, float* __restrict__ o)
{
    const int i = blockIdx.x * blockDim.x + threadIdx.x;
    if (i < 1536) o[i] = b[i] * (i < 512 ? SLQ : 1.f);
}

// cmb[w][h][n][m] = (bias+mask)*log2e, pad cols = -1e9, pad rows = 0
__global__ void cmb_prep(const float* __restrict__ mask, const float* __restrict__ table,
                         const int* __restrict__ idx, float* __restrict__ cmb)
{
    const int w = blockIdx.x, h = blockIdx.y;
    float* dst = cmb + (((size_t)w * NH + h) << 12);
    for (int i = threadIdx.x; i < 4096; i += 256) {
        const int n = i >> 6, m = i & 63;
        float v;
        if (m >= SEQ)      v = -1e9f;
        else if (n >= SEQ) v = 0.f;
        else v = (table[idx[n * SEQ + m] * NH + h] +
                  mask[(size_t)w * SEQ * SEQ + n * SEQ + m]) * LOG2E;
        dst[i] = v;
    }
}

// ---------------------------------------------------------------------------
// fp16 mma.sync GEMM (at HMMA path roofline).
// MODE 0: C fp32 + bias (proj).  MODE 1: QKV fp16 epilogue into q/k/v arrays.
// ---------------------------------------------------------------------------
#define RS        80
#define AT_BYTES  (128 * RS)
#define STAGE     (2 * AT_BYTES)
#define NSTAGE    3
#define GSMEM     (NSTAGE * STAGE)     // 61440

template<int MODE>
__global__ __launch_bounds__(256, 2)
void gemm_f16(const __half* __restrict__ A_g,
              const __half* __restrict__ B_g,
              const float* __restrict__ bias, float* __restrict__ C,
              uint32_t* __restrict__ qh_g, uint32_t* __restrict__ kh_g,
              uint32_t* __restrict__ vh_g, int Ntot)
{
    extern __shared__ __align__(128) char sm[];
    const uint32_t sb = smem_u32(sm);
    const int tid = threadIdx.x;
    const int lane = tid & 31, wid = tid >> 5;
    const int m0 = blockIdx.y * 128, n0 = blockIdx.x * 128;
    const int wm = (wid >> 2) * 64, wn = (wid & 3) * 32;

    const int crow = tid >> 1;
    const int cc   = (tid & 1) * 32;

    const char* gsrc0 = (const char*)(A_g + (size_t)m0 * KDIM);
    const char* gsrc1 = (const char*)(B_g + (size_t)n0 * KDIM);

    float acc[4][4][4];
#pragma unroll
    for (int a = 0; a < 4; a++)
#pragma unroll
        for (int b = 0; b < 4; b++)
#pragma unroll
            for (int c = 0; c < 4; c++) acc[a][b][c] = 0.f;

    auto issue = [&](int s, int kc) {
        const int gofs = crow * 1024 + kc * 64 + cc;
        const uint32_t dst = sb + s * STAGE + crow * RS + cc;
        CPA16(dst,                 gsrc0 + gofs);
        CPA16(dst + 16,            gsrc0 + gofs + 16);
        CPA16(dst + AT_BYTES,      gsrc1 + gofs);
        CPA16(dst + AT_BYTES + 16, gsrc1 + gofs + 16);
        CPCOMMIT();
    };

    issue(0, 0);
    issue(1, 1);

    const int r = lane & 15;
    const uint32_t khalf = (lane >> 4) * 16;

    for (int kc = 0; kc < 16; kc++) {
        const int s = kc % NSTAGE;
        if (kc < 15) { CPWAIT(1); } else { CPWAIT(0); }
        __syncthreads();
        if (kc + 2 < 16) issue((kc + 2) % NSTAGE, kc + 2);

        const uint32_t base = sb + s * STAGE;
#pragma unroll
        for (int kk = 0; kk < 2; kk++) {
            const uint32_t ko = kk * 32 + khalf;
            uint32_t ah[4][4], bh[2][4];
#pragma unroll
            for (int mt = 0; mt < 4; mt++) {
                const uint32_t ra = base + (uint32_t)(wm + mt * 16 + r) * RS + ko;
                LDSM4(ah[mt], ra);
            }
#pragma unroll
            for (int p = 0; p < 2; p++) {
                const uint32_t rb = base + AT_BYTES +
                                    (uint32_t)(wn + p * 16 + r) * RS + ko;
                LDSM4(bh[p], rb);
            }
#pragma unroll
            for (int mt = 0; mt < 4; mt++)
#pragma unroll
                for (int nt = 0; nt < 4; nt++) {
                    const int p = nt >> 1, o = nt & 1;
                    MMA_F16(acc[mt][nt], ah[mt], bh[p][o], bh[p][o + 2]);
                }
        }
    }

    // ---- epilogue ----
    if (MODE == 0) {
#pragma unroll
        for (int mt = 0; mt < 4; mt++) {
            const int gr = m0 + wm + mt * 16 + (lane >> 2);
#pragma unroll
            for (int nt = 0; nt < 4; nt++) {
                const int gc = n0 + wn + nt * 8 + (lane & 3) * 2;
                const float b0 = bias[gc], b1 = bias[gc + 1];
                float2 v0 = { acc[mt][nt][0] + b0, acc[mt][nt][1] + b1 };
                float2 v1 = { acc[mt][nt][2] + b0, acc[mt][nt][3] + b1 };
                *(float2*)&C[(size_t)gr * Ntot + gc] = v0;
                *(float2*)&C[(size_t)(gr + 8) * Ntot + gc] = v1;
            }
        }
    } else {
        const int t = n0 >> 9;                 // 0=q, 1=k, 2=v (uniform per CTA)
        uint32_t* dst_g = (t == 0) ? qh_g : (t == 1) ? kh_g : vh_g;
#pragma unroll
        for (int mt = 0; mt < 4; mt++) {
            const int gr = m0 + wm + mt * 16 + (lane >> 2);
#pragma unroll
            for (int nt = 0; nt < 4; nt++) {
                const int gc = n0 + wn + nt * 8 + (lane & 3) * 2;
                const int lc = gc & 511;
                const float b0 = bias[gc], b1 = bias[gc + 1];
                dst_g[((size_t)gr * 512 + lc) >> 1] =
                    hpack2(acc[mt][nt][0] + b0, acc[mt][nt][1] + b1);
                dst_g[((size_t)(gr + 8) * 512 + lc) >> 1] =
                    hpack2(acc[mt][nt][2] + b0, acc[mt][nt][3] + b1);
            }
        }
    }
}

// ---------------------------------------------------------------------------
// Tensor-core window attention, single-term fp16 q/k/v, log2-domain softmax.
// smem: Q 0, K 5120, V 10240 (64 rows x 80B each)
// ---------------------------------------------------------------------------
#define TQ_H 0
#define TK_H 5120
#define TV_H 10240
#define ASMEM 15360

__global__ __launch_bounds__(128)
void attn_mma(const char* __restrict__ q_g, const char* __restrict__ k_g,
              const char* __restrict__ v_g,
              const float* __restrict__ cmb, __half* __restrict__ out_h)
{
    const int bh = blockIdx.x;
    const int b = bh >> 4, h = bh & 15;
    const int tid = threadIdx.x;
    const int lane = tid & 31, wq = tid >> 5;

    __shared__ __align__(16) char smem[ASMEM];
    const uint32_t sb = smem_u32(smem);

    // zero pad rows 49..63 of all 3 arrays (3 x 15 rows x 5 chunks = 225)
    for (int i = tid; i < 225; i += 128) {
        const int t = i / 75, rem = i - t * 75;
        const int row = 49 + rem / 5, c = (rem - (rem / 5) * 5) * 16;
        *(uint4*)(smem + t * 5120 + row * 80 + c) = make_uint4(0, 0, 0, 0);
    }

    // cp.async staging: rows 0..48, 64B per row, per array
    const size_t rbase = (size_t)b * SEQ * 1024 + h * 64;   // bytes
    const char* gsrc[3] = { q_g + rbase, k_g + rbase, v_g + rbase };
#pragma unroll
    for (int t = 0; t < 3; t++) {
        {
            const int row = tid >> 2, c = (tid & 3) * 16;
            CPA16(sb + t * 5120 + row * 80 + c, gsrc[t] + (size_t)row * 1024 + c);
        }
        const int i = tid + 128;
        if (i < 196) {
            const int row = i >> 2, c = (i & 3) * 16;
            CPA16(sb + t * 5120 + row * 80 + c, gsrc[t] + (size_t)row * 1024 + c);
        }
    }
    CPCOMMIT();

    // ---- acc init from cmb (overlaps the cp.async) ----
    const int r0 = wq * 16 + (lane >> 2);
    const int cb = (lane & 3) * 2;
    float acc[7][4];
    const float* cw = cmb + (((size_t)(b & (NW - 1)) * NH + h) << 12);
#pragma unroll
    for (int nt = 0; nt < 7; nt++) {
        float2 v0 = *(const float2*)(cw + r0 * 64 + nt * 8 + cb);
        float2 v1 = *(const float2*)(cw + (r0 + 8) * 64 + nt * 8 + cb);
        acc[nt][0] = v0.x; acc[nt][1] = v0.y;
        acc[nt][2] = v1.x; acc[nt][3] = v1.y;
    }

    CPWAIT(0);
    __syncthreads();

    // ---- scores: single-term QK^T (nt 0..6) ----
    uint32_t qh[2][4];
#pragma unroll
    for (int kt = 0; kt < 2; kt++) {
        const uint32_t ra = sb + TQ_H + (uint32_t)(wq * 16 + (lane & 15)) * RS +
                            kt * 32 + (lane >> 4) * 16;
        LDSM4(qh[kt], ra);
    }
#pragma unroll
    for (int kt = 0; kt < 2; kt++)
#pragma unroll
        for (int t2p = 0; t2p < 4; t2p += 2) {
            uint32_t kh4[2][4];
#pragma unroll
            for (int j = 0; j < 2; j++) {
                const uint32_t rk = sb + TK_H +
                    (uint32_t)((t2p + j) * 16 + (lane & 7) + ((lane >> 4) & 1) * 8) * RS +
                    kt * 32 + ((lane >> 3) & 1) * 16;
                LDSM4(kh4[j], rk);
            }
#pragma unroll
            for (int j = 0; j < 2; j++) {
                MMA_F16(acc[2 * (t2p + j)], qh[kt], kh4[j][0], kh4[j][1]);
                if (t2p + j < 3)
                    MMA_F16(acc[2 * (t2p + j) + 1], qh[kt], kh4[j][2], kh4[j][3]);
            }
        }

    // ---- fragment softmax (log2 domain, unnormalized) ----
    float m0 = -1e30f, m1 = -1e30f;
#pragma unroll
    for (int nt = 0; nt < 7; nt++) {
        m0 = fmaxf(m0, fmaxf(acc[nt][0], acc[nt][1]));
        m1 = fmaxf(m1, fmaxf(acc[nt][2], acc[nt][3]));
    }
    m0 = fmaxf(m0, __shfl_xor_sync(0xffffffffu, m0, 1));
    m0 = fmaxf(m0, __shfl_xor_sync(0xffffffffu, m0, 2));
    m1 = fmaxf(m1, __shfl_xor_sync(0xffffffffu, m1, 1));
    m1 = fmaxf(m1, __shfl_xor_sync(0xffffffffu, m1, 2));
    float s0 = 0.f, s1 = 0.f;
#pragma unroll
    for (int nt = 0; nt < 7; nt++) {
        acc[nt][0] = ex2(acc[nt][0] - m0); s0 += acc[nt][0];
        acc[nt][1] = ex2(acc[nt][1] - m0); s0 += acc[nt][1];
        acc[nt][2] = ex2(acc[nt][2] - m1); s1 += acc[nt][2];
        acc[nt][3] = ex2(acc[nt][3] - m1); s1 += acc[nt][3];
    }
    s0 += __shfl_xor_sync(0xffffffffu, s0, 1);
    s0 += __shfl_xor_sync(0xffffffffu, s0, 2);
    s1 += __shfl_xor_sync(0xffffffffu, s1, 1);
    s1 += __shfl_xor_sync(0xffffffffu, s1, 2);

    // ---- P -> fp16 single-term fragments ----
    uint32_t ph[4][4];
#pragma unroll
    for (int kk = 0; kk < 3; kk++) {
        ph[kk][0] = hpack2(acc[2 * kk][0],     acc[2 * kk][1]);
        ph[kk][1] = hpack2(acc[2 * kk][2],     acc[2 * kk][3]);
        ph[kk][2] = hpack2(acc[2 * kk + 1][0], acc[2 * kk + 1][1]);
        ph[kk][3] = hpack2(acc[2 * kk + 1][2], acc[2 * kk + 1][3]);
    }
    ph[3][0] = hpack2(acc[6][0], acc[6][1]);
    ph[3][1] = hpack2(acc[6][2], acc[6][3]);
    ph[3][2] = 0u;
    ph[3][3] = 0u;

    // ---- O = P @ V (single-term) ----
    float oacc[4][4];
#pragma unroll
    for (int a = 0; a < 4; a++)
#pragma unroll
        for (int c = 0; c < 4; c++) oacc[a][c] = 0.f;
#pragma unroll
    for (int kkp = 0; kkp < 4; kkp += 2) {
        uint32_t vh4[2][2][4];
#pragma unroll
        for (int j = 0; j < 2; j++)
#pragma unroll
            for (int d2 = 0; d2 < 2; d2++) {
                const uint32_t rv = sb + TV_H +
                    (uint32_t)((kkp + j) * 16 + (lane & 7) + ((lane >> 3) & 1) * 8) * RS +
                    d2 * 32 + ((lane >> 4) & 1) * 16;
                LDSM4T(vh4[j][d2], rv);
            }
#pragma unroll
        for (int j = 0; j < 2; j++)
#pragma unroll
            for (int d2 = 0; d2 < 2; d2++) {
                MMA_F16(oacc[2 * d2],     ph[kkp + j], vh4[j][d2][0], vh4[j][d2][1]);
                MMA_F16(oacc[2 * d2 + 1], ph[kkp + j], vh4[j][d2][2], vh4[j][d2][3]);
            }
    }

    // ---- normalize + write ----
    const float inv0 = 1.f / s0, inv1 = 1.f / s1;
    if (r0 < SEQ) {
        __half* orow = out_h + (size_t)(b * SEQ + r0) * CDIM + h * HD + cb;
#pragma unroll
        for (int dt = 0; dt < 4; dt++) {
            __half2 o = __floats2half2_rn(oacc[dt][0] * inv0, oacc[dt][1] * inv0);
            *(__half2*)(orow + dt * 8) = o;
        }
    }
    if (r0 + 8 < SEQ) {
        __half* orow = out_h + (size_t)(b * SEQ + r0 + 8) * CDIM + h * HD + cb;
#pragma unroll
        for (int dt = 0; dt < 4; dt++) {
            __half2 o = __floats2half2_rn(oacc[dt][2] * inv1, oacc[dt][3] * inv1);
            *(__half2*)(orow + dt * 8) = o;
        }
    }
}

// ---------------------------------------------------------------------------
extern "C" void kernel_launch(void* const* d_in, const int* in_sizes, int n_in,
                              void* d_out, int out_size)
{
    const float* x      = (const float*)d_in[0];
    const float* mask   = (const float*)d_in[1];
    const float* qkv_w  = (const float*)d_in[2];
    const float* qkv_b  = (const float*)d_in[3];
    const float* proj_w = (const float*)d_in[4];
    const float* proj_b = (const float*)d_in[5];
    const float* table  = (const float*)d_in[6];
    const int*   idx    = (const int*)d_in[7];
    float* out = (float*)d_out;

    float *cmb_s, *qb_s;
    __half *xh, *ath, *qwh, *pwh, *qh, *kh, *vh;
    cudaGetSymbolAddress((void**)&cmb_s, g_cmb);
    cudaGetSymbolAddress((void**)&qb_s, g_qb);
    cudaGetSymbolAddress((void**)&xh, g_x_h);
    cudaGetSymbolAddress((void**)&ath, g_att_h);
    cudaGetSymbolAddress((void**)&qwh, g_qw_h);
    cudaGetSymbolAddress((void**)&pwh, g_pw_h);
    cudaGetSymbolAddress((void**)&qh, g_q_h);
    cudaGetSymbolAddress((void**)&kh, g_k_h);
    cudaGetSymbolAddress((void**)&vh, g_v_h);

    cudaFuncSetAttribute(gemm_f16<0>, cudaFuncAttributeMaxDynamicSharedMemorySize, GSMEM);
    cudaFuncSetAttribute(gemm_f16<1>, cudaFuncAttributeMaxDynamicSharedMemorySize, GSMEM);

    const int n4 = MROWS * KDIM / 4;
    fconv<<<(n4 + 255) / 256, 256>>>((const float4*)x, (uint2*)xh, n4);
    wconv<<<dim3(1536 / 32, 512 / 32), dim3(32, 8)>>>(qkv_w, qwh, 512, 1536, SLQ, 512);
    wconv<<<dim3(512 / 32, 512 / 32), dim3(32, 8)>>>(proj_w, pwh, 512, 512, 1.f, 0);
    bprep<<<6, 256>>>(qkv_b, qb_s);
    cmb_prep<<<dim3(NW, NH), 256>>>(mask, table, idx, cmb_s);

    // 1) QKV projection, fp16 epilogue into q/k/v
    gemm_f16<1><<<dim3(1536 / 128, MROWS / 128), 256, GSMEM>>>(
        xh, qwh, qb_s, nullptr,
        (uint32_t*)qh, (uint32_t*)kh, (uint32_t*)vh, 1536);

    // 2) tensor-core window attention
    attn_mma<<<B_WIN * NH, 128>>>((const char*)qh, (const char*)kh,
                                  (const char*)vh, cmb_s, ath);

    // 3) output projection
    gemm_f16<0><<<dim3(512 / 128, MROWS / 128), 256, GSMEM>>>(
        ath, pwh, proj_b, out, nullptr, nullptr, nullptr, 512);
}